// round 5
// baseline (speedup 1.0000x reference)
#include <cuda_runtime.h>
#include <cuda_bf16.h>
#include <math.h>
#include <cstdint>

#define E_DIM 1024
#define H_NUM 16
#define D_DIM 64
#define B_NUM 4
#define S_LEN 1024
#define F_DIM 4096
#define M_ROWS (B_NUM * S_LEN)  // 4096
#define MB1 (1024 * 1024)

// ---------------- scratch (static device globals) ---------------------------
__device__ __align__(16) int8_t g_Bq1[16 * MB1], g_Bq2[16 * MB1];
__device__ __align__(16) float  g_sBall[16 * 4096];
__device__ __align__(16) int8_t g_Aq1[16 * MB1], g_Aq2[16 * MB1];
__device__ __align__(16) float  g_sA[4096];
__device__ __align__(16) int8_t g_Eq1[4 * MB1], g_Eq2[4 * MB1];
__device__ __align__(16) float  g_sE[4096];
__device__ __align__(16) __nv_bfloat16 g_qh[4 * MB1], g_ql[4 * MB1];
__device__ __align__(16) __nv_bfloat16 g_kh[4 * MB1], g_kl[4 * MB1];
__device__ __align__(16) __nv_bfloat16 g_vh[4 * MB1], g_vl[4 * MB1];
__device__ __align__(16) float g_att[4 * MB1];
__device__ __align__(16) float g_stag[16 * MB1];  // weight staging + GELU out (64MB)
__device__ __align__(16) float g_x1[4 * MB1], g_x2[4 * MB1];

// ---------------- PTX helpers -----------------------------------------------
__device__ __forceinline__ uint32_t smem_u32(const void* p) {
    uint32_t a;
    asm("{ .reg .u64 t; cvta.to.shared.u64 t, %1; cvt.u32.u64 %0, t; }" : "=r"(a) : "l"(p));
    return a;
}
__device__ __forceinline__ void cpasync16(uint32_t dst, const void* src) {
    asm volatile("cp.async.cg.shared.global [%0], [%1], 16;" :: "r"(dst), "l"(src));
}
__device__ __forceinline__ void cpcommit() { asm volatile("cp.async.commit_group;" ::: "memory"); }
template <int N>
__device__ __forceinline__ void cpwait() { asm volatile("cp.async.wait_group %0;" :: "n"(N) : "memory"); }

__device__ __forceinline__ void ldsm4(uint32_t (&r)[4], uint32_t addr) {
    asm volatile("ldmatrix.sync.aligned.m8n8.x4.shared.b16 {%0,%1,%2,%3}, [%4];"
                 : "=r"(r[0]), "=r"(r[1]), "=r"(r[2]), "=r"(r[3]) : "r"(addr));
}
__device__ __forceinline__ void ldsm4t(uint32_t (&r)[4], uint32_t addr) {
    asm volatile("ldmatrix.sync.aligned.m8n8.x4.trans.shared.b16 {%0,%1,%2,%3}, [%4];"
                 : "=r"(r[0]), "=r"(r[1]), "=r"(r[2]), "=r"(r[3]) : "r"(addr));
}
__device__ __forceinline__ void mma16816(float (&d)[4], const uint32_t (&a)[4],
                                         const uint32_t (&b)[2]) {
    asm volatile(
        "mma.sync.aligned.m16n8k16.row.col.f32.bf16.bf16.f32 "
        "{%0,%1,%2,%3}, {%4,%5,%6,%7}, {%8,%9}, {%0,%1,%2,%3};"
        : "+f"(d[0]), "+f"(d[1]), "+f"(d[2]), "+f"(d[3])
        : "r"(a[0]), "r"(a[1]), "r"(a[2]), "r"(a[3]), "r"(b[0]), "r"(b[1]));
}
__device__ __forceinline__ void imma16832(int (&d)[4], const uint32_t (&a)[4],
                                          const uint32_t (&b)[2]) {
    asm volatile(
        "mma.sync.aligned.m16n8k32.row.col.s32.s8.s8.s32 "
        "{%0,%1,%2,%3}, {%4,%5,%6,%7}, {%8,%9}, {%0,%1,%2,%3};"
        : "+r"(d[0]), "+r"(d[1]), "+r"(d[2]), "+r"(d[3])
        : "r"(a[0]), "r"(a[1]), "r"(a[2]), "r"(a[3]), "r"(b[0]), "r"(b[1]));
}
__device__ __forceinline__ uint32_t swz128(uint32_t o) { return o ^ ((o >> 3) & 0x70); }

__device__ __forceinline__ void bf_split(float v, __nv_bfloat16& hi, __nv_bfloat16& lo) {
    hi = __float2bfloat16_rn(v);
    lo = __float2bfloat16_rn(v - __bfloat162float(hi));
}
__device__ __forceinline__ void packsplit(float a, float b, uint32_t& hi, uint32_t& lo) {
    __nv_bfloat16 ah, al, bh, bl;
    bf_split(a, ah, al); bf_split(b, bh, bl);
    __nv_bfloat162 hp, lp;
    hp.x = ah; hp.y = bh; lp.x = al; lp.y = bl;
    hi = *(uint32_t*)&hp; lo = *(uint32_t*)&lp;
}
__device__ __forceinline__ void q8pair(float v, float isq, int8_t& a, int8_t& b) {
    float y = v * isq;
    int q = __float2int_rn(y);
    int q2 = __float2int_rn((y - (float)q) * 128.0f);
    a = (int8_t)q; b = (int8_t)q2;
}

// ---------------- weight prep: transpose to f32 staging ----------------------
// [H,E,D] -> Bt[n=h*64+d][k=e] f32
__global__ void wqkv_tr(const float* __restrict__ src, float* __restrict__ dst) {
    int idx = blockIdx.x * 256 + threadIdx.x;
    int n = idx >> 10, k = idx & 1023;
    int h = n >> 6, d = n & 63;
    dst[idx] = src[h * (E_DIM * D_DIM) + k * D_DIM + d];
}
// [K,N] row-major -> Bt[n][k] f32
__global__ void wt_tr(const float* __restrict__ src, float* __restrict__ dst, int K, int N) {
    __shared__ float tile[32][33];
    int n0 = blockIdx.x * 32, k0 = blockIdx.y * 32;
    int tx = threadIdx.x, ty = threadIdx.y;
    #pragma unroll
    for (int i = 0; i < 4; i++)
        tile[ty + 8 * i][tx] = src[(size_t)(k0 + ty + 8 * i) * N + n0 + tx];
    __syncthreads();
    #pragma unroll
    for (int i = 0; i < 4; i++)
        dst[(size_t)(n0 + ty + 8 * i) * K + k0 + tx] = tile[tx][ty + 8 * i];
}

// ---------------- per-row quantization: f32 [rows][iters*1024] -> int8 x2 ----
__global__ void __launch_bounds__(256) quant_rows(
    const float* __restrict__ src, int8_t* __restrict__ q1, int8_t* __restrict__ q2,
    float* __restrict__ sO, int iters) {
    int row = blockIdx.x, t = threadIdx.x;
    int cols = iters << 10;
    const float4* sp = (const float4*)(src + (size_t)row * cols);
    float4 vv[4];
    float mx = 0.0f;
    #pragma unroll 4
    for (int it = 0; it < iters; it++) {
        vv[it] = sp[it * 256 + t];
        mx = fmaxf(mx, fmaxf(fmaxf(fabsf(vv[it].x), fabsf(vv[it].y)),
                             fmaxf(fabsf(vv[it].z), fabsf(vv[it].w))));
    }
    #pragma unroll
    for (int o = 16; o > 0; o >>= 1)
        mx = fmaxf(mx, __shfl_xor_sync(0xffffffffu, mx, o));
    __shared__ float red[8];
    int w = t >> 5;
    if ((t & 31) == 0) red[w] = mx;
    __syncthreads();
    mx = 0.0f;
    #pragma unroll
    for (int i = 0; i < 8; i++) mx = fmaxf(mx, red[i]);
    float sq = mx * (1.0f / 127.0f) + 1e-30f;
    float isq = 1.0f / sq;
    #pragma unroll 4
    for (int it = 0; it < iters; it++) {
        char4 c1, c2;
        q8pair(vv[it].x, isq, c1.x, c2.x);
        q8pair(vv[it].y, isq, c1.y, c2.y);
        q8pair(vv[it].z, isq, c1.z, c2.z);
        q8pair(vv[it].w, isq, c1.w, c2.w);
        size_t o = (size_t)row * cols + (it * 256 + t) * 4;
        *(char4*)(q1 + o) = c1;
        *(char4*)(q2 + o) = c2;
    }
    if (t == 0) sO[row] = sq;
}

// ---------------- LayerNorm: f32 in -> int8 q1/q2 + row scale ----------------
__global__ void __launch_bounds__(256) ln_q8(const float* __restrict__ x,
                                             const float* __restrict__ g,
                                             const float* __restrict__ b,
                                             int8_t* __restrict__ q1,
                                             int8_t* __restrict__ q2,
                                             float* __restrict__ sA) {
    int row = blockIdx.x;
    int t = threadIdx.x;
    float4 v = ((const float4*)(x + (size_t)row * E_DIM))[t];
    float s = v.x + v.y + v.z + v.w;
    float ss = v.x * v.x + v.y * v.y + v.z * v.z + v.w * v.w;
    #pragma unroll
    for (int o = 16; o > 0; o >>= 1) {
        s  += __shfl_xor_sync(0xffffffffu, s, o);
        ss += __shfl_xor_sync(0xffffffffu, ss, o);
    }
    __shared__ float red[2][8];
    __shared__ float redm[8];
    int w = t >> 5, lane = t & 31;
    if (lane == 0) { red[0][w] = s; red[1][w] = ss; }
    __syncthreads();
    s = 0.0f; ss = 0.0f;
    #pragma unroll
    for (int i = 0; i < 8; i++) { s += red[0][i]; ss += red[1][i]; }
    float mu  = s * (1.0f / E_DIM);
    float var = ss * (1.0f / E_DIM) - mu * mu;
    float inv = rsqrtf(var + 1e-5f);
    float4 gv = ((const float4*)g)[t];
    float4 bv = ((const float4*)b)[t];
    float o0 = (v.x - mu) * inv * gv.x + bv.x;
    float o1 = (v.y - mu) * inv * gv.y + bv.y;
    float o2 = (v.z - mu) * inv * gv.z + bv.z;
    float o3 = (v.w - mu) * inv * gv.w + bv.w;
    float mx = fmaxf(fmaxf(fabsf(o0), fabsf(o1)), fmaxf(fabsf(o2), fabsf(o3)));
    #pragma unroll
    for (int o = 16; o > 0; o >>= 1)
        mx = fmaxf(mx, __shfl_xor_sync(0xffffffffu, mx, o));
    if (lane == 0) redm[w] = mx;
    __syncthreads();
    mx = 0.0f;
    #pragma unroll
    for (int i = 0; i < 8; i++) mx = fmaxf(mx, redm[i]);
    float sq = mx * (1.0f / 127.0f) + 1e-30f;
    float isq = 1.0f / sq;
    char4 c1, c2;
    q8pair(o0, isq, c1.x, c2.x);
    q8pair(o1, isq, c1.y, c2.y);
    q8pair(o2, isq, c1.z, c2.z);
    q8pair(o3, isq, c1.w, c2.w);
    size_t base = (size_t)row * E_DIM + t * 4;
    *(char4*)(q1 + base) = c1;
    *(char4*)(q2 + base) = c2;
    if (t == 0) sA[row] = sq;
}

// ---------------- INT8x3 IMMA GEMM -------------------------------------------
// C[M,N] = epi(sA sB (q1A q1B + (q1A q2B + q2A q1B)/128) + bias)
// A: [M,K] int8 q1/q2; B: [N,K] int8 q1/q2 (pre-transposed weights).
// CTA 128x128, BK=64, 8 warps (2m x 4n), warp tile 64x32, double-buffered.
// EPI: 0 -> bf16 hi/lo (QKV), 1 bias+GELU -> f32, 2 bias+res -> f32
#define I8_STAGE 32768
#define I8_SMEM (2 * I8_STAGE + 256)
template <int EPI>
__global__ void __launch_bounds__(256, 1) gemm_i8(
    const int8_t* __restrict__ Aq1, const int8_t* __restrict__ Aq2,
    const float* __restrict__ sA,
    const int8_t* __restrict__ Bq1, const int8_t* __restrict__ Bq2,
    const float* __restrict__ sB,
    const float* __restrict__ bias, const float* __restrict__ res,
    float* __restrict__ outF, __nv_bfloat16* __restrict__ outH,
    __nv_bfloat16* __restrict__ outL, int M, int N, int K) {
    extern __shared__ char dyn[];
    uint32_t sb = (smem_u32(dyn) + 127) & ~127u;
    int tid = threadIdx.x, lane = tid & 31, wid = tid >> 5;
    int rBase = blockIdx.y * 128, cBase = blockIdx.x * 128;
    int m0 = (wid >> 2) * 64, n0 = (wid & 3) * 32;

    int acc1[4][4][4], acc2[4][4][4];
    #pragma unroll
    for (int i = 0; i < 4; i++)
        #pragma unroll
        for (int j = 0; j < 4; j++)
            #pragma unroll
            for (int u = 0; u < 4; u++) { acc1[i][j][u] = 0; acc2[i][j][u] = 0; }

    const int nc = K >> 6;
    auto loadStage = [&](int s, int c) {
        uint32_t base = sb + s * I8_STAGE;
        int k0 = c << 6;
        #pragma unroll
        for (int i = 0; i < 2; i++) {
            int idx = i * 256 + tid;
            int row = idx >> 2, seg = idx & 3;
            uint32_t off = (seg >> 1) * 4096 + (((row * 32) + (seg & 1) * 16) ^ ((row & 4) << 2));
            size_t ga = (size_t)(rBase + row) * K + k0 + seg * 16;
            size_t gb = (size_t)(cBase + row) * K + k0 + seg * 16;
            cpasync16(base + off,         Aq1 + ga);
            cpasync16(base + 8192 + off,  Aq2 + ga);
            cpasync16(base + 16384 + off, Bq1 + gb);
            cpasync16(base + 24576 + off, Bq2 + gb);
        }
    };

    int aRow = (lane & 7) + ((lane >> 3) & 1) * 8;
    int aC   = lane >> 4;
    int bRow = (lane & 7) + ((lane >> 4) & 1) * 8;  // 16-row ldsm4 pattern for B
    int bH   = (lane >> 3) & 1;

    loadStage(0, 0); cpcommit();

    for (int c = 0; c < nc; c++) {
        if (c + 1 < nc) { loadStage((c + 1) & 1, c + 1); cpcommit(); cpwait<1>(); }
        else            { cpwait<0>(); }
        __syncthreads();
        uint32_t base = sb + (c & 1) * I8_STAGE;
        #pragma unroll
        for (int kc = 0; kc < 2; kc++) {
            uint32_t b1r[4][2], b2r[4][2];
            #pragma unroll
            for (int jp = 0; jp < 2; jp++) {
                int row = n0 + jp * 16 + bRow;
                uint32_t off = kc * 4096 + (((row * 32) + bH * 16) ^ ((row & 4) << 2));
                uint32_t t4[4];
                ldsm4(t4, base + 16384 + off);
                b1r[2 * jp][0] = t4[0]; b1r[2 * jp][1] = t4[1];
                b1r[2 * jp + 1][0] = t4[2]; b1r[2 * jp + 1][1] = t4[3];
                ldsm4(t4, base + 24576 + off);
                b2r[2 * jp][0] = t4[0]; b2r[2 * jp][1] = t4[1];
                b2r[2 * jp + 1][0] = t4[2]; b2r[2 * jp + 1][1] = t4[3];
            }
            #pragma unroll
            for (int i = 0; i < 4; i++) {
                uint32_t a1[4], a2[4];
                int row = m0 + i * 16 + aRow;
                uint32_t off = kc * 4096 + (((row * 32) + aC * 16) ^ ((row & 4) << 2));
                ldsm4(a1, base + off);
                ldsm4(a2, base + 8192 + off);
                #pragma unroll
                for (int j = 0; j < 4; j++) {
                    imma16832(acc1[i][j], a1, b1r[j]);
                    imma16832(acc2[i][j], a1, b2r[j]);
                    imma16832(acc2[i][j], a2, b1r[j]);
                }
            }
        }
        __syncthreads();
    }

    int lr = lane >> 2, lc = (lane & 3) << 1;
    #pragma unroll
    for (int i = 0; i < 4; i++) {
        #pragma unroll
        for (int half = 0; half < 2; half++) {
            size_t row = (size_t)(rBase + m0 + i * 16 + lr + half * 8);
            float sa = sA[row];
            #pragma unroll
            for (int j = 0; j < 4; j++) {
                int col = cBase + n0 + j * 8 + lc;
                float v0 = ((float)acc1[i][j][half * 2 + 0] +
                            (float)acc2[i][j][half * 2 + 0] * 0.0078125f) * sa * sB[col] + bias[col];
                float v1 = ((float)acc1[i][j][half * 2 + 1] +
                            (float)acc2[i][j][half * 2 + 1] * 0.0078125f) * sa * sB[col + 1] + bias[col + 1];
                if (EPI == 0) {
                    uint32_t hp, lp;
                    packsplit(v0, v1, hp, lp);
                    *(uint32_t*)(outH + row * N + col) = hp;
                    *(uint32_t*)(outL + row * N + col) = lp;
                } else {
                    if (EPI == 1) {
                        v0 = 0.5f * v0 * (1.0f + erff(v0 * 0.70710678118654752f));
                        v1 = 0.5f * v1 * (1.0f + erff(v1 * 0.70710678118654752f));
                    }
                    if (EPI == 2) {
                        float2 rv = *(const float2*)(res + row * N + col);
                        v0 += rv.x; v1 += rv.y;
                    }
                    float2 o; o.x = v0; o.y = v1;
                    *(float2*)(outF + row * N + col) = o;
                }
            }
        }
    }
}

// ---------------- HMMA flash attention (bf16x3, D=64) -> f32 out -------------
#define ATTN_SMEM (16384 + 2 * 32768 + 1024)
template <bool CAUSAL>
__global__ void __launch_bounds__(128, 2) attn_hmma(
    const __nv_bfloat16* __restrict__ Qh, const __nv_bfloat16* __restrict__ Ql,
    const __nv_bfloat16* __restrict__ Kh, const __nv_bfloat16* __restrict__ Kl,
    const __nv_bfloat16* __restrict__ Vh, const __nv_bfloat16* __restrict__ Vl,
    float* __restrict__ O) {
    extern __shared__ char dyn[];
    uint32_t sb = (smem_u32(dyn) + 1023) & ~1023u;
    int tid = threadIdx.x, lane = tid & 31, w = tid >> 5;
    int b = blockIdx.z, hh = blockIdx.y, qt = blockIdx.x;
    size_t headOff = (size_t)hh * D_DIM;
    size_t tokBase = (size_t)b * S_LEN;

    int aRow = (lane & 7) + ((lane >> 3) & 1) * 8;
    int aC = lane >> 4;

    {
        #pragma unroll
        for (int i = 0; i < 4; i++) {
            int idx = i * 128 + tid;
            int r = idx >> 3, c = idx & 7;
            uint32_t off = swz128(r * 128 + c * 16);
            size_t src = (tokBase + qt * 64 + r) * E_DIM + headOff + c * 8;
            cpasync16(sb + off, Qh + src);
            cpasync16(sb + 8192 + off, Ql + src);
        }
    }
    auto loadKV = [&](int s, int kt) {
        uint32_t base = sb + 16384 + s * 32768;
        #pragma unroll
        for (int i = 0; i < 4; i++) {
            int idx = i * 128 + tid;
            int r = idx >> 3, c = idx & 7;
            uint32_t off = swz128(r * 128 + c * 16);
            size_t src = (tokBase + kt * 64 + r) * E_DIM + headOff + c * 8;
            cpasync16(base + off,         Kh + src);
            cpasync16(base + 8192 + off,  Kl + src);
            cpasync16(base + 16384 + off, Vh + src);
            cpasync16(base + 24576 + off, Vl + src);
        }
    };
    loadKV(0, 0);
    cpcommit();

    uint32_t qh[4][4], ql[4][4];
    float oacc[8][4];
    float mrow[2] = {-1e30f, -1e30f}, lrow[2] = {0.0f, 0.0f};
    #pragma unroll
    for (int j = 0; j < 8; j++)
        #pragma unroll
        for (int u = 0; u < 4; u++) oacc[j][u] = 0.0f;

    const int ntiles = CAUSAL ? (qt + 1) : (S_LEN / 64);
    for (int kt = 0; kt < ntiles; kt++) {
        if (kt + 1 < ntiles) { loadKV((kt + 1) & 1, kt + 1); cpcommit(); cpwait<1>(); }
        else                 { cpwait<0>(); }
        __syncthreads();
        if (kt == 0) {
            #pragma unroll
            for (int s = 0; s < 4; s++) {
                uint32_t addr = sb + swz128((w * 16 + aRow) * 128 + s * 32 + aC * 16);
                ldsm4(qh[s], addr);
                ldsm4(ql[s], addr + 8192);
            }
        }
        uint32_t kb = sb + 16384 + (kt & 1) * 32768;
        uint32_t vb = kb + 16384;

        float sacc[8][4];
        #pragma unroll
        for (int j = 0; j < 8; j++)
            #pragma unroll
            for (int u = 0; u < 4; u++) sacc[j][u] = 0.0f;
        #pragma unroll
        for (int s = 0; s < 4; s++) {
            #pragma unroll
            for (int jp = 0; jp < 4; jp++) {
                uint32_t addr = kb + swz128((jp * 16 + aRow) * 128 + s * 32 + aC * 16);
                uint32_t kh4[4], kl4[4];
                ldsm4(kh4, addr);
                ldsm4(kl4, addr + 8192);
                uint32_t b0h[2] = {kh4[0], kh4[2]}, b1h[2] = {kh4[1], kh4[3]};
                uint32_t b0l[2] = {kl4[0], kl4[2]}, b1l[2] = {kl4[1], kl4[3]};
                mma16816(sacc[2 * jp],     qh[s], b0h);
                mma16816(sacc[2 * jp],     ql[s], b0h);
                mma16816(sacc[2 * jp],     qh[s], b0l);
                mma16816(sacc[2 * jp + 1], qh[s], b1h);
                mma16816(sacc[2 * jp + 1], ql[s], b1h);
                mma16816(sacc[2 * jp + 1], qh[s], b1l);
            }
        }

        if (CAUSAL && kt == qt) {
            int ql0 = w * 16 + (lane >> 2);
            #pragma unroll
            for (int j = 0; j < 8; j++)
                #pragma unroll
                for (int u = 0; u < 4; u++) {
                    int kcol = j * 8 + ((lane & 3) << 1) + (u & 1);
                    int qrow = ql0 + (u >> 1) * 8;
                    if (kcol > qrow) sacc[j][u] = -1e30f;
                }
        }

        #pragma unroll
        for (int h2 = 0; h2 < 2; h2++) {
            float mt = -1e30f;
            #pragma unroll
            for (int j = 0; j < 8; j++)
                mt = fmaxf(mt, fmaxf(sacc[j][2 * h2], sacc[j][2 * h2 + 1]));
            mt = fmaxf(mt, __shfl_xor_sync(0xffffffffu, mt, 1));
            mt = fmaxf(mt, __shfl_xor_sync(0xffffffffu, mt, 2));
            float mn = fmaxf(mrow[h2], mt);
            float sc = __expf(mrow[h2] - mn);
            mrow[h2] = mn;
            float ts = 0.0f;
            #pragma unroll
            for (int j = 0; j < 8; j++) {
                sacc[j][2 * h2]     = __expf(sacc[j][2 * h2] - mn);
                sacc[j][2 * h2 + 1] = __expf(sacc[j][2 * h2 + 1] - mn);
                ts += sacc[j][2 * h2] + sacc[j][2 * h2 + 1];
            }
            ts += __shfl_xor_sync(0xffffffffu, ts, 1);
            ts += __shfl_xor_sync(0xffffffffu, ts, 2);
            lrow[h2] = lrow[h2] * sc + ts;
            #pragma unroll
            for (int j = 0; j < 8; j++) {
                oacc[j][2 * h2]     *= sc;
                oacc[j][2 * h2 + 1] *= sc;
            }
        }

        #pragma unroll
        for (int s = 0; s < 4; s++) {
            uint32_t ph4[4], pl4[4];
            packsplit(sacc[2 * s][0],     sacc[2 * s][1],     ph4[0], pl4[0]);
            packsplit(sacc[2 * s][2],     sacc[2 * s][3],     ph4[1], pl4[1]);
            packsplit(sacc[2 * s + 1][0], sacc[2 * s + 1][1], ph4[2], pl4[2]);
            packsplit(sacc[2 * s + 1][2], sacc[2 * s + 1][3], ph4[3], pl4[3]);
            #pragma unroll
            for (int jp = 0; jp < 4; jp++) {
                uint32_t addr = vb + swz128((s * 16 + aRow) * 128 + jp * 32 + aC * 16);
                uint32_t vh4[4], vl4[4];
                ldsm4t(vh4, addr);
                ldsm4t(vl4, addr + 8192);
                uint32_t b0h[2] = {vh4[0], vh4[1]}, b1h[2] = {vh4[2], vh4[3]};
                uint32_t b0l[2] = {vl4[0], vl4[1]}, b1l[2] = {vl4[2], vl4[3]};
                mma16816(oacc[2 * jp],     ph4, b0h);
                mma16816(oacc[2 * jp],     pl4, b0h);
                mma16816(oacc[2 * jp],     ph4, b0l);
                mma16816(oacc[2 * jp + 1], ph4, b1h);
                mma16816(oacc[2 * jp + 1], pl4, b1h);
                mma16816(oacc[2 * jp + 1], ph4, b1l);
            }
        }
        __syncthreads();
    }

    #pragma unroll
    for (int h2 = 0; h2 < 2; h2++) {
        float inv = 1.0f / lrow[h2];
        int trow = qt * 64 + w * 16 + (lane >> 2) + h2 * 8;
        size_t rp = (tokBase + trow) * E_DIM + headOff;
        #pragma unroll
        for (int j = 0; j < 8; j++) {
            float2 o;
            o.x = oacc[j][2 * h2] * inv;
            o.y = oacc[j][2 * h2 + 1] * inv;
            int col = j * 8 + ((lane & 3) << 1);
            *(float2*)(O + rp + col) = o;
        }
    }
}

// ---------------- launch ------------------------------------------------------
extern "C" void kernel_launch(void* const* d_in, const int* in_sizes, int n_in,
                              void* d_out, int out_size) {
    const float* x    = (const float*)d_in[0];
    const float* enc  = (const float*)d_in[1];
    const float* ln1g = (const float*)d_in[2];
    const float* ln1b = (const float*)d_in[3];
    const float* ln2g = (const float*)d_in[4];
    const float* ln2b = (const float*)d_in[5];
    const float* ln3g = (const float*)d_in[6];
    const float* ln3b = (const float*)d_in[7];
    const float* Wq1  = (const float*)d_in[8];
    const float* bq1  = (const float*)d_in[9];
    const float* Wk1  = (const float*)d_in[10];
    const float* bk1  = (const float*)d_in[11];
    const float* Wv1  = (const float*)d_in[12];
    const float* bv1  = (const float*)d_in[13];
    const float* Wo1  = (const float*)d_in[14];
    const float* bo1  = (const float*)d_in[15];
    const float* Wq2  = (const float*)d_in[16];
    const float* bq2  = (const float*)d_in[17];
    const float* Wk2  = (const float*)d_in[18];
    const float* bk2  = (const float*)d_in[19];
    const float* Wv2  = (const float*)d_in[20];
    const float* bv2  = (const float*)d_in[21];
    const float* Wo2  = (const float*)d_in[22];
    const float* bo2  = (const float*)d_in[23];
    const float* Wup  = (const float*)d_in[24];
    const float* bup  = (const float*)d_in[25];
    const float* Wdn  = (const float*)d_in[26];
    const float* bdn  = (const float*)d_in[27];
    float* out = (float*)d_out;

    int8_t *Bq1, *Bq2, *Aq1, *Aq2, *Eq1, *Eq2;
    float *sBall, *sA, *sE, *att, *stag, *x1, *x2;
    __nv_bfloat16 *qh, *ql, *kh, *kl, *vh, *vl;
    cudaGetSymbolAddress((void**)&Bq1, g_Bq1);
    cudaGetSymbolAddress((void**)&Bq2, g_Bq2);
    cudaGetSymbolAddress((void**)&sBall, g_sBall);
    cudaGetSymbolAddress((void**)&Aq1, g_Aq1);
    cudaGetSymbolAddress((void**)&Aq2, g_Aq2);
    cudaGetSymbolAddress((void**)&sA,  g_sA);
    cudaGetSymbolAddress((void**)&Eq1, g_Eq1);
    cudaGetSymbolAddress((void**)&Eq2, g_Eq2);
    cudaGetSymbolAddress((void**)&sE,  g_sE);
    cudaGetSymbolAddress((void**)&qh,  g_qh);
    cudaGetSymbolAddress((void**)&ql,  g_ql);
    cudaGetSymbolAddress((void**)&kh,  g_kh);
    cudaGetSymbolAddress((void**)&kl,  g_kl);
    cudaGetSymbolAddress((void**)&vh,  g_vh);
    cudaGetSymbolAddress((void**)&vl,  g_vl);
    cudaGetSymbolAddress((void**)&att, g_att);
    cudaGetSymbolAddress((void**)&stag, g_stag);
    cudaGetSymbolAddress((void**)&x1,  g_x1);
    cudaGetSymbolAddress((void**)&x2,  g_x2);

    cudaFuncSetAttribute(gemm_i8<0>, cudaFuncAttributeMaxDynamicSharedMemorySize, I8_SMEM);
    cudaFuncSetAttribute(gemm_i8<1>, cudaFuncAttributeMaxDynamicSharedMemorySize, I8_SMEM);
    cudaFuncSetAttribute(gemm_i8<2>, cudaFuncAttributeMaxDynamicSharedMemorySize, I8_SMEM);
    cudaFuncSetAttribute(attn_hmma<true>,  cudaFuncAttributeMaxDynamicSharedMemorySize, ATTN_SMEM);
    cudaFuncSetAttribute(attn_hmma<false>, cudaFuncAttributeMaxDynamicSharedMemorySize, ATTN_SMEM);

    const int WS = E_DIM * E_DIM;  // 1M int8 per square slot
    dim3 gSq(8, 32);
    dim3 gUp(32, 32);
    dim3 gAttn(S_LEN / 64, H_NUM, B_NUM);
    dim3 trB(32, 8);

    // ---- block 1 (ncu -s 5 lands on a GEMM) ----
    wqkv_tr<<<4096, 256>>>(Wq1, stag);                                              // 0
    quant_rows<<<1024, 256>>>(stag, Bq1 + 0 * WS, Bq2 + 0 * WS, sBall + 0 * 4096, 1);   // 1
    ln_q8<<<M_ROWS, 256>>>(x, ln1g, ln1b, Aq1, Aq2, sA);                            // 2
    wqkv_tr<<<4096, 256>>>(Wk1, stag);                                              // 3
    quant_rows<<<1024, 256>>>(stag, Bq1 + 1 * WS, Bq2 + 1 * WS, sBall + 1 * 4096, 1);   // 4
    gemm_i8<0><<<gSq, 256, I8_SMEM>>>(Aq1, Aq2, sA, Bq1 + 0 * WS, Bq2 + 0 * WS,
        sBall + 0 * 4096, bq1, nullptr, nullptr, qh, ql, M_ROWS, E_DIM, E_DIM);     // 5
    wqkv_tr<<<4096, 256>>>(Wv1, stag);                                              // 6
    quant_rows<<<1024, 256>>>(stag, Bq1 + 2 * WS, Bq2 + 2 * WS, sBall + 2 * 4096, 1);   // 7
    gemm_i8<0><<<gSq, 256, I8_SMEM>>>(Aq1, Aq2, sA, Bq1 + 1 * WS, Bq2 + 1 * WS,
        sBall + 1 * 4096, bk1, nullptr, nullptr, kh, kl, M_ROWS, E_DIM, E_DIM);     // 8
    gemm_i8<0><<<gSq, 256, I8_SMEM>>>(Aq1, Aq2, sA, Bq1 + 2 * WS, Bq2 + 2 * WS,
        sBall + 2 * 4096, bv1, nullptr, nullptr, vh, vl, M_ROWS, E_DIM, E_DIM);     // 9
    attn_hmma<true><<<gAttn, 128, ATTN_SMEM>>>(qh, ql, kh, kl, vh, vl, att);        // 10
    wt_tr<<<dim3(32, 32), trB>>>(Wo1, stag, 1024, 1024);                            // 11
    quant_rows<<<1024, 256>>>(stag, Bq1 + 6 * WS, Bq2 + 6 * WS, sBall + 6 * 4096, 1);   // 12
    quant_rows<<<4096, 256>>>(att, Aq1, Aq2, sA, 1);                                // 13
    gemm_i8<2><<<gSq, 256, I8_SMEM>>>(Aq1, Aq2, sA, Bq1 + 6 * WS, Bq2 + 6 * WS,
        sBall + 6 * 4096, bo1, x, x1, nullptr, nullptr, M_ROWS, E_DIM, E_DIM);      // 14

    // ---- block 2 ----
    ln_q8<<<M_ROWS, 256>>>(x1, ln2g, ln2b, Aq1, Aq2, sA);
    quant_rows<<<4096, 256>>>(enc, Eq1, Eq2, sE, 1);
    wqkv_tr<<<4096, 256>>>(Wq2, stag);
    quant_rows<<<1024, 256>>>(stag, Bq1 + 3 * WS, Bq2 + 3 * WS, sBall + 3 * 4096, 1);
    gemm_i8<0><<<gSq, 256, I8_SMEM>>>(Aq1, Aq2, sA, Bq1 + 3 * WS, Bq2 + 3 * WS,
        sBall + 3 * 4096, bq2, nullptr, nullptr, qh, ql, M_ROWS, E_DIM, E_DIM);
    wqkv_tr<<<4096, 256>>>(Wk2, stag);
    quant_rows<<<1024, 256>>>(stag, Bq1 + 4 * WS, Bq2 + 4 * WS, sBall + 4 * 4096, 1);
    gemm_i8<0><<<gSq, 256, I8_SMEM>>>(Eq1, Eq2, sE, Bq1 + 4 * WS, Bq2 + 4 * WS,
        sBall + 4 * 4096, bk2, nullptr, nullptr, kh, kl, M_ROWS, E_DIM, E_DIM);
    wqkv_tr<<<4096, 256>>>(Wv2, stag);
    quant_rows<<<1024, 256>>>(stag, Bq1 + 5 * WS, Bq2 + 5 * WS, sBall + 5 * 4096, 1);
    gemm_i8<0><<<gSq, 256, I8_SMEM>>>(Eq1, Eq2, sE, Bq1 + 5 * WS, Bq2 + 5 * WS,
        sBall + 5 * 4096, bv2, nullptr, nullptr, vh, vl, M_ROWS, E_DIM, E_DIM);
    attn_hmma<false><<<gAttn, 128, ATTN_SMEM>>>(qh, ql, kh, kl, vh, vl, att);
    wt_tr<<<dim3(32, 32), trB>>>(Wo2, stag, 1024, 1024);
    quant_rows<<<1024, 256>>>(stag, Bq1 + 7 * WS, Bq2 + 7 * WS, sBall + 7 * 4096, 1);
    quant_rows<<<4096, 256>>>(att, Aq1, Aq2, sA, 1);
    gemm_i8<2><<<gSq, 256, I8_SMEM>>>(Aq1, Aq2, sA, Bq1 + 7 * WS, Bq2 + 7 * WS,
        sBall + 7 * 4096, bo2, x1, x2, nullptr, nullptr, M_ROWS, E_DIM, E_DIM);

    // ---- FFN ----
    ln_q8<<<M_ROWS, 256>>>(x2, ln3g, ln3b, Aq1, Aq2, sA);
    wt_tr<<<dim3(32, 128), trB>>>(Wdn, stag, 4096, 1024);     // Bt [1024][4096]
    quant_rows<<<1024, 256>>>(stag, Bq1 + 12 * WS, Bq2 + 12 * WS, sBall + 12 * 4096, 4);
    wt_tr<<<dim3(128, 32), trB>>>(Wup, stag, 1024, 4096);     // Bt [4096][1024]
    quant_rows<<<4096, 256>>>(stag, Bq1 + 8 * WS, Bq2 + 8 * WS, sBall + 8 * 4096, 1);
    gemm_i8<1><<<gUp, 256, I8_SMEM>>>(Aq1, Aq2, sA, Bq1 + 8 * WS, Bq2 + 8 * WS,
        sBall + 8 * 4096, bup, nullptr, stag, nullptr, nullptr, M_ROWS, F_DIM, E_DIM);
    quant_rows<<<4096, 256>>>(stag, Aq1, Aq2, sA, 4);
    gemm_i8<2><<<gSq, 256, I8_SMEM>>>(Aq1, Aq2, sA, Bq1 + 12 * WS, Bq2 + 12 * WS,
        sBall + 12 * 4096, bdn, x2, out, nullptr, nullptr, M_ROWS, E_DIM, F_DIM);
}

// round 6
// speedup vs baseline: 3.1511x; 3.1511x over previous
#include <cuda_runtime.h>
#include <cuda_bf16.h>
#include <cuda_fp16.h>
#include <math.h>
#include <cstdint>

#define E_DIM 1024
#define H_NUM 16
#define D_DIM 64
#define B_NUM 4
#define S_LEN 1024
#define F_DIM 4096
#define M_ROWS (B_NUM * S_LEN)  // 4096
#define MB1 (1024 * 1024)

// ---------------- scratch (static device globals) ---------------------------
__device__ __align__(16) __nv_bfloat16 g_Bh[8 * MB1], g_Bl[8 * MB1];   // QKV weights bf16 hi/lo (slots 0-5)
__device__ __align__(16) half g_W16h[10 * MB1], g_W16l[10 * MB1];      // Wo1@0,Wo2@1,Wup@2-5,Wdn@6-9
__device__ __align__(16) __nv_bfloat16 g_hh[4 * MB1], g_hl[4 * MB1];   // LN1/2 out
__device__ __align__(16) __nv_bfloat16 g_ech[4 * MB1], g_ecl[4 * MB1]; // enc split
__device__ __align__(16) __nv_bfloat16 g_qh[4 * MB1], g_ql[4 * MB1];
__device__ __align__(16) __nv_bfloat16 g_kh[4 * MB1], g_kl[4 * MB1];
__device__ __align__(16) __nv_bfloat16 g_vh[4 * MB1], g_vl[4 * MB1];
__device__ __align__(16) half g_a16[16 * MB1];   // attn out (4M) / GELU out (16M)
__device__ __align__(16) half g_h16[4 * MB1];    // LN3 out fp16
__device__ __align__(16) float g_x1[4 * MB1], g_x2[4 * MB1];

// ---------------- PTX helpers -----------------------------------------------
__device__ __forceinline__ uint32_t smem_u32(const void* p) {
    uint32_t a;
    asm("{ .reg .u64 t; cvta.to.shared.u64 t, %1; cvt.u32.u64 %0, t; }" : "=r"(a) : "l"(p));
    return a;
}
__device__ __forceinline__ void cpasync16(uint32_t dst, const void* src) {
    asm volatile("cp.async.cg.shared.global [%0], [%1], 16;" :: "r"(dst), "l"(src));
}
__device__ __forceinline__ void cpcommit() { asm volatile("cp.async.commit_group;" ::: "memory"); }
template <int N>
__device__ __forceinline__ void cpwait() { asm volatile("cp.async.wait_group %0;" :: "n"(N) : "memory"); }

__device__ __forceinline__ void ldsm4(uint32_t (&r)[4], uint32_t addr) {
    asm volatile("ldmatrix.sync.aligned.m8n8.x4.shared.b16 {%0,%1,%2,%3}, [%4];"
                 : "=r"(r[0]), "=r"(r[1]), "=r"(r[2]), "=r"(r[3]) : "r"(addr));
}
__device__ __forceinline__ void ldsm4t(uint32_t (&r)[4], uint32_t addr) {
    asm volatile("ldmatrix.sync.aligned.m8n8.x4.trans.shared.b16 {%0,%1,%2,%3}, [%4];"
                 : "=r"(r[0]), "=r"(r[1]), "=r"(r[2]), "=r"(r[3]) : "r"(addr));
}
__device__ __forceinline__ void ldsm2(uint32_t (&r)[2], uint32_t addr) {
    asm volatile("ldmatrix.sync.aligned.m8n8.x2.shared.b16 {%0,%1}, [%2];"
                 : "=r"(r[0]), "=r"(r[1]) : "r"(addr));
}
__device__ __forceinline__ void mma16816(float (&d)[4], const uint32_t (&a)[4],
                                         const uint32_t (&b)[2]) {
    asm volatile(
        "mma.sync.aligned.m16n8k16.row.col.f32.bf16.bf16.f32 "
        "{%0,%1,%2,%3}, {%4,%5,%6,%7}, {%8,%9}, {%0,%1,%2,%3};"
        : "+f"(d[0]), "+f"(d[1]), "+f"(d[2]), "+f"(d[3])
        : "r"(a[0]), "r"(a[1]), "r"(a[2]), "r"(a[3]), "r"(b[0]), "r"(b[1]));
}
__device__ __forceinline__ void mma16816h(float (&d)[4], const uint32_t (&a)[4],
                                          const uint32_t (&b)[2]) {
    asm volatile(
        "mma.sync.aligned.m16n8k16.row.col.f32.f16.f16.f32 "
        "{%0,%1,%2,%3}, {%4,%5,%6,%7}, {%8,%9}, {%0,%1,%2,%3};"
        : "+f"(d[0]), "+f"(d[1]), "+f"(d[2]), "+f"(d[3])
        : "r"(a[0]), "r"(a[1]), "r"(a[2]), "r"(a[3]), "r"(b[0]), "r"(b[1]));
}
__device__ __forceinline__ uint32_t swz128(uint32_t o) { return o ^ ((o >> 3) & 0x70); }

__device__ __forceinline__ void bf_split(float v, __nv_bfloat16& hi, __nv_bfloat16& lo) {
    hi = __float2bfloat16_rn(v);
    lo = __float2bfloat16_rn(v - __bfloat162float(hi));
}
__device__ __forceinline__ void packsplit(float a, float b, uint32_t& hi, uint32_t& lo) {
    __nv_bfloat16 ah, al, bh, bl;
    bf_split(a, ah, al); bf_split(b, bh, bl);
    __nv_bfloat162 hp, lp;
    hp.x = ah; hp.y = bh; lp.x = al; lp.y = bl;
    hi = *(uint32_t*)&hp; lo = *(uint32_t*)&lp;
}
__device__ __forceinline__ void h_split(float v, half& hi, half& lo) {
    hi = __float2half_rn(v);
    lo = __float2half_rn(v - __half2float(hi));
}

// ---------------- weight prep -------------------------------------------------
// All 6 QKV weights: [H,E,D] -> Bt[n=h*64+d][k=e], bf16 hi/lo, smem-tiled transpose.
__global__ void __launch_bounds__(256) wqkv_split_all(
    const float* __restrict__ w0, const float* __restrict__ w1,
    const float* __restrict__ w2, const float* __restrict__ w3,
    const float* __restrict__ w4, const float* __restrict__ w5,
    __nv_bfloat16* __restrict__ oh, __nv_bfloat16* __restrict__ ol) {
    __shared__ float tile[32][33];
    int dt = blockIdx.x;            // 0..1 (d tile)
    int et = blockIdx.y;            // 0..31 (e tile)
    int z  = blockIdx.z;            // 0..95 = s*16 + h
    int s = z >> 4, h = z & 15;
    const float* src;
    switch (s) {
        case 0: src = w0; break; case 1: src = w1; break; case 2: src = w2; break;
        case 3: src = w3; break; case 4: src = w4; break; default: src = w5; break;
    }
    int tx = threadIdx.x & 31, ty = threadIdx.x >> 5;  // (32,8)
    int e0 = et * 32, d0 = dt * 32;
    #pragma unroll
    for (int i = 0; i < 4; i++)
        tile[ty + 8 * i][tx] = src[h * (E_DIM * D_DIM) + (e0 + ty + 8 * i) * D_DIM + d0 + tx];
    __syncthreads();
    #pragma unroll
    for (int i = 0; i < 4; i++) {
        float v = tile[tx][ty + 8 * i];
        __nv_bfloat16 hi, lo; bf_split(v, hi, lo);
        size_t oidx = (size_t)s * MB1 + (size_t)(h * 64 + d0 + ty + 8 * i) * E_DIM + e0 + tx;
        oh[oidx] = hi; ol[oidx] = lo;
    }
}
// [K,N] row-major -> Bt[n][k], fp16 hi/lo
__global__ void wt_split16(const float* __restrict__ src,
                           half* __restrict__ oh, half* __restrict__ ol, int K, int N) {
    __shared__ float tile[32][33];
    int n0 = blockIdx.x * 32, k0 = blockIdx.y * 32;
    int tx = threadIdx.x, ty = threadIdx.y;  // (32,8)
    #pragma unroll
    for (int i = 0; i < 4; i++)
        tile[ty + 8 * i][tx] = src[(size_t)(k0 + ty + 8 * i) * N + n0 + tx];
    __syncthreads();
    #pragma unroll
    for (int i = 0; i < 4; i++) {
        float v = tile[tx][ty + 8 * i];
        half hi, lo; h_split(v, hi, lo);
        size_t oidx = (size_t)(n0 + ty + 8 * i) * K + k0 + tx;
        oh[oidx] = hi; ol[oidx] = lo;
    }
}
// f32 -> bf16 hi/lo
__global__ void split4(const float* __restrict__ src,
                       __nv_bfloat16* __restrict__ oh, __nv_bfloat16* __restrict__ ol) {
    int i = blockIdx.x * 256 + threadIdx.x;
    float4 v = ((const float4*)src)[i];
    uint32_t h0, h1, l0, l1;
    packsplit(v.x, v.y, h0, l0);
    packsplit(v.z, v.w, h1, l1);
    *(uint32_t*)(oh + 4 * (size_t)i) = h0;
    *(uint32_t*)(oh + 4 * (size_t)i + 2) = h1;
    *(uint32_t*)(ol + 4 * (size_t)i) = l0;
    *(uint32_t*)(ol + 4 * (size_t)i + 2) = l1;
}

// ---------------- LayerNorm: OUT=0 -> bf16 hi/lo, OUT=1 -> fp16 ---------------
template <int OUT>
__global__ void __launch_bounds__(256) ln_kernel(const float* __restrict__ x,
                                                 const float* __restrict__ g,
                                                 const float* __restrict__ b,
                                                 __nv_bfloat16* __restrict__ oh,
                                                 __nv_bfloat16* __restrict__ ol,
                                                 half* __restrict__ o16) {
    int row = blockIdx.x;
    int t = threadIdx.x;
    float4 v = ((const float4*)(x + (size_t)row * E_DIM))[t];
    float s = v.x + v.y + v.z + v.w;
    float ss = v.x * v.x + v.y * v.y + v.z * v.z + v.w * v.w;
    #pragma unroll
    for (int o = 16; o > 0; o >>= 1) {
        s  += __shfl_xor_sync(0xffffffffu, s, o);
        ss += __shfl_xor_sync(0xffffffffu, ss, o);
    }
    __shared__ float red[2][8];
    int w = t >> 5, lane = t & 31;
    if (lane == 0) { red[0][w] = s; red[1][w] = ss; }
    __syncthreads();
    s = 0.0f; ss = 0.0f;
    #pragma unroll
    for (int i = 0; i < 8; i++) { s += red[0][i]; ss += red[1][i]; }
    float mu  = s * (1.0f / E_DIM);
    float var = ss * (1.0f / E_DIM) - mu * mu;
    float inv = rsqrtf(var + 1e-5f);
    float4 gv = ((const float4*)g)[t];
    float4 bv = ((const float4*)b)[t];
    float o0 = (v.x - mu) * inv * gv.x + bv.x;
    float o1 = (v.y - mu) * inv * gv.y + bv.y;
    float o2 = (v.z - mu) * inv * gv.z + bv.z;
    float o3 = (v.w - mu) * inv * gv.w + bv.w;
    size_t base = (size_t)row * E_DIM + t * 4;
    if (OUT == 0) {
        uint32_t h0, h1, l0, l1;
        packsplit(o0, o1, h0, l0);
        packsplit(o2, o3, h1, l1);
        *(uint32_t*)(oh + base) = h0; *(uint32_t*)(oh + base + 2) = h1;
        *(uint32_t*)(ol + base) = l0; *(uint32_t*)(ol + base + 2) = l1;
    } else {
        half2 p0, p1;
        p0.x = __float2half_rn(o0); p0.y = __float2half_rn(o1);
        p1.x = __float2half_rn(o2); p1.y = __float2half_rn(o3);
        *(half2*)(o16 + base) = p0; *(half2*)(o16 + base + 2) = p1;
    }
}

// ---------------- HMMA bf16x3 GEMM (QKV only) ---------------------------------
// EPI 3: bias -> bf16 hi/lo outputs (attention operands)
#define STAGE_BYTES 32768
#define GEMM_SMEM (2 * STAGE_BYTES + 256)
__global__ void __launch_bounds__(128, 2) gemm_hmma3(
    const __nv_bfloat16* __restrict__ Ah, const __nv_bfloat16* __restrict__ Al,
    const __nv_bfloat16* __restrict__ Bh, const __nv_bfloat16* __restrict__ Bl,
    const float* __restrict__ bias,
    __nv_bfloat16* __restrict__ outH, __nv_bfloat16* __restrict__ outL,
    int M, int N, int K) {
    extern __shared__ char dyn[];
    uint32_t sb = (smem_u32(dyn) + 127) & ~127u;
    int tid = threadIdx.x, lane = tid & 31, wid = tid >> 5;
    int rBase = blockIdx.y * 128, cBase = blockIdx.x * 128;
    int m0 = (wid >> 1) * 64, n0 = (wid & 1) * 64;

    float acc[4][8][4];
    #pragma unroll
    for (int i = 0; i < 4; i++)
        #pragma unroll
        for (int j = 0; j < 8; j++)
            #pragma unroll
            for (int u = 0; u < 4; u++) acc[i][j][u] = 0.0f;

    const int nc = K >> 5;
    auto loadStage = [&](int s, int c) {
        uint32_t base = sb + s * STAGE_BYTES;
        int k0 = c << 5;
        #pragma unroll
        for (int i = 0; i < 4; i++) {
            int idx = i * 128 + tid;
            int row = idx >> 2, seg = idx & 3;
            uint32_t off = (seg >> 1) * 4096 + (((row * 32) + (seg & 1) * 16) ^ ((row & 4) << 2));
            size_t ga = (size_t)(rBase + row) * K + k0 + seg * 8;
            size_t gb = (size_t)(cBase + row) * K + k0 + seg * 8;
            cpasync16(base + off,         Ah + ga);
            cpasync16(base + 8192 + off,  Al + ga);
            cpasync16(base + 16384 + off, Bh + gb);
            cpasync16(base + 24576 + off, Bl + gb);
        }
    };

    int aRow = (lane & 7) + ((lane >> 3) & 1) * 8;
    int aH   = lane >> 4;
    int bRow = lane & 7;
    int bH   = (lane >> 3) & 1;

    loadStage(0, 0); cpcommit();

    for (int c = 0; c < nc; c++) {
        if (c + 1 < nc) { loadStage((c + 1) & 1, c + 1); cpcommit(); cpwait<1>(); }
        else            { cpwait<0>(); }
        __syncthreads();
        uint32_t base = sb + (c & 1) * STAGE_BYTES;
        #pragma unroll
        for (int kc = 0; kc < 2; kc++) {
            uint32_t bh[8][2], bl[8][2];
            #pragma unroll
            for (int j = 0; j < 8; j++) {
                int row = n0 + j * 8 + bRow;
                uint32_t off = kc * 4096 + (((row * 32) + bH * 16) ^ ((row & 4) << 2));
                ldsm2(bh[j], base + 16384 + off);
                ldsm2(bl[j], base + 24576 + off);
            }
            #pragma unroll
            for (int i = 0; i < 4; i++) {
                uint32_t ah[4], al[4];
                int row = m0 + i * 16 + aRow;
                uint32_t off = kc * 4096 + (((row * 32) + aH * 16) ^ ((row & 4) << 2));
                ldsm4(ah, base + off);
                ldsm4(al, base + 8192 + off);
                #pragma unroll
                for (int j = 0; j < 8; j++) {
                    mma16816(acc[i][j], ah, bh[j]);
                    mma16816(acc[i][j], ah, bl[j]);
                    mma16816(acc[i][j], al, bh[j]);
                }
            }
        }
        __syncthreads();
    }

    int lr = lane >> 2, lc = (lane & 3) << 1;
    #pragma unroll
    for (int i = 0; i < 4; i++) {
        #pragma unroll
        for (int half_ = 0; half_ < 2; half_++) {
            size_t row = (size_t)(rBase + m0 + i * 16 + lr + half_ * 8);
            #pragma unroll
            for (int j = 0; j < 8; j++) {
                int col = cBase + n0 + j * 8 + lc;
                float v0 = acc[i][j][half_ * 2 + 0] + bias[col];
                float v1 = acc[i][j][half_ * 2 + 1] + bias[col + 1];
                uint32_t hp, lp;
                packsplit(v0, v1, hp, lp);
                *(uint32_t*)(outH + row * N + col) = hp;
                *(uint32_t*)(outL + row * N + col) = lp;
            }
        }
    }
}

// ---------------- fp16x2 GEMM (Wo / FFN) --------------------------------------
// C = epi(A(fp16) @ (Bh+Bl)^T + bias); EPI: 1 = bias+GELU->fp16, 2 = bias+res->f32
// CTA 128x128, BK=64, 4 warps (2x2), warp tile 64x64, double-buffered.
// Stage: A 16K @0, Bh 16K @16K, Bl 16K @32K; rows 128B, full swz128.
#define G16_STAGE 49152
#define G16_SMEM (2 * G16_STAGE + 256)
template <int EPI>
__global__ void __launch_bounds__(128, 2) gemm16(
    const half* __restrict__ A,
    const half* __restrict__ Bh, const half* __restrict__ Bl,
    const float* __restrict__ bias, const float* __restrict__ res,
    float* __restrict__ outF, half* __restrict__ outH,
    int M, int N, int K) {
    extern __shared__ char dyn[];
    uint32_t sb = (smem_u32(dyn) + 127) & ~127u;
    int tid = threadIdx.x, lane = tid & 31, wid = tid >> 5;
    int rBase = blockIdx.y * 128, cBase = blockIdx.x * 128;
    int m0 = (wid >> 1) * 64, n0 = (wid & 1) * 64;

    float acc[4][8][4];
    #pragma unroll
    for (int i = 0; i < 4; i++)
        #pragma unroll
        for (int j = 0; j < 8; j++)
            #pragma unroll
            for (int u = 0; u < 4; u++) acc[i][j][u] = 0.0f;

    const int nc = K >> 6;
    auto loadStage = [&](int s, int c) {
        uint32_t base = sb + s * G16_STAGE;
        int k0 = c << 6;
        #pragma unroll
        for (int i = 0; i < 8; i++) {
            int idx = i * 128 + tid;
            int row = idx >> 3, c16 = idx & 7;
            uint32_t off = swz128(row * 128 + c16 * 16);
            size_t ga = (size_t)(rBase + row) * K + k0 + c16 * 8;
            size_t gb = (size_t)(cBase + row) * K + k0 + c16 * 8;
            cpasync16(base + off,         A + ga);
            cpasync16(base + 16384 + off, Bh + gb);
            cpasync16(base + 32768 + off, Bl + gb);
        }
    };

    int aRow = (lane & 7) + ((lane >> 3) & 1) * 8;
    int aC   = lane >> 4;
    int bRow16 = (lane & 7) + ((lane >> 4) & 1) * 8;
    int bH     = (lane >> 3) & 1;

    loadStage(0, 0); cpcommit();

    for (int c = 0; c < nc; c++) {
        if (c + 1 < nc) { loadStage((c + 1) & 1, c + 1); cpcommit(); cpwait<1>(); }
        else            { cpwait<0>(); }
        __syncthreads();
        uint32_t base = sb + (c & 1) * G16_STAGE;
        #pragma unroll
        for (int kc = 0; kc < 4; kc++) {
            uint32_t bh[8][2], bl[8][2];
            #pragma unroll
            for (int jp = 0; jp < 4; jp++) {
                int row = n0 + jp * 16 + bRow16;
                uint32_t off = swz128(row * 128 + kc * 32 + bH * 16);
                uint32_t t4[4];
                ldsm4(t4, base + 16384 + off);
                bh[2 * jp][0] = t4[0]; bh[2 * jp][1] = t4[1];
                bh[2 * jp + 1][0] = t4[2]; bh[2 * jp + 1][1] = t4[3];
                ldsm4(t4, base + 32768 + off);
                bl[2 * jp][0] = t4[0]; bl[2 * jp][1] = t4[1];
                bl[2 * jp + 1][0] = t4[2]; bl[2 * jp + 1][1] = t4[3];
            }
            #pragma unroll
            for (int i = 0; i < 4; i++) {
                uint32_t a4[4];
                int row = m0 + i * 16 + aRow;
                ldsm4(a4, base + swz128(row * 128 + kc * 32 + aC * 16));
                #pragma unroll
                for (int j = 0; j < 8; j++) {
                    mma16816h(acc[i][j], a4, bh[j]);
                    mma16816h(acc[i][j], a4, bl[j]);
                }
            }
        }
        __syncthreads();
    }

    int lr = lane >> 2, lc = (lane & 3) << 1;
    #pragma unroll
    for (int i = 0; i < 4; i++) {
        #pragma unroll
        for (int half_ = 0; half_ < 2; half_++) {
            size_t row = (size_t)(rBase + m0 + i * 16 + lr + half_ * 8);
            #pragma unroll
            for (int j = 0; j < 8; j++) {
                int col = cBase + n0 + j * 8 + lc;
                float v0 = acc[i][j][half_ * 2 + 0] + bias[col];
                float v1 = acc[i][j][half_ * 2 + 1] + bias[col + 1];
                if (EPI == 1) {
                    v0 = 0.5f * v0 * (1.0f + erff(v0 * 0.70710678118654752f));
                    v1 = 0.5f * v1 * (1.0f + erff(v1 * 0.70710678118654752f));
                    half2 hp;
                    hp.x = __float2half_rn(v0); hp.y = __float2half_rn(v1);
                    *(half2*)(outH + row * N + col) = hp;
                } else {
                    float2 rv = *(const float2*)(res + row * N + col);
                    float2 o; o.x = v0 + rv.x; o.y = v1 + rv.y;
                    *(float2*)(outF + row * N + col) = o;
                }
            }
        }
    }
}

// ---------------- HMMA flash attention (bf16x3, D=64) -> fp16 out ------------
#define ATTN_SMEM (16384 + 2 * 32768 + 1024)
template <bool CAUSAL>
__global__ void __launch_bounds__(128, 2) attn_hmma(
    const __nv_bfloat16* __restrict__ Qh, const __nv_bfloat16* __restrict__ Ql,
    const __nv_bfloat16* __restrict__ Kh, const __nv_bfloat16* __restrict__ Kl,
    const __nv_bfloat16* __restrict__ Vh, const __nv_bfloat16* __restrict__ Vl,
    half* __restrict__ O) {
    extern __shared__ char dyn[];
    uint32_t sb = (smem_u32(dyn) + 1023) & ~1023u;
    int tid = threadIdx.x, lane = tid & 31, w = tid >> 5;
    int b = blockIdx.z, hh = blockIdx.y, qt = blockIdx.x;
    size_t headOff = (size_t)hh * D_DIM;
    size_t tokBase = (size_t)b * S_LEN;

    int aRow = (lane & 7) + ((lane >> 3) & 1) * 8;
    int aC = lane >> 4;

    {
        #pragma unroll
        for (int i = 0; i < 4; i++) {
            int idx = i * 128 + tid;
            int r = idx >> 3, c = idx & 7;
            uint32_t off = swz128(r * 128 + c * 16);
            size_t src = (tokBase + qt * 64 + r) * E_DIM + headOff + c * 8;
            cpasync16(sb + off, Qh + src);
            cpasync16(sb + 8192 + off, Ql + src);
        }
    }
    auto loadKV = [&](int s, int kt) {
        uint32_t base = sb + 16384 + s * 32768;
        #pragma unroll
        for (int i = 0; i < 4; i++) {
            int idx = i * 128 + tid;
            int r = idx >> 3, c = idx & 7;
            uint32_t off = swz128(r * 128 + c * 16);
            size_t src = (tokBase + kt * 64 + r) * E_DIM + headOff + c * 8;
            cpasync16(base + off,         Kh + src);
            cpasync16(base + 8192 + off,  Kl + src);
            cpasync16(base + 16384 + off, Vh + src);
            cpasync16(base + 24576 + off, Vl + src);
        }
    };
    loadKV(0, 0);
    cpcommit();

    uint32_t qh[4][4], ql[4][4];
    float oacc[8][4];
    float mrow[2] = {-1e30f, -1e30f}, lrow[2] = {0.0f, 0.0f};
    #pragma unroll
    for (int j = 0; j < 8; j++)
        #pragma unroll
        for (int u = 0; u < 4; u++) oacc[j][u] = 0.0f;

    const int ntiles = CAUSAL ? (qt + 1) : (S_LEN / 64);
    for (int kt = 0; kt < ntiles; kt++) {
        if (kt + 1 < ntiles) { loadKV((kt + 1) & 1, kt + 1); cpcommit(); cpwait<1>(); }
        else                 { cpwait<0>(); }
        __syncthreads();
        if (kt == 0) {
            #pragma unroll
            for (int s = 0; s < 4; s++) {
                uint32_t addr = sb + swz128((w * 16 + aRow) * 128 + s * 32 + aC * 16);
                ldsm4(qh[s], addr);
                ldsm4(ql[s], addr + 8192);
            }
        }
        uint32_t kb = sb + 16384 + (kt & 1) * 32768;
        uint32_t vb = kb + 16384;

        float sacc[8][4];
        #pragma unroll
        for (int j = 0; j < 8; j++)
            #pragma unroll
            for (int u = 0; u < 4; u++) sacc[j][u] = 0.0f;
        #pragma unroll
        for (int s = 0; s < 4; s++) {
            #pragma unroll
            for (int jp = 0; jp < 4; jp++) {
                uint32_t addr = kb + swz128((jp * 16 + aRow) * 128 + s * 32 + aC * 16);
                uint32_t kh4[4], kl4[4];
                ldsm4(kh4, addr);
                ldsm4(kl4, addr + 8192);
                uint32_t b0h[2] = {kh4[0], kh4[2]}, b1h[2] = {kh4[1], kh4[3]};
                uint32_t b0l[2] = {kl4[0], kl4[2]}, b1l[2] = {kl4[1], kl4[3]};
                mma16816(sacc[2 * jp],     qh[s], b0h);
                mma16816(sacc[2 * jp],     ql[s], b0h);
                mma16816(sacc[2 * jp],     qh[s], b0l);
                mma16816(sacc[2 * jp + 1], qh[s], b1h);
                mma16816(sacc[2 * jp + 1], ql[s], b1h);
                mma16816(sacc[2 * jp + 1], qh[s], b1l);
            }
        }

        if (CAUSAL && kt == qt) {
            int ql0 = w * 16 + (lane >> 2);
            #pragma unroll
            for (int j = 0; j < 8; j++)
                #pragma unroll
                for (int u = 0; u < 4; u++) {
                    int kcol = j * 8 + ((lane & 3) << 1) + (u & 1);
                    int qrow = ql0 + (u >> 1) * 8;
                    if (kcol > qrow) sacc[j][u] = -1e30f;
                }
        }

        #pragma unroll
        for (int h2 = 0; h2 < 2; h2++) {
            float mt = -1e30f;
            #pragma unroll
            for (int j = 0; j < 8; j++)
                mt = fmaxf(mt, fmaxf(sacc[j][2 * h2], sacc[j][2 * h2 + 1]));
            mt = fmaxf(mt, __shfl_xor_sync(0xffffffffu, mt, 1));
            mt = fmaxf(mt, __shfl_xor_sync(0xffffffffu, mt, 2));
            float mn = fmaxf(mrow[h2], mt);
            float sc = __expf(mrow[h2] - mn);
            mrow[h2] = mn;
            float ts = 0.0f;
            #pragma unroll
            for (int j = 0; j < 8; j++) {
                sacc[j][2 * h2]     = __expf(sacc[j][2 * h2] - mn);
                sacc[j][2 * h2 + 1] = __expf(sacc[j][2 * h2 + 1] - mn);
                ts += sacc[j][2 * h2] + sacc[j][2 * h2 + 1];
            }
            ts += __shfl_xor_sync(0xffffffffu, ts, 1);
            ts += __shfl_xor_sync(0xffffffffu, ts, 2);
            lrow[h2] = lrow[h2] * sc + ts;
            #pragma unroll
            for (int j = 0; j < 8; j++) {
                oacc[j][2 * h2]     *= sc;
                oacc[j][2 * h2 + 1] *= sc;
            }
        }

        #pragma unroll
        for (int s = 0; s < 4; s++) {
            uint32_t ph4[4], pl4[4];
            packsplit(sacc[2 * s][0],     sacc[2 * s][1],     ph4[0], pl4[0]);
            packsplit(sacc[2 * s][2],     sacc[2 * s][3],     ph4[1], pl4[1]);
            packsplit(sacc[2 * s + 1][0], sacc[2 * s + 1][1], ph4[2], pl4[2]);
            packsplit(sacc[2 * s + 1][2], sacc[2 * s + 1][3], ph4[3], pl4[3]);
            #pragma unroll
            for (int jp = 0; jp < 4; jp++) {
                uint32_t addr = vb + swz128((s * 16 + aRow) * 128 + jp * 32 + aC * 16);
                uint32_t vh4[4], vl4[4];
                ldsm4t(vh4, addr);
                ldsm4t(vl4, addr + 8192);
                uint32_t b0h[2] = {vh4[0], vh4[1]}, b1h[2] = {vh4[2], vh4[3]};
                uint32_t b0l[2] = {vl4[0], vl4[1]}, b1l[2] = {vl4[2], vl4[3]};
                mma16816(oacc[2 * jp],     ph4, b0h);
                mma16816(oacc[2 * jp],     pl4, b0h);
                mma16816(oacc[2 * jp],     ph4, b0l);
                mma16816(oacc[2 * jp + 1], ph4, b1h);
                mma16816(oacc[2 * jp + 1], pl4, b1h);
                mma16816(oacc[2 * jp + 1], ph4, b1l);
            }
        }
        __syncthreads();
    }

    #pragma unroll
    for (int h2 = 0; h2 < 2; h2++) {
        float inv = 1.0f / lrow[h2];
        int trow = qt * 64 + w * 16 + (lane >> 2) + h2 * 8;
        size_t rp = (tokBase + trow) * E_DIM + headOff;
        #pragma unroll
        for (int j = 0; j < 8; j++) {
            half2 o;
            o.x = __float2half_rn(oacc[j][2 * h2] * inv);
            o.y = __float2half_rn(oacc[j][2 * h2 + 1] * inv);
            int col = j * 8 + ((lane & 3) << 1);
            *(half2*)(O + rp + col) = o;
        }
    }
}

// ---------------- launch ------------------------------------------------------
extern "C" void kernel_launch(void* const* d_in, const int* in_sizes, int n_in,
                              void* d_out, int out_size) {
    const float* x    = (const float*)d_in[0];
    const float* enc  = (const float*)d_in[1];
    const float* ln1g = (const float*)d_in[2];
    const float* ln1b = (const float*)d_in[3];
    const float* ln2g = (const float*)d_in[4];
    const float* ln2b = (const float*)d_in[5];
    const float* ln3g = (const float*)d_in[6];
    const float* ln3b = (const float*)d_in[7];
    const float* Wq1  = (const float*)d_in[8];
    const float* bq1  = (const float*)d_in[9];
    const float* Wk1  = (const float*)d_in[10];
    const float* bk1  = (const float*)d_in[11];
    const float* Wv1  = (const float*)d_in[12];
    const float* bv1  = (const float*)d_in[13];
    const float* Wo1  = (const float*)d_in[14];
    const float* bo1  = (const float*)d_in[15];
    const float* Wq2  = (const float*)d_in[16];
    const float* bq2  = (const float*)d_in[17];
    const float* Wk2  = (const float*)d_in[18];
    const float* bk2  = (const float*)d_in[19];
    const float* Wv2  = (const float*)d_in[20];
    const float* bv2  = (const float*)d_in[21];
    const float* Wo2  = (const float*)d_in[22];
    const float* bo2  = (const float*)d_in[23];
    const float* Wup  = (const float*)d_in[24];
    const float* bup  = (const float*)d_in[25];
    const float* Wdn  = (const float*)d_in[26];
    const float* bdn  = (const float*)d_in[27];
    float* out = (float*)d_out;

    __nv_bfloat16 *Bh, *Bl, *hh, *hl, *ech, *ecl, *qh, *ql, *kh, *kl, *vh, *vl;
    half *W16h, *W16l, *a16, *h16;
    float *x1, *x2;
    cudaGetSymbolAddress((void**)&Bh,   g_Bh);
    cudaGetSymbolAddress((void**)&Bl,   g_Bl);
    cudaGetSymbolAddress((void**)&W16h, g_W16h);
    cudaGetSymbolAddress((void**)&W16l, g_W16l);
    cudaGetSymbolAddress((void**)&hh,   g_hh);
    cudaGetSymbolAddress((void**)&hl,   g_hl);
    cudaGetSymbolAddress((void**)&ech,  g_ech);
    cudaGetSymbolAddress((void**)&ecl,  g_ecl);
    cudaGetSymbolAddress((void**)&qh,   g_qh);
    cudaGetSymbolAddress((void**)&ql,   g_ql);
    cudaGetSymbolAddress((void**)&kh,   g_kh);
    cudaGetSymbolAddress((void**)&kl,   g_kl);
    cudaGetSymbolAddress((void**)&vh,   g_vh);
    cudaGetSymbolAddress((void**)&vl,   g_vl);
    cudaGetSymbolAddress((void**)&a16,  g_a16);
    cudaGetSymbolAddress((void**)&h16,  g_h16);
    cudaGetSymbolAddress((void**)&x1,   g_x1);
    cudaGetSymbolAddress((void**)&x2,   g_x2);

    cudaFuncSetAttribute(gemm_hmma3, cudaFuncAttributeMaxDynamicSharedMemorySize, GEMM_SMEM);
    cudaFuncSetAttribute(gemm16<1>, cudaFuncAttributeMaxDynamicSharedMemorySize, G16_SMEM);
    cudaFuncSetAttribute(gemm16<2>, cudaFuncAttributeMaxDynamicSharedMemorySize, G16_SMEM);
    cudaFuncSetAttribute(attn_hmma<true>,  cudaFuncAttributeMaxDynamicSharedMemorySize, ATTN_SMEM);
    cudaFuncSetAttribute(attn_hmma<false>, cudaFuncAttributeMaxDynamicSharedMemorySize, ATTN_SMEM);

    const int WS = E_DIM * E_DIM;  // 1M elements per square slot
    dim3 gSq(8, 32);
    dim3 gUp(32, 32);
    dim3 gAttn(S_LEN / 64, H_NUM, B_NUM);
    dim3 trB(32, 8);

    // launch order: index 5 (ncu capture) = a QKV GEMM
    wqkv_split_all<<<dim3(2, 32, 96), 256>>>(Wq1, Wk1, Wv1, Wq2, Wk2, Wv2, Bh, Bl);    // 0
    split4<<<4096, 256>>>(enc, ech, ecl);                                               // 1
    ln_kernel<0><<<M_ROWS, 256>>>(x, ln1g, ln1b, hh, hl, nullptr);                      // 2
    wt_split16<<<dim3(32, 32), trB>>>(Wo1, W16h + 0 * WS, W16l + 0 * WS, 1024, 1024);   // 3
    wt_split16<<<dim3(128, 32), trB>>>(Wup, W16h + 2 * WS, W16l + 2 * WS, 1024, 4096);  // 4
    gemm_hmma3<<<gSq, 128, GEMM_SMEM>>>(hh, hl, Bh + 0 * WS, Bl + 0 * WS, bq1,
                                        qh, ql, M_ROWS, E_DIM, E_DIM);                  // 5 (ncu)
    gemm_hmma3<<<gSq, 128, GEMM_SMEM>>>(hh, hl, Bh + 1 * WS, Bl + 1 * WS, bk1,
                                        kh, kl, M_ROWS, E_DIM, E_DIM);                  // 6
    gemm_hmma3<<<gSq, 128, GEMM_SMEM>>>(hh, hl, Bh + 2 * WS, Bl + 2 * WS, bv1,
                                        vh, vl, M_ROWS, E_DIM, E_DIM);                  // 7
    attn_hmma<true><<<gAttn, 128, ATTN_SMEM>>>(qh, ql, kh, kl, vh, vl, a16);            // 8
    wt_split16<<<dim3(32, 32), trB>>>(Wo2, W16h + 1 * WS, W16l + 1 * WS, 1024, 1024);   // 9
    gemm16<2><<<gSq, 128, G16_SMEM>>>(a16, W16h + 0 * WS, W16l + 0 * WS, bo1, x,
                                      x1, nullptr, M_ROWS, E_DIM, E_DIM);               // 10

    ln_kernel<0><<<M_ROWS, 256>>>(x1, ln2g, ln2b, hh, hl, nullptr);                     // 11
    gemm_hmma3<<<gSq, 128, GEMM_SMEM>>>(hh, hl,   Bh + 3 * WS, Bl + 3 * WS, bq2,
                                        qh, ql, M_ROWS, E_DIM, E_DIM);                  // 12
    gemm_hmma3<<<gSq, 128, GEMM_SMEM>>>(ech, ecl, Bh + 4 * WS, Bl + 4 * WS, bk2,
                                        kh, kl, M_ROWS, E_DIM, E_DIM);                  // 13
    gemm_hmma3<<<gSq, 128, GEMM_SMEM>>>(ech, ecl, Bh + 5 * WS, Bl + 5 * WS, bv2,
                                        vh, vl, M_ROWS, E_DIM, E_DIM);                  // 14
    attn_hmma<false><<<gAttn, 128, ATTN_SMEM>>>(qh, ql, kh, kl, vh, vl, a16);           // 15
    wt_split16<<<dim3(32, 128), trB>>>(Wdn, W16h + 6 * WS, W16l + 6 * WS, 4096, 1024);  // 16
    gemm16<2><<<gSq, 128, G16_SMEM>>>(a16, W16h + 1 * WS, W16l + 1 * WS, bo2, x1,
                                      x2, nullptr, M_ROWS, E_DIM, E_DIM);               // 17

    ln_kernel<1><<<M_ROWS, 256>>>(x2, ln3g, ln3b, nullptr, nullptr, h16);               // 18
    gemm16<1><<<gUp, 128, G16_SMEM>>>(h16, W16h + 2 * WS, W16l + 2 * WS, bup, nullptr,
                                      nullptr, a16, M_ROWS, F_DIM, E_DIM);              // 19
    gemm16<2><<<gSq, 128, G16_SMEM>>>(a16, W16h + 6 * WS, W16l + 6 * WS, bdn, x2,
                                      out, nullptr, M_ROWS, E_DIM, F_DIM);              // 20
}

// round 7
// speedup vs baseline: 4.0819x; 1.2954x over previous
#include <cuda_runtime.h>
#include <cuda_fp16.h>
#include <math.h>
#include <cstdint>

#define E_DIM 1024
#define H_NUM 16
#define D_DIM 64
#define B_NUM 4
#define S_LEN 1024
#define F_DIM 4096
#define M_ROWS (B_NUM * S_LEN)  // 4096
#define MB1 (1024 * 1024)

// ---------------- scratch (static device globals) ---------------------------
// Weight slots (fp16 hi/lo, [N][K] transposed): QKV1 0-2, QKV2 3-5, Wo1 6, Wo2 7,
// Wup 8-11, Wdn 12-15.
__device__ __align__(16) half g_W16h[16 * MB1], g_W16l[16 * MB1];
__device__ __align__(16) half g_h16[4 * MB1];          // LN out (single fp16)
__device__ __align__(16) half g_e16[4 * MB1];          // enc (single fp16)
__device__ __align__(16) half g_q16[4 * MB1];          // Q (single fp16)
__device__ __align__(16) half g_kh16[4 * MB1], g_kl16[4 * MB1];
__device__ __align__(16) half g_vh16[4 * MB1], g_vl16[4 * MB1];
__device__ __align__(16) half g_a16[16 * MB1];         // attn out (4M) / GELU out (16M)
__device__ __align__(16) float g_x1[4 * MB1], g_x2[4 * MB1];

// ---------------- PTX helpers -----------------------------------------------
__device__ __forceinline__ uint32_t smem_u32(const void* p) {
    uint32_t a;
    asm("{ .reg .u64 t; cvta.to.shared.u64 t, %1; cvt.u32.u64 %0, t; }" : "=r"(a) : "l"(p));
    return a;
}
__device__ __forceinline__ void cpasync16(uint32_t dst, const void* src) {
    asm volatile("cp.async.cg.shared.global [%0], [%1], 16;" :: "r"(dst), "l"(src));
}
__device__ __forceinline__ void cpcommit() { asm volatile("cp.async.commit_group;" ::: "memory"); }
template <int N>
__device__ __forceinline__ void cpwait() { asm volatile("cp.async.wait_group %0;" :: "n"(N) : "memory"); }

__device__ __forceinline__ void ldsm4(uint32_t (&r)[4], uint32_t addr) {
    asm volatile("ldmatrix.sync.aligned.m8n8.x4.shared.b16 {%0,%1,%2,%3}, [%4];"
                 : "=r"(r[0]), "=r"(r[1]), "=r"(r[2]), "=r"(r[3]) : "r"(addr));
}
__device__ __forceinline__ void ldsm4t(uint32_t (&r)[4], uint32_t addr) {
    asm volatile("ldmatrix.sync.aligned.m8n8.x4.trans.shared.b16 {%0,%1,%2,%3}, [%4];"
                 : "=r"(r[0]), "=r"(r[1]), "=r"(r[2]), "=r"(r[3]) : "r"(addr));
}
__device__ __forceinline__ void mma16816h(float (&d)[4], const uint32_t (&a)[4],
                                          const uint32_t (&b)[2]) {
    asm volatile(
        "mma.sync.aligned.m16n8k16.row.col.f32.f16.f16.f32 "
        "{%0,%1,%2,%3}, {%4,%5,%6,%7}, {%8,%9}, {%0,%1,%2,%3};"
        : "+f"(d[0]), "+f"(d[1]), "+f"(d[2]), "+f"(d[3])
        : "r"(a[0]), "r"(a[1]), "r"(a[2]), "r"(a[3]), "r"(b[0]), "r"(b[1]));
}
__device__ __forceinline__ uint32_t swz128(uint32_t o) { return o ^ ((o >> 3) & 0x70); }

__device__ __forceinline__ void h_split(float v, half& hi, half& lo) {
    hi = __float2half_rn(v);
    lo = __float2half_rn(v - __half2float(hi));
}
__device__ __forceinline__ void packh2(float a, float b, uint32_t& r) {
    half2 p; p.x = __float2half_rn(a); p.y = __float2half_rn(b);
    r = *(uint32_t*)&p;
}
__device__ __forceinline__ void packsplit16(float a, float b, uint32_t& hi, uint32_t& lo) {
    half ah, al, bh, bl;
    h_split(a, ah, al); h_split(b, bh, bl);
    half2 hp, lp;
    hp.x = ah; hp.y = bh; lp.x = al; lp.y = bl;
    hi = *(uint32_t*)&hp; lo = *(uint32_t*)&lp;
}

// ---------------- weight prep -------------------------------------------------
// All 6 QKV weights: [H,E,D] -> Bt[n=h*64+d][k=e], fp16 hi/lo (slots 0-5).
__global__ void __launch_bounds__(256) wqkv_split_all(
    const float* __restrict__ w0, const float* __restrict__ w1,
    const float* __restrict__ w2, const float* __restrict__ w3,
    const float* __restrict__ w4, const float* __restrict__ w5,
    half* __restrict__ oh, half* __restrict__ ol) {
    __shared__ float tile[32][33];
    int dt = blockIdx.x;            // 0..1
    int et = blockIdx.y;            // 0..31
    int z  = blockIdx.z;            // s*16 + h
    int s = z >> 4, h = z & 15;
    const float* src;
    switch (s) {
        case 0: src = w0; break; case 1: src = w1; break; case 2: src = w2; break;
        case 3: src = w3; break; case 4: src = w4; break; default: src = w5; break;
    }
    int tx = threadIdx.x & 31, ty = threadIdx.x >> 5;
    int e0 = et * 32, d0 = dt * 32;
    #pragma unroll
    for (int i = 0; i < 4; i++)
        tile[ty + 8 * i][tx] = src[h * (E_DIM * D_DIM) + (e0 + ty + 8 * i) * D_DIM + d0 + tx];
    __syncthreads();
    #pragma unroll
    for (int i = 0; i < 4; i++) {
        float v = tile[tx][ty + 8 * i];
        half hi, lo; h_split(v, hi, lo);
        size_t oidx = (size_t)s * MB1 + (size_t)(h * 64 + d0 + ty + 8 * i) * E_DIM + e0 + tx;
        oh[oidx] = hi; ol[oidx] = lo;
    }
}
// [K,N] row-major -> Bt[n][k], fp16 hi/lo
__global__ void wt_split16(const float* __restrict__ src,
                           half* __restrict__ oh, half* __restrict__ ol, int K, int N) {
    __shared__ float tile[32][33];
    int n0 = blockIdx.x * 32, k0 = blockIdx.y * 32;
    int tx = threadIdx.x, ty = threadIdx.y;
    #pragma unroll
    for (int i = 0; i < 4; i++)
        tile[ty + 8 * i][tx] = src[(size_t)(k0 + ty + 8 * i) * N + n0 + tx];
    __syncthreads();
    #pragma unroll
    for (int i = 0; i < 4; i++) {
        float v = tile[tx][ty + 8 * i];
        half hi, lo; h_split(v, hi, lo);
        size_t oidx = (size_t)(n0 + ty + 8 * i) * K + k0 + tx;
        oh[oidx] = hi; ol[oidx] = lo;
    }
}
// f32 -> single fp16
__global__ void cvt16(const float* __restrict__ src, half* __restrict__ dst) {
    int i = blockIdx.x * 256 + threadIdx.x;
    float4 v = ((const float4*)src)[i];
    uint32_t p0, p1;
    packh2(v.x, v.y, p0);
    packh2(v.z, v.w, p1);
    *(uint32_t*)(dst + 4 * (size_t)i) = p0;
    *(uint32_t*)(dst + 4 * (size_t)i + 2) = p1;
}

// ---------------- LayerNorm: f32 -> single fp16 -------------------------------
__global__ void __launch_bounds__(256) ln_kernel(const float* __restrict__ x,
                                                 const float* __restrict__ g,
                                                 const float* __restrict__ b,
                                                 half* __restrict__ o16) {
    int row = blockIdx.x;
    int t = threadIdx.x;
    float4 v = ((const float4*)(x + (size_t)row * E_DIM))[t];
    float s = v.x + v.y + v.z + v.w;
    float ss = v.x * v.x + v.y * v.y + v.z * v.z + v.w * v.w;
    #pragma unroll
    for (int o = 16; o > 0; o >>= 1) {
        s  += __shfl_xor_sync(0xffffffffu, s, o);
        ss += __shfl_xor_sync(0xffffffffu, ss, o);
    }
    __shared__ float red[2][8];
    int w = t >> 5, lane = t & 31;
    if (lane == 0) { red[0][w] = s; red[1][w] = ss; }
    __syncthreads();
    s = 0.0f; ss = 0.0f;
    #pragma unroll
    for (int i = 0; i < 8; i++) { s += red[0][i]; ss += red[1][i]; }
    float mu  = s * (1.0f / E_DIM);
    float var = ss * (1.0f / E_DIM) - mu * mu;
    float inv = rsqrtf(var + 1e-5f);
    float4 gv = ((const float4*)g)[t];
    float4 bv = ((const float4*)b)[t];
    float o0 = (v.x - mu) * inv * gv.x + bv.x;
    float o1 = (v.y - mu) * inv * gv.y + bv.y;
    float o2 = (v.z - mu) * inv * gv.z + bv.z;
    float o3 = (v.w - mu) * inv * gv.w + bv.w;
    size_t base = (size_t)row * E_DIM + t * 4;
    uint32_t p0, p1;
    packh2(o0, o1, p0);
    packh2(o2, o3, p1);
    *(uint32_t*)(o16 + base) = p0;
    *(uint32_t*)(o16 + base + 2) = p1;
}

// ---------------- fp16x2 GEMM --------------------------------------------------
// C = epi(A(fp16) @ (Bh+Bl)^T + bias)
// EPI: 0 bias -> fp16 single, 1 bias+GELU -> fp16, 2 bias+res -> f32,
//      3 bias -> fp16 hi/lo
// CTA 128x128, BK=64, 4 warps (2x2), warp tile 64x64, double-buffered.
#define G16_STAGE 49152
#define G16_SMEM (2 * G16_STAGE + 256)
template <int EPI>
__global__ void __launch_bounds__(128, 2) gemm16(
    const half* __restrict__ A,
    const half* __restrict__ Bh, const half* __restrict__ Bl,
    const float* __restrict__ bias, const float* __restrict__ res,
    float* __restrict__ outF, half* __restrict__ outH, half* __restrict__ outL,
    int M, int N, int K) {
    extern __shared__ char dyn[];
    uint32_t sb = (smem_u32(dyn) + 127) & ~127u;
    int tid = threadIdx.x, lane = tid & 31, wid = tid >> 5;
    int rBase = blockIdx.y * 128, cBase = blockIdx.x * 128;
    int m0 = (wid >> 1) * 64, n0 = (wid & 1) * 64;

    float acc[4][8][4];
    #pragma unroll
    for (int i = 0; i < 4; i++)
        #pragma unroll
        for (int j = 0; j < 8; j++)
            #pragma unroll
            for (int u = 0; u < 4; u++) acc[i][j][u] = 0.0f;

    const int nc = K >> 6;
    auto loadStage = [&](int s, int c) {
        uint32_t base = sb + s * G16_STAGE;
        int k0 = c << 6;
        #pragma unroll
        for (int i = 0; i < 8; i++) {
            int idx = i * 128 + tid;
            int row = idx >> 3, c16 = idx & 7;
            uint32_t off = swz128(row * 128 + c16 * 16);
            size_t ga = (size_t)(rBase + row) * K + k0 + c16 * 8;
            size_t gb = (size_t)(cBase + row) * K + k0 + c16 * 8;
            cpasync16(base + off,         A + ga);
            cpasync16(base + 16384 + off, Bh + gb);
            cpasync16(base + 32768 + off, Bl + gb);
        }
    };

    int aRow = (lane & 7) + ((lane >> 3) & 1) * 8;
    int aC   = lane >> 4;
    int bRow16 = (lane & 7) + ((lane >> 4) & 1) * 8;
    int bH     = (lane >> 3) & 1;

    loadStage(0, 0); cpcommit();

    for (int c = 0; c < nc; c++) {
        if (c + 1 < nc) { loadStage((c + 1) & 1, c + 1); cpcommit(); cpwait<1>(); }
        else            { cpwait<0>(); }
        __syncthreads();
        uint32_t base = sb + (c & 1) * G16_STAGE;
        #pragma unroll
        for (int kc = 0; kc < 4; kc++) {
            uint32_t bh[8][2], bl[8][2];
            #pragma unroll
            for (int jp = 0; jp < 4; jp++) {
                int row = n0 + jp * 16 + bRow16;
                uint32_t off = swz128(row * 128 + kc * 32 + bH * 16);
                uint32_t t4[4];
                ldsm4(t4, base + 16384 + off);
                bh[2 * jp][0] = t4[0]; bh[2 * jp][1] = t4[1];
                bh[2 * jp + 1][0] = t4[2]; bh[2 * jp + 1][1] = t4[3];
                ldsm4(t4, base + 32768 + off);
                bl[2 * jp][0] = t4[0]; bl[2 * jp][1] = t4[1];
                bl[2 * jp + 1][0] = t4[2]; bl[2 * jp + 1][1] = t4[3];
            }
            #pragma unroll
            for (int i = 0; i < 4; i++) {
                uint32_t a4[4];
                int row = m0 + i * 16 + aRow;
                ldsm4(a4, base + swz128(row * 128 + kc * 32 + aC * 16));
                #pragma unroll
                for (int j = 0; j < 8; j++) {
                    mma16816h(acc[i][j], a4, bh[j]);
                    mma16816h(acc[i][j], a4, bl[j]);
                }
            }
        }
        __syncthreads();
    }

    int lr = lane >> 2, lc = (lane & 3) << 1;
    #pragma unroll
    for (int i = 0; i < 4; i++) {
        #pragma unroll
        for (int half_ = 0; half_ < 2; half_++) {
            size_t row = (size_t)(rBase + m0 + i * 16 + lr + half_ * 8);
            #pragma unroll
            for (int j = 0; j < 8; j++) {
                int col = cBase + n0 + j * 8 + lc;
                float v0 = acc[i][j][half_ * 2 + 0] + bias[col];
                float v1 = acc[i][j][half_ * 2 + 1] + bias[col + 1];
                if (EPI == 0) {
                    uint32_t p;
                    packh2(v0, v1, p);
                    *(uint32_t*)(outH + row * N + col) = p;
                } else if (EPI == 3) {
                    uint32_t hp, lp;
                    packsplit16(v0, v1, hp, lp);
                    *(uint32_t*)(outH + row * N + col) = hp;
                    *(uint32_t*)(outL + row * N + col) = lp;
                } else if (EPI == 1) {
                    v0 = 0.5f * v0 * (1.0f + erff(v0 * 0.70710678118654752f));
                    v1 = 0.5f * v1 * (1.0f + erff(v1 * 0.70710678118654752f));
                    uint32_t p;
                    packh2(v0, v1, p);
                    *(uint32_t*)(outH + row * N + col) = p;
                } else {
                    float2 rv = *(const float2*)(res + row * N + col);
                    float2 o; o.x = v0 + rv.x; o.y = v1 + rv.y;
                    *(float2*)(outF + row * N + col) = o;
                }
            }
        }
    }
}

// ---------------- fp16x2 flash attention (D=64) -> fp16 out -------------------
// Q single fp16; K, V fp16 hi/lo. grid (S/64, H, B), 128 threads.
// SMEM: Q 8K @0 | stage s at 8K + s*32K: Kh, Kl, Vh, Vl (8K each).
#define ATTN_SMEM (8192 + 2 * 32768 + 1024)
template <bool CAUSAL>
__global__ void __launch_bounds__(128, 2) attn16(
    const half* __restrict__ Q,
    const half* __restrict__ Kh, const half* __restrict__ Kl,
    const half* __restrict__ Vh, const half* __restrict__ Vl,
    half* __restrict__ O) {
    extern __shared__ char dyn[];
    uint32_t sb = (smem_u32(dyn) + 1023) & ~1023u;
    int tid = threadIdx.x, lane = tid & 31, w = tid >> 5;
    int b = blockIdx.z, hh = blockIdx.y, qt = blockIdx.x;
    size_t headOff = (size_t)hh * D_DIM;
    size_t tokBase = (size_t)b * S_LEN;

    int aRow = (lane & 7) + ((lane >> 3) & 1) * 8;
    int aC = lane >> 4;

    {
        #pragma unroll
        for (int i = 0; i < 4; i++) {
            int idx = i * 128 + tid;
            int r = idx >> 3, c = idx & 7;
            uint32_t off = swz128(r * 128 + c * 16);
            cpasync16(sb + off, Q + (tokBase + qt * 64 + r) * E_DIM + headOff + c * 8);
        }
    }
    auto loadKV = [&](int s, int kt) {
        uint32_t base = sb + 8192 + s * 32768;
        #pragma unroll
        for (int i = 0; i < 4; i++) {
            int idx = i * 128 + tid;
            int r = idx >> 3, c = idx & 7;
            uint32_t off = swz128(r * 128 + c * 16);
            size_t src = (tokBase + kt * 64 + r) * E_DIM + headOff + c * 8;
            cpasync16(base + off,         Kh + src);
            cpasync16(base + 8192 + off,  Kl + src);
            cpasync16(base + 16384 + off, Vh + src);
            cpasync16(base + 24576 + off, Vl + src);
        }
    };
    loadKV(0, 0);
    cpcommit();

    uint32_t qf[4][4];
    float oacc[8][4];
    float mrow[2] = {-1e30f, -1e30f}, lrow[2] = {0.0f, 0.0f};
    #pragma unroll
    for (int j = 0; j < 8; j++)
        #pragma unroll
        for (int u = 0; u < 4; u++) oacc[j][u] = 0.0f;

    const int ntiles = CAUSAL ? (qt + 1) : (S_LEN / 64);
    for (int kt = 0; kt < ntiles; kt++) {
        if (kt + 1 < ntiles) { loadKV((kt + 1) & 1, kt + 1); cpcommit(); cpwait<1>(); }
        else                 { cpwait<0>(); }
        __syncthreads();
        if (kt == 0) {
            #pragma unroll
            for (int s = 0; s < 4; s++)
                ldsm4(qf[s], sb + swz128((w * 16 + aRow) * 128 + s * 32 + aC * 16));
        }
        uint32_t kb = sb + 8192 + (kt & 1) * 32768;
        uint32_t vb = kb + 16384;

        // ---- scores ----
        float sacc[8][4];
        #pragma unroll
        for (int j = 0; j < 8; j++)
            #pragma unroll
            for (int u = 0; u < 4; u++) sacc[j][u] = 0.0f;
        #pragma unroll
        for (int s = 0; s < 4; s++) {
            #pragma unroll
            for (int jp = 0; jp < 4; jp++) {
                uint32_t addr = kb + swz128((jp * 16 + aRow) * 128 + s * 32 + aC * 16);
                uint32_t kh4[4], kl4[4];
                ldsm4(kh4, addr);
                ldsm4(kl4, addr + 8192);
                uint32_t b0h[2] = {kh4[0], kh4[2]}, b1h[2] = {kh4[1], kh4[3]};
                uint32_t b0l[2] = {kl4[0], kl4[2]}, b1l[2] = {kl4[1], kl4[3]};
                mma16816h(sacc[2 * jp],     qf[s], b0h);
                mma16816h(sacc[2 * jp],     qf[s], b0l);
                mma16816h(sacc[2 * jp + 1], qf[s], b1h);
                mma16816h(sacc[2 * jp + 1], qf[s], b1l);
            }
        }

        if (CAUSAL && kt == qt) {
            int ql0 = w * 16 + (lane >> 2);
            #pragma unroll
            for (int j = 0; j < 8; j++)
                #pragma unroll
                for (int u = 0; u < 4; u++) {
                    int kcol = j * 8 + ((lane & 3) << 1) + (u & 1);
                    int qrow = ql0 + (u >> 1) * 8;
                    if (kcol > qrow) sacc[j][u] = -1e30f;
                }
        }

        // ---- online softmax ----
        #pragma unroll
        for (int h2 = 0; h2 < 2; h2++) {
            float mt = -1e30f;
            #pragma unroll
            for (int j = 0; j < 8; j++)
                mt = fmaxf(mt, fmaxf(sacc[j][2 * h2], sacc[j][2 * h2 + 1]));
            mt = fmaxf(mt, __shfl_xor_sync(0xffffffffu, mt, 1));
            mt = fmaxf(mt, __shfl_xor_sync(0xffffffffu, mt, 2));
            float mn = fmaxf(mrow[h2], mt);
            float sc = __expf(mrow[h2] - mn);
            mrow[h2] = mn;
            float ts = 0.0f;
            #pragma unroll
            for (int j = 0; j < 8; j++) {
                sacc[j][2 * h2]     = __expf(sacc[j][2 * h2] - mn);
                sacc[j][2 * h2 + 1] = __expf(sacc[j][2 * h2 + 1] - mn);
                ts += sacc[j][2 * h2] + sacc[j][2 * h2 + 1];
            }
            ts += __shfl_xor_sync(0xffffffffu, ts, 1);
            ts += __shfl_xor_sync(0xffffffffu, ts, 2);
            lrow[h2] = lrow[h2] * sc + ts;
            #pragma unroll
            for (int j = 0; j < 8; j++) {
                oacc[j][2 * h2]     *= sc;
                oacc[j][2 * h2 + 1] *= sc;
            }
        }

        // ---- O += P V ----
        #pragma unroll
        for (int s = 0; s < 4; s++) {
            uint32_t pf[4];
            packh2(sacc[2 * s][0],     sacc[2 * s][1],     pf[0]);
            packh2(sacc[2 * s][2],     sacc[2 * s][3],     pf[1]);
            packh2(sacc[2 * s + 1][0], sacc[2 * s + 1][1], pf[2]);
            packh2(sacc[2 * s + 1][2], sacc[2 * s + 1][3], pf[3]);
            #pragma unroll
            for (int jp = 0; jp < 4; jp++) {
                uint32_t addr = vb + swz128((s * 16 + aRow) * 128 + jp * 32 + aC * 16);
                uint32_t vh4[4], vl4[4];
                ldsm4t(vh4, addr);
                ldsm4t(vl4, addr + 8192);
                uint32_t b0h[2] = {vh4[0], vh4[1]}, b1h[2] = {vh4[2], vh4[3]};
                uint32_t b0l[2] = {vl4[0], vl4[1]}, b1l[2] = {vl4[2], vl4[3]};
                mma16816h(oacc[2 * jp],     pf, b0h);
                mma16816h(oacc[2 * jp],     pf, b0l);
                mma16816h(oacc[2 * jp + 1], pf, b1h);
                mma16816h(oacc[2 * jp + 1], pf, b1l);
            }
        }
        __syncthreads();
    }

    #pragma unroll
    for (int h2 = 0; h2 < 2; h2++) {
        float inv = 1.0f / lrow[h2];
        int trow = qt * 64 + w * 16 + (lane >> 2) + h2 * 8;
        size_t rp = (tokBase + trow) * E_DIM + headOff;
        #pragma unroll
        for (int j = 0; j < 8; j++) {
            uint32_t p;
            packh2(oacc[j][2 * h2] * inv, oacc[j][2 * h2 + 1] * inv, p);
            int col = j * 8 + ((lane & 3) << 1);
            *(uint32_t*)(O + rp + col) = p;
        }
    }
}

// ---------------- launch ------------------------------------------------------
extern "C" void kernel_launch(void* const* d_in, const int* in_sizes, int n_in,
                              void* d_out, int out_size) {
    const float* x    = (const float*)d_in[0];
    const float* enc  = (const float*)d_in[1];
    const float* ln1g = (const float*)d_in[2];
    const float* ln1b = (const float*)d_in[3];
    const float* ln2g = (const float*)d_in[4];
    const float* ln2b = (const float*)d_in[5];
    const float* ln3g = (const float*)d_in[6];
    const float* ln3b = (const float*)d_in[7];
    const float* Wq1  = (const float*)d_in[8];
    const float* bq1  = (const float*)d_in[9];
    const float* Wk1  = (const float*)d_in[10];
    const float* bk1  = (const float*)d_in[11];
    const float* Wv1  = (const float*)d_in[12];
    const float* bv1  = (const float*)d_in[13];
    const float* Wo1  = (const float*)d_in[14];
    const float* bo1  = (const float*)d_in[15];
    const float* Wq2  = (const float*)d_in[16];
    const float* bq2  = (const float*)d_in[17];
    const float* Wk2  = (const float*)d_in[18];
    const float* bk2  = (const float*)d_in[19];
    const float* Wv2  = (const float*)d_in[20];
    const float* bv2  = (const float*)d_in[21];
    const float* Wo2  = (const float*)d_in[22];
    const float* bo2  = (const float*)d_in[23];
    const float* Wup  = (const float*)d_in[24];
    const float* bup  = (const float*)d_in[25];
    const float* Wdn  = (const float*)d_in[26];
    const float* bdn  = (const float*)d_in[27];
    float* out = (float*)d_out;

    half *W16h, *W16l, *h16, *e16, *q16, *kh16, *kl16, *vh16, *vl16, *a16;
    float *x1, *x2;
    cudaGetSymbolAddress((void**)&W16h, g_W16h);
    cudaGetSymbolAddress((void**)&W16l, g_W16l);
    cudaGetSymbolAddress((void**)&h16,  g_h16);
    cudaGetSymbolAddress((void**)&e16,  g_e16);
    cudaGetSymbolAddress((void**)&q16,  g_q16);
    cudaGetSymbolAddress((void**)&kh16, g_kh16);
    cudaGetSymbolAddress((void**)&kl16, g_kl16);
    cudaGetSymbolAddress((void**)&vh16, g_vh16);
    cudaGetSymbolAddress((void**)&vl16, g_vl16);
    cudaGetSymbolAddress((void**)&a16,  g_a16);
    cudaGetSymbolAddress((void**)&x1,   g_x1);
    cudaGetSymbolAddress((void**)&x2,   g_x2);

    cudaFuncSetAttribute(gemm16<0>, cudaFuncAttributeMaxDynamicSharedMemorySize, G16_SMEM);
    cudaFuncSetAttribute(gemm16<1>, cudaFuncAttributeMaxDynamicSharedMemorySize, G16_SMEM);
    cudaFuncSetAttribute(gemm16<2>, cudaFuncAttributeMaxDynamicSharedMemorySize, G16_SMEM);
    cudaFuncSetAttribute(gemm16<3>, cudaFuncAttributeMaxDynamicSharedMemorySize, G16_SMEM);
    cudaFuncSetAttribute(attn16<true>,  cudaFuncAttributeMaxDynamicSharedMemorySize, ATTN_SMEM);
    cudaFuncSetAttribute(attn16<false>, cudaFuncAttributeMaxDynamicSharedMemorySize, ATTN_SMEM);

    const int WS = E_DIM * E_DIM;
    dim3 gSq(8, 32);
    dim3 gUp(32, 32);
    dim3 gAttn(S_LEN / 64, H_NUM, B_NUM);
    dim3 trB(32, 8);

    // launch order: index 5 (ncu capture) = a QKV GEMM
    wqkv_split_all<<<dim3(2, 32, 96), 256>>>(Wq1, Wk1, Wv1, Wq2, Wk2, Wv2, W16h, W16l); // 0
    cvt16<<<4096, 256>>>(enc, e16);                                                     // 1
    ln_kernel<<<M_ROWS, 256>>>(x, ln1g, ln1b, h16);                                     // 2
    wt_split16<<<dim3(32, 32), trB>>>(Wo1, W16h + 6 * WS, W16l + 6 * WS, 1024, 1024);   // 3
    wt_split16<<<dim3(128, 32), trB>>>(Wup, W16h + 8 * WS, W16l + 8 * WS, 1024, 4096);  // 4
    gemm16<0><<<gSq, 128, G16_SMEM>>>(h16, W16h + 0 * WS, W16l + 0 * WS, bq1, nullptr,
                                      nullptr, q16, nullptr, M_ROWS, E_DIM, E_DIM);     // 5 (ncu)
    gemm16<3><<<gSq, 128, G16_SMEM>>>(h16, W16h + 1 * WS, W16l + 1 * WS, bk1, nullptr,
                                      nullptr, kh16, kl16, M_ROWS, E_DIM, E_DIM);       // 6
    gemm16<3><<<gSq, 128, G16_SMEM>>>(h16, W16h + 2 * WS, W16l + 2 * WS, bv1, nullptr,
                                      nullptr, vh16, vl16, M_ROWS, E_DIM, E_DIM);       // 7
    attn16<true><<<gAttn, 128, ATTN_SMEM>>>(q16, kh16, kl16, vh16, vl16, a16);          // 8
    wt_split16<<<dim3(32, 32), trB>>>(Wo2, W16h + 7 * WS, W16l + 7 * WS, 1024, 1024);   // 9
    gemm16<2><<<gSq, 128, G16_SMEM>>>(a16, W16h + 6 * WS, W16l + 6 * WS, bo1, x,
                                      x1, nullptr, nullptr, M_ROWS, E_DIM, E_DIM);      // 10

    ln_kernel<<<M_ROWS, 256>>>(x1, ln2g, ln2b, h16);                                    // 11
    gemm16<0><<<gSq, 128, G16_SMEM>>>(h16, W16h + 3 * WS, W16l + 3 * WS, bq2, nullptr,
                                      nullptr, q16, nullptr, M_ROWS, E_DIM, E_DIM);     // 12
    gemm16<3><<<gSq, 128, G16_SMEM>>>(e16, W16h + 4 * WS, W16l + 4 * WS, bk2, nullptr,
                                      nullptr, kh16, kl16, M_ROWS, E_DIM, E_DIM);       // 13
    gemm16<3><<<gSq, 128, G16_SMEM>>>(e16, W16h + 5 * WS, W16l + 5 * WS, bv2, nullptr,
                                      nullptr, vh16, vl16, M_ROWS, E_DIM, E_DIM);       // 14
    attn16<false><<<gAttn, 128, ATTN_SMEM>>>(q16, kh16, kl16, vh16, vl16, a16);         // 15
    wt_split16<<<dim3(32, 128), trB>>>(Wdn, W16h + 12 * WS, W16l + 12 * WS, 4096, 1024);// 16
    gemm16<2><<<gSq, 128, G16_SMEM>>>(a16, W16h + 7 * WS, W16l + 7 * WS, bo2, x1,
                                      x2, nullptr, nullptr, M_ROWS, E_DIM, E_DIM);      // 17

    ln_kernel<<<M_ROWS, 256>>>(x2, ln3g, ln3b, h16);                                    // 18
    gemm16<1><<<gUp, 128, G16_SMEM>>>(h16, W16h + 8 * WS, W16l + 8 * WS, bup, nullptr,
                                      nullptr, a16, nullptr, M_ROWS, F_DIM, E_DIM);     // 19
    gemm16<2><<<gSq, 128, G16_SMEM>>>(a16, W16h + 12 * WS, W16l + 12 * WS, bdn, x2,
                                      out, nullptr, nullptr, M_ROWS, E_DIM, F_DIM);     // 20
}

// round 8
// speedup vs baseline: 5.8447x; 1.4318x over previous
#include <cuda_runtime.h>
#include <cuda_fp16.h>
#include <math.h>
#include <cstdint>

#define E_DIM 1024
#define H_NUM 16
#define D_DIM 64
#define B_NUM 4
#define S_LEN 1024
#define F_DIM 4096
#define M_ROWS (B_NUM * S_LEN)  // 4096
#define MB1 (1024 * 1024)

// ---------------- scratch (static device globals) ---------------------------
// Weight slots (single fp16, [N][K] transposed): QKV1 0-2, QKV2 3-5, Wo1 6, Wo2 7,
// Wup 8-11, Wdn 12-15.
__device__ __align__(16) half g_W16[16 * MB1];
__device__ __align__(16) half g_h16[4 * MB1];          // LN out
__device__ __align__(16) half g_e16[4 * MB1];          // enc
__device__ __align__(16) half g_q16[4 * MB1];          // Q
__device__ __align__(16) half g_kh16[4 * MB1], g_kl16[4 * MB1];
__device__ __align__(16) half g_vh16[4 * MB1], g_vl16[4 * MB1];
__device__ __align__(16) half g_a16[16 * MB1];         // attn out / GELU out
__device__ __align__(16) float g_x1[4 * MB1], g_x2[4 * MB1];

// ---------------- PTX helpers -----------------------------------------------
__device__ __forceinline__ uint32_t smem_u32(const void* p) {
    uint32_t a;
    asm("{ .reg .u64 t; cvta.to.shared.u64 t, %1; cvt.u32.u64 %0, t; }" : "=r"(a) : "l"(p));
    return a;
}
__device__ __forceinline__ void cpasync16(uint32_t dst, const void* src) {
    asm volatile("cp.async.cg.shared.global [%0], [%1], 16;" :: "r"(dst), "l"(src));
}
__device__ __forceinline__ void cpcommit() { asm volatile("cp.async.commit_group;" ::: "memory"); }
template <int N>
__device__ __forceinline__ void cpwait() { asm volatile("cp.async.wait_group %0;" :: "n"(N) : "memory"); }

__device__ __forceinline__ void ldsm4(uint32_t (&r)[4], uint32_t addr) {
    asm volatile("ldmatrix.sync.aligned.m8n8.x4.shared.b16 {%0,%1,%2,%3}, [%4];"
                 : "=r"(r[0]), "=r"(r[1]), "=r"(r[2]), "=r"(r[3]) : "r"(addr));
}
__device__ __forceinline__ void ldsm4t(uint32_t (&r)[4], uint32_t addr) {
    asm volatile("ldmatrix.sync.aligned.m8n8.x4.trans.shared.b16 {%0,%1,%2,%3}, [%4];"
                 : "=r"(r[0]), "=r"(r[1]), "=r"(r[2]), "=r"(r[3]) : "r"(addr));
}
__device__ __forceinline__ void mma16816h(float (&d)[4], const uint32_t (&a)[4],
                                          const uint32_t (&b)[2]) {
    asm volatile(
        "mma.sync.aligned.m16n8k16.row.col.f32.f16.f16.f32 "
        "{%0,%1,%2,%3}, {%4,%5,%6,%7}, {%8,%9}, {%0,%1,%2,%3};"
        : "+f"(d[0]), "+f"(d[1]), "+f"(d[2]), "+f"(d[3])
        : "r"(a[0]), "r"(a[1]), "r"(a[2]), "r"(a[3]), "r"(b[0]), "r"(b[1]));
}
__device__ __forceinline__ uint32_t swz128(uint32_t o) { return o ^ ((o >> 3) & 0x70); }

__device__ __forceinline__ void h_split(float v, half& hi, half& lo) {
    hi = __float2half_rn(v);
    lo = __float2half_rn(v - __half2float(hi));
}
__device__ __forceinline__ void packh2(float a, float b, uint32_t& r) {
    half2 p; p.x = __float2half_rn(a); p.y = __float2half_rn(b);
    r = *(uint32_t*)&p;
}
__device__ __forceinline__ void packsplit16(float a, float b, uint32_t& hi, uint32_t& lo) {
    half ah, al, bh, bl;
    h_split(a, ah, al); h_split(b, bh, bl);
    half2 hp, lp;
    hp.x = ah; hp.y = bh; lp.x = al; lp.y = bl;
    hi = *(uint32_t*)&hp; lo = *(uint32_t*)&lp;
}

// ---------------- weight prep -------------------------------------------------
// All 6 QKV weights: [H,E,D] -> Bt[n=h*64+d][k=e], single fp16 (slots 0-5).
__global__ void __launch_bounds__(256) wqkv_cvt_all(
    const float* __restrict__ w0, const float* __restrict__ w1,
    const float* __restrict__ w2, const float* __restrict__ w3,
    const float* __restrict__ w4, const float* __restrict__ w5,
    half* __restrict__ o16) {
    __shared__ float tile[32][33];
    int dt = blockIdx.x;
    int et = blockIdx.y;
    int z  = blockIdx.z;            // s*16 + h
    int s = z >> 4, h = z & 15;
    const float* src;
    switch (s) {
        case 0: src = w0; break; case 1: src = w1; break; case 2: src = w2; break;
        case 3: src = w3; break; case 4: src = w4; break; default: src = w5; break;
    }
    int tx = threadIdx.x & 31, ty = threadIdx.x >> 5;
    int e0 = et * 32, d0 = dt * 32;
    #pragma unroll
    for (int i = 0; i < 4; i++)
        tile[ty + 8 * i][tx] = src[h * (E_DIM * D_DIM) + (e0 + ty + 8 * i) * D_DIM + d0 + tx];
    __syncthreads();
    #pragma unroll
    for (int i = 0; i < 4; i++) {
        size_t oidx = (size_t)s * MB1 + (size_t)(h * 64 + d0 + ty + 8 * i) * E_DIM + e0 + tx;
        o16[oidx] = __float2half_rn(tile[tx][ty + 8 * i]);
    }
}
// [K,N] row-major -> Bt[n][k], single fp16
__global__ void wt_cvt16(const float* __restrict__ src,
                         half* __restrict__ o16, int K, int N) {
    __shared__ float tile[32][33];
    int n0 = blockIdx.x * 32, k0 = blockIdx.y * 32;
    int tx = threadIdx.x, ty = threadIdx.y;
    #pragma unroll
    for (int i = 0; i < 4; i++)
        tile[ty + 8 * i][tx] = src[(size_t)(k0 + ty + 8 * i) * N + n0 + tx];
    __syncthreads();
    #pragma unroll
    for (int i = 0; i < 4; i++)
        o16[(size_t)(n0 + ty + 8 * i) * K + k0 + tx] = __float2half_rn(tile[tx][ty + 8 * i]);
}
// f32 -> single fp16
__global__ void cvt16(const float* __restrict__ src, half* __restrict__ dst) {
    int i = blockIdx.x * 256 + threadIdx.x;
    float4 v = ((const float4*)src)[i];
    uint32_t p0, p1;
    packh2(v.x, v.y, p0);
    packh2(v.z, v.w, p1);
    *(uint32_t*)(dst + 4 * (size_t)i) = p0;
    *(uint32_t*)(dst + 4 * (size_t)i + 2) = p1;
}

// ---------------- LayerNorm: f32 -> single fp16 -------------------------------
__global__ void __launch_bounds__(256) ln_kernel(const float* __restrict__ x,
                                                 const float* __restrict__ g,
                                                 const float* __restrict__ b,
                                                 half* __restrict__ o16) {
    int row = blockIdx.x;
    int t = threadIdx.x;
    float4 v = ((const float4*)(x + (size_t)row * E_DIM))[t];
    float s = v.x + v.y + v.z + v.w;
    float ss = v.x * v.x + v.y * v.y + v.z * v.z + v.w * v.w;
    #pragma unroll
    for (int o = 16; o > 0; o >>= 1) {
        s  += __shfl_xor_sync(0xffffffffu, s, o);
        ss += __shfl_xor_sync(0xffffffffu, ss, o);
    }
    __shared__ float red[2][8];
    int w = t >> 5, lane = t & 31;
    if (lane == 0) { red[0][w] = s; red[1][w] = ss; }
    __syncthreads();
    s = 0.0f; ss = 0.0f;
    #pragma unroll
    for (int i = 0; i < 8; i++) { s += red[0][i]; ss += red[1][i]; }
    float mu  = s * (1.0f / E_DIM);
    float var = ss * (1.0f / E_DIM) - mu * mu;
    float inv = rsqrtf(var + 1e-5f);
    float4 gv = ((const float4*)g)[t];
    float4 bv = ((const float4*)b)[t];
    float o0 = (v.x - mu) * inv * gv.x + bv.x;
    float o1 = (v.y - mu) * inv * gv.y + bv.y;
    float o2 = (v.z - mu) * inv * gv.z + bv.z;
    float o3 = (v.w - mu) * inv * gv.w + bv.w;
    size_t base = (size_t)row * E_DIM + t * 4;
    uint32_t p0, p1;
    packh2(o0, o1, p0);
    packh2(o2, o3, p1);
    *(uint32_t*)(o16 + base) = p0;
    *(uint32_t*)(o16 + base + 2) = p1;
}

// ---------------- fp16 GEMM (single x single) ----------------------------------
// C = epi(A(fp16) @ B(fp16)^T + bias)
// EPI: 0 bias -> fp16 single, 1 bias+GELU -> fp16, 2 bias+res -> f32,
//      3 bias -> fp16 hi/lo
// CTA 128x128, BK=64, 4 warps (2x2), warp tile 64x64, double-buffered.
#define G16_STAGE 32768
#define G16_SMEM (2 * G16_STAGE + 256)
template <int EPI>
__global__ void __launch_bounds__(128, 2) gemm16(
    const half* __restrict__ A, const half* __restrict__ B,
    const float* __restrict__ bias, const float* __restrict__ res,
    float* __restrict__ outF, half* __restrict__ outH, half* __restrict__ outL,
    int M, int N, int K) {
    extern __shared__ char dyn[];
    uint32_t sb = (smem_u32(dyn) + 127) & ~127u;
    int tid = threadIdx.x, lane = tid & 31, wid = tid >> 5;
    int rBase = blockIdx.y * 128, cBase = blockIdx.x * 128;
    int m0 = (wid >> 1) * 64, n0 = (wid & 1) * 64;

    float acc[4][8][4];
    #pragma unroll
    for (int i = 0; i < 4; i++)
        #pragma unroll
        for (int j = 0; j < 8; j++)
            #pragma unroll
            for (int u = 0; u < 4; u++) acc[i][j][u] = 0.0f;

    const int nc = K >> 6;
    auto loadStage = [&](int s, int c) {
        uint32_t base = sb + s * G16_STAGE;
        int k0 = c << 6;
        #pragma unroll
        for (int i = 0; i < 8; i++) {
            int idx = i * 128 + tid;
            int row = idx >> 3, c16 = idx & 7;
            uint32_t off = swz128(row * 128 + c16 * 16);
            cpasync16(base + off,         A + (size_t)(rBase + row) * K + k0 + c16 * 8);
            cpasync16(base + 16384 + off, B + (size_t)(cBase + row) * K + k0 + c16 * 8);
        }
    };

    int aRow = (lane & 7) + ((lane >> 3) & 1) * 8;
    int aC   = lane >> 4;
    int bRow16 = (lane & 7) + ((lane >> 4) & 1) * 8;
    int bH     = (lane >> 3) & 1;

    loadStage(0, 0); cpcommit();

    for (int c = 0; c < nc; c++) {
        if (c + 1 < nc) { loadStage((c + 1) & 1, c + 1); cpcommit(); cpwait<1>(); }
        else            { cpwait<0>(); }
        __syncthreads();
        uint32_t base = sb + (c & 1) * G16_STAGE;
        #pragma unroll
        for (int kc = 0; kc < 4; kc++) {
            uint32_t bh[8][2];
            #pragma unroll
            for (int jp = 0; jp < 4; jp++) {
                int row = n0 + jp * 16 + bRow16;
                uint32_t t4[4];
                ldsm4(t4, base + 16384 + swz128(row * 128 + kc * 32 + bH * 16));
                bh[2 * jp][0] = t4[0]; bh[2 * jp][1] = t4[1];
                bh[2 * jp + 1][0] = t4[2]; bh[2 * jp + 1][1] = t4[3];
            }
            #pragma unroll
            for (int i = 0; i < 4; i++) {
                uint32_t a4[4];
                int row = m0 + i * 16 + aRow;
                ldsm4(a4, base + swz128(row * 128 + kc * 32 + aC * 16));
                #pragma unroll
                for (int j = 0; j < 8; j++)
                    mma16816h(acc[i][j], a4, bh[j]);
            }
        }
        __syncthreads();
    }

    int lr = lane >> 2, lc = (lane & 3) << 1;
    #pragma unroll
    for (int i = 0; i < 4; i++) {
        #pragma unroll
        for (int half_ = 0; half_ < 2; half_++) {
            size_t row = (size_t)(rBase + m0 + i * 16 + lr + half_ * 8);
            #pragma unroll
            for (int j = 0; j < 8; j++) {
                int col = cBase + n0 + j * 8 + lc;
                float v0 = acc[i][j][half_ * 2 + 0] + bias[col];
                float v1 = acc[i][j][half_ * 2 + 1] + bias[col + 1];
                if (EPI == 0) {
                    uint32_t p;
                    packh2(v0, v1, p);
                    *(uint32_t*)(outH + row * N + col) = p;
                } else if (EPI == 3) {
                    uint32_t hp, lp;
                    packsplit16(v0, v1, hp, lp);
                    *(uint32_t*)(outH + row * N + col) = hp;
                    *(uint32_t*)(outL + row * N + col) = lp;
                } else if (EPI == 1) {
                    v0 = 0.5f * v0 * (1.0f + erff(v0 * 0.70710678118654752f));
                    v1 = 0.5f * v1 * (1.0f + erff(v1 * 0.70710678118654752f));
                    uint32_t p;
                    packh2(v0, v1, p);
                    *(uint32_t*)(outH + row * N + col) = p;
                } else {
                    float2 rv = *(const float2*)(res + row * N + col);
                    float2 o; o.x = v0 + rv.x; o.y = v1 + rv.y;
                    *(float2*)(outF + row * N + col) = o;
                }
            }
        }
    }
}

// ---------------- fp16x2 flash attention (D=64) -> fp16 out -------------------
// Q single fp16; K, V fp16 hi/lo. grid (S/64, H, B), 128 threads.
#define ATTN_SMEM (8192 + 2 * 32768 + 1024)
template <bool CAUSAL>
__global__ void __launch_bounds__(128, 2) attn16(
    const half* __restrict__ Q,
    const half* __restrict__ Kh, const half* __restrict__ Kl,
    const half* __restrict__ Vh, const half* __restrict__ Vl,
    half* __restrict__ O) {
    extern __shared__ char dyn[];
    uint32_t sb = (smem_u32(dyn) + 1023) & ~1023u;
    int tid = threadIdx.x, lane = tid & 31, w = tid >> 5;
    int b = blockIdx.z, hh = blockIdx.y, qt = blockIdx.x;
    size_t headOff = (size_t)hh * D_DIM;
    size_t tokBase = (size_t)b * S_LEN;

    int aRow = (lane & 7) + ((lane >> 3) & 1) * 8;
    int aC = lane >> 4;

    {
        #pragma unroll
        for (int i = 0; i < 4; i++) {
            int idx = i * 128 + tid;
            int r = idx >> 3, c = idx & 7;
            uint32_t off = swz128(r * 128 + c * 16);
            cpasync16(sb + off, Q + (tokBase + qt * 64 + r) * E_DIM + headOff + c * 8);
        }
    }
    auto loadKV = [&](int s, int kt) {
        uint32_t base = sb + 8192 + s * 32768;
        #pragma unroll
        for (int i = 0; i < 4; i++) {
            int idx = i * 128 + tid;
            int r = idx >> 3, c = idx & 7;
            uint32_t off = swz128(r * 128 + c * 16);
            size_t src = (tokBase + kt * 64 + r) * E_DIM + headOff + c * 8;
            cpasync16(base + off,         Kh + src);
            cpasync16(base + 8192 + off,  Kl + src);
            cpasync16(base + 16384 + off, Vh + src);
            cpasync16(base + 24576 + off, Vl + src);
        }
    };
    loadKV(0, 0);
    cpcommit();

    uint32_t qf[4][4];
    float oacc[8][4];
    float mrow[2] = {-1e30f, -1e30f}, lrow[2] = {0.0f, 0.0f};
    #pragma unroll
    for (int j = 0; j < 8; j++)
        #pragma unroll
        for (int u = 0; u < 4; u++) oacc[j][u] = 0.0f;

    const int ntiles = CAUSAL ? (qt + 1) : (S_LEN / 64);
    for (int kt = 0; kt < ntiles; kt++) {
        if (kt + 1 < ntiles) { loadKV((kt + 1) & 1, kt + 1); cpcommit(); cpwait<1>(); }
        else                 { cpwait<0>(); }
        __syncthreads();
        if (kt == 0) {
            #pragma unroll
            for (int s = 0; s < 4; s++)
                ldsm4(qf[s], sb + swz128((w * 16 + aRow) * 128 + s * 32 + aC * 16));
        }
        uint32_t kb = sb + 8192 + (kt & 1) * 32768;
        uint32_t vb = kb + 16384;

        float sacc[8][4];
        #pragma unroll
        for (int j = 0; j < 8; j++)
            #pragma unroll
            for (int u = 0; u < 4; u++) sacc[j][u] = 0.0f;
        #pragma unroll
        for (int s = 0; s < 4; s++) {
            #pragma unroll
            for (int jp = 0; jp < 4; jp++) {
                uint32_t addr = kb + swz128((jp * 16 + aRow) * 128 + s * 32 + aC * 16);
                uint32_t kh4[4], kl4[4];
                ldsm4(kh4, addr);
                ldsm4(kl4, addr + 8192);
                uint32_t b0h[2] = {kh4[0], kh4[2]}, b1h[2] = {kh4[1], kh4[3]};
                uint32_t b0l[2] = {kl4[0], kl4[2]}, b1l[2] = {kl4[1], kl4[3]};
                mma16816h(sacc[2 * jp],     qf[s], b0h);
                mma16816h(sacc[2 * jp],     qf[s], b0l);
                mma16816h(sacc[2 * jp + 1], qf[s], b1h);
                mma16816h(sacc[2 * jp + 1], qf[s], b1l);
            }
        }

        if (CAUSAL && kt == qt) {
            int ql0 = w * 16 + (lane >> 2);
            #pragma unroll
            for (int j = 0; j < 8; j++)
                #pragma unroll
                for (int u = 0; u < 4; u++) {
                    int kcol = j * 8 + ((lane & 3) << 1) + (u & 1);
                    int qrow = ql0 + (u >> 1) * 8;
                    if (kcol > qrow) sacc[j][u] = -1e30f;
                }
        }

        #pragma unroll
        for (int h2 = 0; h2 < 2; h2++) {
            float mt = -1e30f;
            #pragma unroll
            for (int j = 0; j < 8; j++)
                mt = fmaxf(mt, fmaxf(sacc[j][2 * h2], sacc[j][2 * h2 + 1]));
            mt = fmaxf(mt, __shfl_xor_sync(0xffffffffu, mt, 1));
            mt = fmaxf(mt, __shfl_xor_sync(0xffffffffu, mt, 2));
            float mn = fmaxf(mrow[h2], mt);
            float sc = __expf(mrow[h2] - mn);
            mrow[h2] = mn;
            float ts = 0.0f;
            #pragma unroll
            for (int j = 0; j < 8; j++) {
                sacc[j][2 * h2]     = __expf(sacc[j][2 * h2] - mn);
                sacc[j][2 * h2 + 1] = __expf(sacc[j][2 * h2 + 1] - mn);
                ts += sacc[j][2 * h2] + sacc[j][2 * h2 + 1];
            }
            ts += __shfl_xor_sync(0xffffffffu, ts, 1);
            ts += __shfl_xor_sync(0xffffffffu, ts, 2);
            lrow[h2] = lrow[h2] * sc + ts;
            #pragma unroll
            for (int j = 0; j < 8; j++) {
                oacc[j][2 * h2]     *= sc;
                oacc[j][2 * h2 + 1] *= sc;
            }
        }

        #pragma unroll
        for (int s = 0; s < 4; s++) {
            uint32_t pf[4];
            packh2(sacc[2 * s][0],     sacc[2 * s][1],     pf[0]);
            packh2(sacc[2 * s][2],     sacc[2 * s][3],     pf[1]);
            packh2(sacc[2 * s + 1][0], sacc[2 * s + 1][1], pf[2]);
            packh2(sacc[2 * s + 1][2], sacc[2 * s + 1][3], pf[3]);
            #pragma unroll
            for (int jp = 0; jp < 4; jp++) {
                uint32_t addr = vb + swz128((s * 16 + aRow) * 128 + jp * 32 + aC * 16);
                uint32_t vh4[4], vl4[4];
                ldsm4t(vh4, addr);
                ldsm4t(vl4, addr + 8192);
                uint32_t b0h[2] = {vh4[0], vh4[1]}, b1h[2] = {vh4[2], vh4[3]};
                uint32_t b0l[2] = {vl4[0], vl4[1]}, b1l[2] = {vl4[2], vl4[3]};
                mma16816h(oacc[2 * jp],     pf, b0h);
                mma16816h(oacc[2 * jp],     pf, b0l);
                mma16816h(oacc[2 * jp + 1], pf, b1h);
                mma16816h(oacc[2 * jp + 1], pf, b1l);
            }
        }
        __syncthreads();
    }

    #pragma unroll
    for (int h2 = 0; h2 < 2; h2++) {
        float inv = 1.0f / lrow[h2];
        int trow = qt * 64 + w * 16 + (lane >> 2) + h2 * 8;
        size_t rp = (tokBase + trow) * E_DIM + headOff;
        #pragma unroll
        for (int j = 0; j < 8; j++) {
            uint32_t p;
            packh2(oacc[j][2 * h2] * inv, oacc[j][2 * h2 + 1] * inv, p);
            int col = j * 8 + ((lane & 3) << 1);
            *(uint32_t*)(O + rp + col) = p;
        }
    }
}

// ---------------- launch ------------------------------------------------------
extern "C" void kernel_launch(void* const* d_in, const int* in_sizes, int n_in,
                              void* d_out, int out_size) {
    const float* x    = (const float*)d_in[0];
    const float* enc  = (const float*)d_in[1];
    const float* ln1g = (const float*)d_in[2];
    const float* ln1b = (const float*)d_in[3];
    const float* ln2g = (const float*)d_in[4];
    const float* ln2b = (const float*)d_in[5];
    const float* ln3g = (const float*)d_in[6];
    const float* ln3b = (const float*)d_in[7];
    const float* Wq1  = (const float*)d_in[8];
    const float* bq1  = (const float*)d_in[9];
    const float* Wk1  = (const float*)d_in[10];
    const float* bk1  = (const float*)d_in[11];
    const float* Wv1  = (const float*)d_in[12];
    const float* bv1  = (const float*)d_in[13];
    const float* Wo1  = (const float*)d_in[14];
    const float* bo1  = (const float*)d_in[15];
    const float* Wq2  = (const float*)d_in[16];
    const float* bq2  = (const float*)d_in[17];
    const float* Wk2  = (const float*)d_in[18];
    const float* bk2  = (const float*)d_in[19];
    const float* Wv2  = (const float*)d_in[20];
    const float* bv2  = (const float*)d_in[21];
    const float* Wo2  = (const float*)d_in[22];
    const float* bo2  = (const float*)d_in[23];
    const float* Wup  = (const float*)d_in[24];
    const float* bup  = (const float*)d_in[25];
    const float* Wdn  = (const float*)d_in[26];
    const float* bdn  = (const float*)d_in[27];
    float* out = (float*)d_out;

    half *W16, *h16, *e16, *q16, *kh16, *kl16, *vh16, *vl16, *a16;
    float *x1, *x2;
    cudaGetSymbolAddress((void**)&W16,  g_W16);
    cudaGetSymbolAddress((void**)&h16,  g_h16);
    cudaGetSymbolAddress((void**)&e16,  g_e16);
    cudaGetSymbolAddress((void**)&q16,  g_q16);
    cudaGetSymbolAddress((void**)&kh16, g_kh16);
    cudaGetSymbolAddress((void**)&kl16, g_kl16);
    cudaGetSymbolAddress((void**)&vh16, g_vh16);
    cudaGetSymbolAddress((void**)&vl16, g_vl16);
    cudaGetSymbolAddress((void**)&a16,  g_a16);
    cudaGetSymbolAddress((void**)&x1,   g_x1);
    cudaGetSymbolAddress((void**)&x2,   g_x2);

    cudaFuncSetAttribute(gemm16<0>, cudaFuncAttributeMaxDynamicSharedMemorySize, G16_SMEM);
    cudaFuncSetAttribute(gemm16<1>, cudaFuncAttributeMaxDynamicSharedMemorySize, G16_SMEM);
    cudaFuncSetAttribute(gemm16<2>, cudaFuncAttributeMaxDynamicSharedMemorySize, G16_SMEM);
    cudaFuncSetAttribute(gemm16<3>, cudaFuncAttributeMaxDynamicSharedMemorySize, G16_SMEM);
    cudaFuncSetAttribute(attn16<true>,  cudaFuncAttributeMaxDynamicSharedMemorySize, ATTN_SMEM);
    cudaFuncSetAttribute(attn16<false>, cudaFuncAttributeMaxDynamicSharedMemorySize, ATTN_SMEM);

    const int WS = E_DIM * E_DIM;
    dim3 gSq(8, 32);
    dim3 gUp(32, 32);
    dim3 gAttn(S_LEN / 64, H_NUM, B_NUM);
    dim3 trB(32, 8);

    // launch order: index 5 (ncu capture) = a QKV GEMM
    wqkv_cvt_all<<<dim3(2, 32, 96), 256>>>(Wq1, Wk1, Wv1, Wq2, Wk2, Wv2, W16);          // 0
    cvt16<<<4096, 256>>>(enc, e16);                                                     // 1
    ln_kernel<<<M_ROWS, 256>>>(x, ln1g, ln1b, h16);                                     // 2
    wt_cvt16<<<dim3(32, 32), trB>>>(Wo1, W16 + 6 * WS, 1024, 1024);                     // 3
    wt_cvt16<<<dim3(128, 32), trB>>>(Wup, W16 + 8 * WS, 1024, 4096);                    // 4
    gemm16<0><<<gSq, 128, G16_SMEM>>>(h16, W16 + 0 * WS, bq1, nullptr,
                                      nullptr, q16, nullptr, M_ROWS, E_DIM, E_DIM);     // 5 (ncu)
    gemm16<3><<<gSq, 128, G16_SMEM>>>(h16, W16 + 1 * WS, bk1, nullptr,
                                      nullptr, kh16, kl16, M_ROWS, E_DIM, E_DIM);       // 6
    gemm16<3><<<gSq, 128, G16_SMEM>>>(h16, W16 + 2 * WS, bv1, nullptr,
                                      nullptr, vh16, vl16, M_ROWS, E_DIM, E_DIM);       // 7
    attn16<true><<<gAttn, 128, ATTN_SMEM>>>(q16, kh16, kl16, vh16, vl16, a16);          // 8
    wt_cvt16<<<dim3(32, 32), trB>>>(Wo2, W16 + 7 * WS, 1024, 1024);                     // 9
    gemm16<2><<<gSq, 128, G16_SMEM>>>(a16, W16 + 6 * WS, bo1, x,
                                      x1, nullptr, nullptr, M_ROWS, E_DIM, E_DIM);      // 10

    ln_kernel<<<M_ROWS, 256>>>(x1, ln2g, ln2b, h16);                                    // 11
    gemm16<0><<<gSq, 128, G16_SMEM>>>(h16, W16 + 3 * WS, bq2, nullptr,
                                      nullptr, q16, nullptr, M_ROWS, E_DIM, E_DIM);     // 12
    gemm16<3><<<gSq, 128, G16_SMEM>>>(e16, W16 + 4 * WS, bk2, nullptr,
                                      nullptr, kh16, kl16, M_ROWS, E_DIM, E_DIM);       // 13
    gemm16<3><<<gSq, 128, G16_SMEM>>>(e16, W16 + 5 * WS, bv2, nullptr,
                                      nullptr, vh16, vl16, M_ROWS, E_DIM, E_DIM);       // 14
    attn16<false><<<gAttn, 128, ATTN_SMEM>>>(q16, kh16, kl16, vh16, vl16, a16);         // 15
    wt_cvt16<<<dim3(32, 128), trB>>>(Wdn, W16 + 12 * WS, 4096, 1024);                   // 16
    gemm16<2><<<gSq, 128, G16_SMEM>>>(a16, W16 + 7 * WS, bo2, x1,
                                      x2, nullptr, nullptr, M_ROWS, E_DIM, E_DIM);      // 17

    ln_kernel<<<M_ROWS, 256>>>(x2, ln3g, ln3b, h16);                                    // 18
    gemm16<1><<<gUp, 128, G16_SMEM>>>(h16, W16 + 8 * WS, bup, nullptr,
                                      nullptr, a16, nullptr, M_ROWS, F_DIM, E_DIM);     // 19
    gemm16<2><<<gSq, 128, G16_SMEM>>>(a16, W16 + 12 * WS, bdn, x2,
                                      out, nullptr, nullptr, M_ROWS, E_DIM, F_DIM);     // 20
}

// round 9
// speedup vs baseline: 6.2465x; 1.0687x over previous
#include <cuda_runtime.h>
#include <cuda_fp16.h>
#include <math.h>
#include <cstdint>

#define E_DIM 1024
#define H_NUM 16
#define D_DIM 64
#define B_NUM 4
#define S_LEN 1024
#define F_DIM 4096
#define M_ROWS (B_NUM * S_LEN)  // 4096
#define MB1 (1024 * 1024)

// ---------------- scratch (static device globals) ---------------------------
// Weight slots (single fp16, [N][K] transposed): QKV1 0-2, QKV2 3-5, Wo1 6, Wo2 7,
// Wup 8-11, Wdn 12-15.
__device__ __align__(16) half g_W16[16 * MB1];
__device__ __align__(16) half g_h16[4 * MB1];          // LN out
__device__ __align__(16) half g_e16[4 * MB1];          // enc
__device__ __align__(16) half g_q16[4 * MB1];          // Q (single)
__device__ __align__(16) half g_kh16[4 * MB1], g_kl16[4 * MB1];  // K hi/lo
__device__ __align__(16) half g_v16[4 * MB1];          // V (single)
__device__ __align__(16) half g_a16[16 * MB1];         // attn out / GELU out
__device__ __align__(16) float g_x1[4 * MB1], g_x2[4 * MB1];

// ---------------- PTX helpers -----------------------------------------------
__device__ __forceinline__ uint32_t smem_u32(const void* p) {
    uint32_t a;
    asm("{ .reg .u64 t; cvta.to.shared.u64 t, %1; cvt.u32.u64 %0, t; }" : "=r"(a) : "l"(p));
    return a;
}
__device__ __forceinline__ void cpasync16(uint32_t dst, const void* src) {
    asm volatile("cp.async.cg.shared.global [%0], [%1], 16;" :: "r"(dst), "l"(src));
}
__device__ __forceinline__ void cpcommit() { asm volatile("cp.async.commit_group;" ::: "memory"); }
template <int N>
__device__ __forceinline__ void cpwait() { asm volatile("cp.async.wait_group %0;" :: "n"(N) : "memory"); }

__device__ __forceinline__ void ldsm4(uint32_t (&r)[4], uint32_t addr) {
    asm volatile("ldmatrix.sync.aligned.m8n8.x4.shared.b16 {%0,%1,%2,%3}, [%4];"
                 : "=r"(r[0]), "=r"(r[1]), "=r"(r[2]), "=r"(r[3]) : "r"(addr));
}
__device__ __forceinline__ void ldsm4t(uint32_t (&r)[4], uint32_t addr) {
    asm volatile("ldmatrix.sync.aligned.m8n8.x4.trans.shared.b16 {%0,%1,%2,%3}, [%4];"
                 : "=r"(r[0]), "=r"(r[1]), "=r"(r[2]), "=r"(r[3]) : "r"(addr));
}
__device__ __forceinline__ void mma16816h(float (&d)[4], const uint32_t (&a)[4],
                                          const uint32_t (&b)[2]) {
    asm volatile(
        "mma.sync.aligned.m16n8k16.row.col.f32.f16.f16.f32 "
        "{%0,%1,%2,%3}, {%4,%5,%6,%7}, {%8,%9}, {%0,%1,%2,%3};"
        : "+f"(d[0]), "+f"(d[1]), "+f"(d[2]), "+f"(d[3])
        : "r"(a[0]), "r"(a[1]), "r"(a[2]), "r"(a[3]), "r"(b[0]), "r"(b[1]));
}
__device__ __forceinline__ uint32_t swz128(uint32_t o) { return o ^ ((o >> 3) & 0x70); }

__device__ __forceinline__ void h_split(float v, half& hi, half& lo) {
    hi = __float2half_rn(v);
    lo = __float2half_rn(v - __half2float(hi));
}
__device__ __forceinline__ void packh2(float a, float b, uint32_t& r) {
    half2 p; p.x = __float2half_rn(a); p.y = __float2half_rn(b);
    r = *(uint32_t*)&p;
}
__device__ __forceinline__ void packsplit16(float a, float b, uint32_t& hi, uint32_t& lo) {
    half ah, al, bh, bl;
    h_split(a, ah, al); h_split(b, bh, bl);
    half2 hp, lp;
    hp.x = ah; hp.y = bh; lp.x = al; lp.y = bl;
    hi = *(uint32_t*)&hp; lo = *(uint32_t*)&lp;
}

// ---------------- weight prep -------------------------------------------------
// All 6 QKV weights: [H,E,D] -> Bt[n=h*64+d][k=e], single fp16 (slots 0-5).
__global__ void __launch_bounds__(256) wqkv_cvt_all(
    const float* __restrict__ w0, const float* __restrict__ w1,
    const float* __restrict__ w2, const float* __restrict__ w3,
    const float* __restrict__ w4, const float* __restrict__ w5,
    half* __restrict__ o16) {
    __shared__ float tile[32][33];
    int dt = blockIdx.x;
    int et = blockIdx.y;
    int z  = blockIdx.z;            // s*16 + h
    int s = z >> 4, h = z & 15;
    const float* src;
    switch (s) {
        case 0: src = w0; break; case 1: src = w1; break; case 2: src = w2; break;
        case 3: src = w3; break; case 4: src = w4; break; default: src = w5; break;
    }
    int tx = threadIdx.x & 31, ty = threadIdx.x >> 5;
    int e0 = et * 32, d0 = dt * 32;
    #pragma unroll
    for (int i = 0; i < 4; i++)
        tile[ty + 8 * i][tx] = src[h * (E_DIM * D_DIM) + (e0 + ty + 8 * i) * D_DIM + d0 + tx];
    __syncthreads();
    #pragma unroll
    for (int i = 0; i < 4; i++) {
        size_t oidx = (size_t)s * MB1 + (size_t)(h * 64 + d0 + ty + 8 * i) * E_DIM + e0 + tx;
        o16[oidx] = __float2half_rn(tile[tx][ty + 8 * i]);
    }
}
// [K,N] row-major -> Bt[n][k], single fp16
__global__ void wt_cvt16(const float* __restrict__ src,
                         half* __restrict__ o16, int K, int N) {
    __shared__ float tile[32][33];
    int n0 = blockIdx.x * 32, k0 = blockIdx.y * 32;
    int tx = threadIdx.x, ty = threadIdx.y;
    #pragma unroll
    for (int i = 0; i < 4; i++)
        tile[ty + 8 * i][tx] = src[(size_t)(k0 + ty + 8 * i) * N + n0 + tx];
    __syncthreads();
    #pragma unroll
    for (int i = 0; i < 4; i++)
        o16[(size_t)(n0 + ty + 8 * i) * K + k0 + tx] = __float2half_rn(tile[tx][ty + 8 * i]);
}
// f32 -> single fp16
__global__ void cvt16(const float* __restrict__ src, half* __restrict__ dst) {
    int i = blockIdx.x * 256 + threadIdx.x;
    float4 v = ((const float4*)src)[i];
    uint32_t p0, p1;
    packh2(v.x, v.y, p0);
    packh2(v.z, v.w, p1);
    *(uint32_t*)(dst + 4 * (size_t)i) = p0;
    *(uint32_t*)(dst + 4 * (size_t)i + 2) = p1;
}

// ---------------- LayerNorm: f32 -> single fp16 -------------------------------
__global__ void __launch_bounds__(256) ln_kernel(const float* __restrict__ x,
                                                 const float* __restrict__ g,
                                                 const float* __restrict__ b,
                                                 half* __restrict__ o16) {
    int row = blockIdx.x;
    int t = threadIdx.x;
    float4 v = ((const float4*)(x + (size_t)row * E_DIM))[t];
    float s = v.x + v.y + v.z + v.w;
    float ss = v.x * v.x + v.y * v.y + v.z * v.z + v.w * v.w;
    #pragma unroll
    for (int o = 16; o > 0; o >>= 1) {
        s  += __shfl_xor_sync(0xffffffffu, s, o);
        ss += __shfl_xor_sync(0xffffffffu, ss, o);
    }
    __shared__ float red[2][8];
    int w = t >> 5, lane = t & 31;
    if (lane == 0) { red[0][w] = s; red[1][w] = ss; }
    __syncthreads();
    s = 0.0f; ss = 0.0f;
    #pragma unroll
    for (int i = 0; i < 8; i++) { s += red[0][i]; ss += red[1][i]; }
    float mu  = s * (1.0f / E_DIM);
    float var = ss * (1.0f / E_DIM) - mu * mu;
    float inv = rsqrtf(var + 1e-5f);
    float4 gv = ((const float4*)g)[t];
    float4 bv = ((const float4*)b)[t];
    float o0 = (v.x - mu) * inv * gv.x + bv.x;
    float o1 = (v.y - mu) * inv * gv.y + bv.y;
    float o2 = (v.z - mu) * inv * gv.z + bv.z;
    float o3 = (v.w - mu) * inv * gv.w + bv.w;
    size_t base = (size_t)row * E_DIM + t * 4;
    uint32_t p0, p1;
    packh2(o0, o1, p0);
    packh2(o2, o3, p1);
    *(uint32_t*)(o16 + base) = p0;
    *(uint32_t*)(o16 + base + 2) = p1;
}

// ---------------- GEMM mainloop macro body -------------------------------------
// Shared by gemm16 and gemm_qkv. CTA 128x128, BK=64, 4 warps (2x2), warp 64x64.
#define G16_STAGE 32768
#define G16_SMEM (2 * G16_STAGE + 256)

// ---------------- fp16 GEMM (single x single) ----------------------------------
// EPI: 0 bias -> fp16 single, 1 bias+GELU -> fp16, 2 bias+res -> f32
template <int EPI>
__global__ void __launch_bounds__(128, 2) gemm16(
    const half* __restrict__ A, const half* __restrict__ B,
    const float* __restrict__ bias, const float* __restrict__ res,
    float* __restrict__ outF, half* __restrict__ outH,
    int M, int N, int K) {
    extern __shared__ char dyn[];
    uint32_t sb = (smem_u32(dyn) + 127) & ~127u;
    int tid = threadIdx.x, lane = tid & 31, wid = tid >> 5;
    int rBase = blockIdx.y * 128, cBase = blockIdx.x * 128;
    int m0 = (wid >> 1) * 64, n0 = (wid & 1) * 64;

    float acc[4][8][4];
    #pragma unroll
    for (int i = 0; i < 4; i++)
        #pragma unroll
        for (int j = 0; j < 8; j++)
            #pragma unroll
            for (int u = 0; u < 4; u++) acc[i][j][u] = 0.0f;

    const int nc = K >> 6;
    auto loadStage = [&](int s, int c) {
        uint32_t base = sb + s * G16_STAGE;
        int k0 = c << 6;
        #pragma unroll
        for (int i = 0; i < 8; i++) {
            int idx = i * 128 + tid;
            int row = idx >> 3, c16 = idx & 7;
            uint32_t off = swz128(row * 128 + c16 * 16);
            cpasync16(base + off,         A + (size_t)(rBase + row) * K + k0 + c16 * 8);
            cpasync16(base + 16384 + off, B + (size_t)(cBase + row) * K + k0 + c16 * 8);
        }
    };

    int aRow = (lane & 7) + ((lane >> 3) & 1) * 8;
    int aC   = lane >> 4;
    int bRow16 = (lane & 7) + ((lane >> 4) & 1) * 8;
    int bH     = (lane >> 3) & 1;

    loadStage(0, 0); cpcommit();

    for (int c = 0; c < nc; c++) {
        if (c + 1 < nc) { loadStage((c + 1) & 1, c + 1); cpcommit(); cpwait<1>(); }
        else            { cpwait<0>(); }
        __syncthreads();
        uint32_t base = sb + (c & 1) * G16_STAGE;
        #pragma unroll
        for (int kc = 0; kc < 4; kc++) {
            uint32_t bh[8][2];
            #pragma unroll
            for (int jp = 0; jp < 4; jp++) {
                int row = n0 + jp * 16 + bRow16;
                uint32_t t4[4];
                ldsm4(t4, base + 16384 + swz128(row * 128 + kc * 32 + bH * 16));
                bh[2 * jp][0] = t4[0]; bh[2 * jp][1] = t4[1];
                bh[2 * jp + 1][0] = t4[2]; bh[2 * jp + 1][1] = t4[3];
            }
            #pragma unroll
            for (int i = 0; i < 4; i++) {
                uint32_t a4[4];
                int row = m0 + i * 16 + aRow;
                ldsm4(a4, base + swz128(row * 128 + kc * 32 + aC * 16));
                #pragma unroll
                for (int j = 0; j < 8; j++)
                    mma16816h(acc[i][j], a4, bh[j]);
            }
        }
        __syncthreads();
    }

    int lr = lane >> 2, lc = (lane & 3) << 1;
    #pragma unroll
    for (int i = 0; i < 4; i++) {
        #pragma unroll
        for (int half_ = 0; half_ < 2; half_++) {
            size_t row = (size_t)(rBase + m0 + i * 16 + lr + half_ * 8);
            #pragma unroll
            for (int j = 0; j < 8; j++) {
                int col = cBase + n0 + j * 8 + lc;
                float v0 = acc[i][j][half_ * 2 + 0] + bias[col];
                float v1 = acc[i][j][half_ * 2 + 1] + bias[col + 1];
                if (EPI == 0) {
                    uint32_t p;
                    packh2(v0, v1, p);
                    *(uint32_t*)(outH + row * N + col) = p;
                } else if (EPI == 1) {
                    v0 = 0.5f * v0 * (1.0f + erff(v0 * 0.70710678118654752f));
                    v1 = 0.5f * v1 * (1.0f + erff(v1 * 0.70710678118654752f));
                    uint32_t p;
                    packh2(v0, v1, p);
                    *(uint32_t*)(outH + row * N + col) = p;
                } else {
                    float2 rv = *(const float2*)(res + row * N + col);
                    float2 o; o.x = v0 + rv.x; o.y = v1 + rv.y;
                    *(float2*)(outF + row * N + col) = o;
                }
            }
        }
    }
}

// ---------------- fused QKV / KV projection GEMM -------------------------------
// MODE 0 (N=3072): region 0 -> single o0 (Q), region 1 -> hi/lo o1h/o1l (K),
//                  region 2 -> single o2 (V)
// MODE 1 (N=2048): region 0 -> hi/lo o1h/o1l (K), region 1 -> single o2 (V)
// All outputs are [M][1024].
template <int MODE>
__global__ void __launch_bounds__(128, 2) gemm_qkv(
    const half* __restrict__ A, const half* __restrict__ B,
    const float* __restrict__ b0, const float* __restrict__ b1,
    const float* __restrict__ b2,
    half* __restrict__ o0, half* __restrict__ o1h, half* __restrict__ o1l,
    half* __restrict__ o2, int M, int K) {
    extern __shared__ char dyn[];
    uint32_t sb = (smem_u32(dyn) + 127) & ~127u;
    int tid = threadIdx.x, lane = tid & 31, wid = tid >> 5;
    int rBase = blockIdx.y * 128, cBase = blockIdx.x * 128;
    int m0 = (wid >> 1) * 64, n0 = (wid & 1) * 64;

    float acc[4][8][4];
    #pragma unroll
    for (int i = 0; i < 4; i++)
        #pragma unroll
        for (int j = 0; j < 8; j++)
            #pragma unroll
            for (int u = 0; u < 4; u++) acc[i][j][u] = 0.0f;

    const int nc = K >> 6;
    auto loadStage = [&](int s, int c) {
        uint32_t base = sb + s * G16_STAGE;
        int k0 = c << 6;
        #pragma unroll
        for (int i = 0; i < 8; i++) {
            int idx = i * 128 + tid;
            int row = idx >> 3, c16 = idx & 7;
            uint32_t off = swz128(row * 128 + c16 * 16);
            cpasync16(base + off,         A + (size_t)(rBase + row) * K + k0 + c16 * 8);
            cpasync16(base + 16384 + off, B + (size_t)(cBase + row) * K + k0 + c16 * 8);
        }
    };

    int aRow = (lane & 7) + ((lane >> 3) & 1) * 8;
    int aC   = lane >> 4;
    int bRow16 = (lane & 7) + ((lane >> 4) & 1) * 8;
    int bH     = (lane >> 3) & 1;

    loadStage(0, 0); cpcommit();

    for (int c = 0; c < nc; c++) {
        if (c + 1 < nc) { loadStage((c + 1) & 1, c + 1); cpcommit(); cpwait<1>(); }
        else            { cpwait<0>(); }
        __syncthreads();
        uint32_t base = sb + (c & 1) * G16_STAGE;
        #pragma unroll
        for (int kc = 0; kc < 4; kc++) {
            uint32_t bh[8][2];
            #pragma unroll
            for (int jp = 0; jp < 4; jp++) {
                int row = n0 + jp * 16 + bRow16;
                uint32_t t4[4];
                ldsm4(t4, base + 16384 + swz128(row * 128 + kc * 32 + bH * 16));
                bh[2 * jp][0] = t4[0]; bh[2 * jp][1] = t4[1];
                bh[2 * jp + 1][0] = t4[2]; bh[2 * jp + 1][1] = t4[3];
            }
            #pragma unroll
            for (int i = 0; i < 4; i++) {
                uint32_t a4[4];
                int row = m0 + i * 16 + aRow;
                ldsm4(a4, base + swz128(row * 128 + kc * 32 + aC * 16));
                #pragma unroll
                for (int j = 0; j < 8; j++)
                    mma16816h(acc[i][j], a4, bh[j]);
            }
        }
        __syncthreads();
    }

    // epilogue: region from global column
    int region = cBase >> 10;
    int cLoc = (cBase & 1023) + n0;  // local column base within region
    const float* bias = (MODE == 0)
        ? (region == 0 ? b0 : (region == 1 ? b1 : b2))
        : (region == 0 ? b1 : b2);
    bool hilo = (MODE == 0) ? (region == 1) : (region == 0);
    half* outS = (MODE == 0) ? (region == 0 ? o0 : o2) : o2;

    int lr = lane >> 2, lc = (lane & 3) << 1;
    #pragma unroll
    for (int i = 0; i < 4; i++) {
        #pragma unroll
        for (int half_ = 0; half_ < 2; half_++) {
            size_t row = (size_t)(rBase + m0 + i * 16 + lr + half_ * 8);
            #pragma unroll
            for (int j = 0; j < 8; j++) {
                int col = cLoc + j * 8 + lc;
                float v0 = acc[i][j][half_ * 2 + 0] + bias[col];
                float v1 = acc[i][j][half_ * 2 + 1] + bias[col + 1];
                if (hilo) {
                    uint32_t hp, lp;
                    packsplit16(v0, v1, hp, lp);
                    *(uint32_t*)(o1h + row * E_DIM + col) = hp;
                    *(uint32_t*)(o1l + row * E_DIM + col) = lp;
                } else {
                    uint32_t p;
                    packh2(v0, v1, p);
                    *(uint32_t*)(outS + row * E_DIM + col) = p;
                }
            }
        }
    }
}

// ---------------- flash attention (D=64): Q,P,V single; K hi/lo ---------------
// grid (S/64, H, B), 128 threads.
// SMEM: Q 8K @0 | stage s at 8K + s*24K: Kh, Kl, Vh (8K each).
#define ATTN_SMEM (8192 + 2 * 24576 + 1024)
template <bool CAUSAL>
__global__ void __launch_bounds__(128, 2) attn16(
    const half* __restrict__ Q,
    const half* __restrict__ Kh, const half* __restrict__ Kl,
    const half* __restrict__ V,
    half* __restrict__ O) {
    extern __shared__ char dyn[];
    uint32_t sb = (smem_u32(dyn) + 1023) & ~1023u;
    int tid = threadIdx.x, lane = tid & 31, w = tid >> 5;
    int b = blockIdx.z, hh = blockIdx.y, qt = blockIdx.x;
    size_t headOff = (size_t)hh * D_DIM;
    size_t tokBase = (size_t)b * S_LEN;

    int aRow = (lane & 7) + ((lane >> 3) & 1) * 8;
    int aC = lane >> 4;

    {
        #pragma unroll
        for (int i = 0; i < 4; i++) {
            int idx = i * 128 + tid;
            int r = idx >> 3, c = idx & 7;
            uint32_t off = swz128(r * 128 + c * 16);
            cpasync16(sb + off, Q + (tokBase + qt * 64 + r) * E_DIM + headOff + c * 8);
        }
    }
    auto loadKV = [&](int s, int kt) {
        uint32_t base = sb + 8192 + s * 24576;
        #pragma unroll
        for (int i = 0; i < 4; i++) {
            int idx = i * 128 + tid;
            int r = idx >> 3, c = idx & 7;
            uint32_t off = swz128(r * 128 + c * 16);
            size_t src = (tokBase + kt * 64 + r) * E_DIM + headOff + c * 8;
            cpasync16(base + off,         Kh + src);
            cpasync16(base + 8192 + off,  Kl + src);
            cpasync16(base + 16384 + off, V + src);
        }
    };
    loadKV(0, 0);
    cpcommit();

    uint32_t qf[4][4];
    float oacc[8][4];
    float mrow[2] = {-1e30f, -1e30f}, lrow[2] = {0.0f, 0.0f};
    #pragma unroll
    for (int j = 0; j < 8; j++)
        #pragma unroll
        for (int u = 0; u < 4; u++) oacc[j][u] = 0.0f;

    const int ntiles = CAUSAL ? (qt + 1) : (S_LEN / 64);
    for (int kt = 0; kt < ntiles; kt++) {
        if (kt + 1 < ntiles) { loadKV((kt + 1) & 1, kt + 1); cpcommit(); cpwait<1>(); }
        else                 { cpwait<0>(); }
        __syncthreads();
        if (kt == 0) {
            #pragma unroll
            for (int s = 0; s < 4; s++)
                ldsm4(qf[s], sb + swz128((w * 16 + aRow) * 128 + s * 32 + aC * 16));
        }
        uint32_t kb = sb + 8192 + (kt & 1) * 24576;
        uint32_t vb = kb + 16384;

        float sacc[8][4];
        #pragma unroll
        for (int j = 0; j < 8; j++)
            #pragma unroll
            for (int u = 0; u < 4; u++) sacc[j][u] = 0.0f;
        #pragma unroll
        for (int s = 0; s < 4; s++) {
            #pragma unroll
            for (int jp = 0; jp < 4; jp++) {
                uint32_t addr = kb + swz128((jp * 16 + aRow) * 128 + s * 32 + aC * 16);
                uint32_t kh4[4], kl4[4];
                ldsm4(kh4, addr);
                ldsm4(kl4, addr + 8192);
                uint32_t b0h[2] = {kh4[0], kh4[2]}, b1h[2] = {kh4[1], kh4[3]};
                uint32_t b0l[2] = {kl4[0], kl4[2]}, b1l[2] = {kl4[1], kl4[3]};
                mma16816h(sacc[2 * jp],     qf[s], b0h);
                mma16816h(sacc[2 * jp],     qf[s], b0l);
                mma16816h(sacc[2 * jp + 1], qf[s], b1h);
                mma16816h(sacc[2 * jp + 1], qf[s], b1l);
            }
        }

        if (CAUSAL && kt == qt) {
            int ql0 = w * 16 + (lane >> 2);
            #pragma unroll
            for (int j = 0; j < 8; j++)
                #pragma unroll
                for (int u = 0; u < 4; u++) {
                    int kcol = j * 8 + ((lane & 3) << 1) + (u & 1);
                    int qrow = ql0 + (u >> 1) * 8;
                    if (kcol > qrow) sacc[j][u] = -1e30f;
                }
        }

        #pragma unroll
        for (int h2 = 0; h2 < 2; h2++) {
            float mt = -1e30f;
            #pragma unroll
            for (int j = 0; j < 8; j++)
                mt = fmaxf(mt, fmaxf(sacc[j][2 * h2], sacc[j][2 * h2 + 1]));
            mt = fmaxf(mt, __shfl_xor_sync(0xffffffffu, mt, 1));
            mt = fmaxf(mt, __shfl_xor_sync(0xffffffffu, mt, 2));
            float mn = fmaxf(mrow[h2], mt);
            float sc = __expf(mrow[h2] - mn);
            mrow[h2] = mn;
            float ts = 0.0f;
            #pragma unroll
            for (int j = 0; j < 8; j++) {
                sacc[j][2 * h2]     = __expf(sacc[j][2 * h2] - mn);
                sacc[j][2 * h2 + 1] = __expf(sacc[j][2 * h2 + 1] - mn);
                ts += sacc[j][2 * h2] + sacc[j][2 * h2 + 1];
            }
            ts += __shfl_xor_sync(0xffffffffu, ts, 1);
            ts += __shfl_xor_sync(0xffffffffu, ts, 2);
            lrow[h2] = lrow[h2] * sc + ts;
            #pragma unroll
            for (int j = 0; j < 8; j++) {
                oacc[j][2 * h2]     *= sc;
                oacc[j][2 * h2 + 1] *= sc;
            }
        }

        #pragma unroll
        for (int s = 0; s < 4; s++) {
            uint32_t pf[4];
            packh2(sacc[2 * s][0],     sacc[2 * s][1],     pf[0]);
            packh2(sacc[2 * s][2],     sacc[2 * s][3],     pf[1]);
            packh2(sacc[2 * s + 1][0], sacc[2 * s + 1][1], pf[2]);
            packh2(sacc[2 * s + 1][2], sacc[2 * s + 1][3], pf[3]);
            #pragma unroll
            for (int jp = 0; jp < 4; jp++) {
                uint32_t vh4[4];
                ldsm4t(vh4, vb + swz128((s * 16 + aRow) * 128 + jp * 32 + aC * 16));
                uint32_t b0h[2] = {vh4[0], vh4[1]}, b1h[2] = {vh4[2], vh4[3]};
                mma16816h(oacc[2 * jp],     pf, b0h);
                mma16816h(oacc[2 * jp + 1], pf, b1h);
            }
        }
        __syncthreads();
    }

    #pragma unroll
    for (int h2 = 0; h2 < 2; h2++) {
        float inv = 1.0f / lrow[h2];
        int trow = qt * 64 + w * 16 + (lane >> 2) + h2 * 8;
        size_t rp = (tokBase + trow) * E_DIM + headOff;
        #pragma unroll
        for (int j = 0; j < 8; j++) {
            uint32_t p;
            packh2(oacc[j][2 * h2] * inv, oacc[j][2 * h2 + 1] * inv, p);
            int col = j * 8 + ((lane & 3) << 1);
            *(uint32_t*)(O + rp + col) = p;
        }
    }
}

// ---------------- launch ------------------------------------------------------
extern "C" void kernel_launch(void* const* d_in, const int* in_sizes, int n_in,
                              void* d_out, int out_size) {
    const float* x    = (const float*)d_in[0];
    const float* enc  = (const float*)d_in[1];
    const float* ln1g = (const float*)d_in[2];
    const float* ln1b = (const float*)d_in[3];
    const float* ln2g = (const float*)d_in[4];
    const float* ln2b = (const float*)d_in[5];
    const float* ln3g = (const float*)d_in[6];
    const float* ln3b = (const float*)d_in[7];
    const float* Wq1  = (const float*)d_in[8];
    const float* bq1  = (const float*)d_in[9];
    const float* Wk1  = (const float*)d_in[10];
    const float* bk1  = (const float*)d_in[11];
    const float* Wv1  = (const float*)d_in[12];
    const float* bv1  = (const float*)d_in[13];
    const float* Wo1  = (const float*)d_in[14];
    const float* bo1  = (const float*)d_in[15];
    const float* Wq2  = (const float*)d_in[16];
    const float* bq2  = (const float*)d_in[17];
    const float* Wk2  = (const float*)d_in[18];
    const float* bk2  = (const float*)d_in[19];
    const float* Wv2  = (const float*)d_in[20];
    const float* bv2  = (const float*)d_in[21];
    const float* Wo2  = (const float*)d_in[22];
    const float* bo2  = (const float*)d_in[23];
    const float* Wup  = (const float*)d_in[24];
    const float* bup  = (const float*)d_in[25];
    const float* Wdn  = (const float*)d_in[26];
    const float* bdn  = (const float*)d_in[27];
    float* out = (float*)d_out;

    half *W16, *h16, *e16, *q16, *kh16, *kl16, *v16, *a16;
    float *x1, *x2;
    cudaGetSymbolAddress((void**)&W16,  g_W16);
    cudaGetSymbolAddress((void**)&h16,  g_h16);
    cudaGetSymbolAddress((void**)&e16,  g_e16);
    cudaGetSymbolAddress((void**)&q16,  g_q16);
    cudaGetSymbolAddress((void**)&kh16, g_kh16);
    cudaGetSymbolAddress((void**)&kl16, g_kl16);
    cudaGetSymbolAddress((void**)&v16,  g_v16);
    cudaGetSymbolAddress((void**)&a16,  g_a16);
    cudaGetSymbolAddress((void**)&x1,   g_x1);
    cudaGetSymbolAddress((void**)&x2,   g_x2);

    cudaFuncSetAttribute(gemm16<0>, cudaFuncAttributeMaxDynamicSharedMemorySize, G16_SMEM);
    cudaFuncSetAttribute(gemm16<1>, cudaFuncAttributeMaxDynamicSharedMemorySize, G16_SMEM);
    cudaFuncSetAttribute(gemm16<2>, cudaFuncAttributeMaxDynamicSharedMemorySize, G16_SMEM);
    cudaFuncSetAttribute(gemm_qkv<0>, cudaFuncAttributeMaxDynamicSharedMemorySize, G16_SMEM);
    cudaFuncSetAttribute(gemm_qkv<1>, cudaFuncAttributeMaxDynamicSharedMemorySize, G16_SMEM);
    cudaFuncSetAttribute(attn16<true>,  cudaFuncAttributeMaxDynamicSharedMemorySize, ATTN_SMEM);
    cudaFuncSetAttribute(attn16<false>, cudaFuncAttributeMaxDynamicSharedMemorySize, ATTN_SMEM);

    const int WS = E_DIM * E_DIM;
    dim3 gSq(8, 32);
    dim3 gUp(32, 32);
    dim3 gQKV(24, 32);
    dim3 gKV(16, 32);
    dim3 gAttn(S_LEN / 64, H_NUM, B_NUM);
    dim3 trB(32, 8);

    // launch order: index 5 (ncu capture) = fused QKV1 GEMM
    wqkv_cvt_all<<<dim3(2, 32, 96), 256>>>(Wq1, Wk1, Wv1, Wq2, Wk2, Wv2, W16);          // 0
    cvt16<<<4096, 256>>>(enc, e16);                                                     // 1
    ln_kernel<<<M_ROWS, 256>>>(x, ln1g, ln1b, h16);                                     // 2
    wt_cvt16<<<dim3(32, 32), trB>>>(Wo1, W16 + 6 * WS, 1024, 1024);                     // 3
    wt_cvt16<<<dim3(128, 32), trB>>>(Wup, W16 + 8 * WS, 1024, 4096);                    // 4
    gemm_qkv<0><<<gQKV, 128, G16_SMEM>>>(h16, W16, bq1, bk1, bv1,
                                         q16, kh16, kl16, v16, M_ROWS, E_DIM);          // 5 (ncu)
    attn16<true><<<gAttn, 128, ATTN_SMEM>>>(q16, kh16, kl16, v16, a16);                 // 6
    wt_cvt16<<<dim3(32, 32), trB>>>(Wo2, W16 + 7 * WS, 1024, 1024);                     // 7
    gemm16<2><<<gSq, 128, G16_SMEM>>>(a16, W16 + 6 * WS, bo1, x,
                                      x1, nullptr, M_ROWS, E_DIM, E_DIM);               // 8

    ln_kernel<<<M_ROWS, 256>>>(x1, ln2g, ln2b, h16);                                    // 9
    gemm16<0><<<gSq, 128, G16_SMEM>>>(h16, W16 + 3 * WS, bq2, nullptr,
                                      nullptr, q16, M_ROWS, E_DIM, E_DIM);              // 10
    gemm_qkv<1><<<gKV, 128, G16_SMEM>>>(e16, W16 + 4 * WS, nullptr, bk2, bv2,
                                        nullptr, kh16, kl16, v16, M_ROWS, E_DIM);       // 11
    attn16<false><<<gAttn, 128, ATTN_SMEM>>>(q16, kh16, kl16, v16, a16);                // 12
    wt_cvt16<<<dim3(32, 128), trB>>>(Wdn, W16 + 12 * WS, 4096, 1024);                   // 13
    gemm16<2><<<gSq, 128, G16_SMEM>>>(a16, W16 + 7 * WS, bo2, x1,
                                      x2, nullptr, M_ROWS, E_DIM, E_DIM);               // 14

    ln_kernel<<<M_ROWS, 256>>>(x2, ln3g, ln3b, h16);                                    // 15
    gemm16<1><<<gUp, 128, G16_SMEM>>>(h16, W16 + 8 * WS, bup, nullptr,
                                      nullptr, a16, M_ROWS, F_DIM, E_DIM);              // 16
    gemm16<2><<<gSq, 128, G16_SMEM>>>(a16, W16 + 12 * WS, bdn, x2,
                                      out, nullptr, M_ROWS, E_DIM, F_DIM);              // 17
}

// round 10
// speedup vs baseline: 6.3811x; 1.0215x over previous
#include <cuda_runtime.h>
#include <cuda_fp16.h>
#include <math.h>
#include <cstdint>

#define E_DIM 1024
#define H_NUM 16
#define D_DIM 64
#define B_NUM 4
#define S_LEN 1024
#define F_DIM 4096
#define M_ROWS (B_NUM * S_LEN)  // 4096
#define MB1 (1024 * 1024)

// ---------------- scratch (static device globals) ---------------------------
// Weight slots (single fp16, [N][K] transposed): QKV1 0-2, QKV2 3-5, Wo1 6, Wo2 7,
// Wup 8-11, Wdn 12-15.
__device__ __align__(16) half g_W16[16 * MB1];
__device__ __align__(16) half g_h16[4 * MB1];          // LN out
__device__ __align__(16) half g_e16[4 * MB1];          // enc
__device__ __align__(16) half g_q16[4 * MB1];          // Q (single)
__device__ __align__(16) half g_kh16[4 * MB1], g_kl16[4 * MB1];  // K hi/lo
__device__ __align__(16) half g_v16[4 * MB1];          // V (single)
__device__ __align__(16) half g_a16[16 * MB1];         // attn out / GELU out
__device__ __align__(16) float g_x1[4 * MB1], g_x2[4 * MB1];

// ---------------- PTX helpers -----------------------------------------------
__device__ __forceinline__ uint32_t smem_u32(const void* p) {
    uint32_t a;
    asm("{ .reg .u64 t; cvta.to.shared.u64 t, %1; cvt.u32.u64 %0, t; }" : "=r"(a) : "l"(p));
    return a;
}
__device__ __forceinline__ void cpasync16(uint32_t dst, const void* src) {
    asm volatile("cp.async.cg.shared.global [%0], [%1], 16;" :: "r"(dst), "l"(src));
}
__device__ __forceinline__ void cpcommit() { asm volatile("cp.async.commit_group;" ::: "memory"); }
template <int N>
__device__ __forceinline__ void cpwait() { asm volatile("cp.async.wait_group %0;" :: "n"(N) : "memory"); }

__device__ __forceinline__ void ldsm4(uint32_t (&r)[4], uint32_t addr) {
    asm volatile("ldmatrix.sync.aligned.m8n8.x4.shared.b16 {%0,%1,%2,%3}, [%4];"
                 : "=r"(r[0]), "=r"(r[1]), "=r"(r[2]), "=r"(r[3]) : "r"(addr));
}
__device__ __forceinline__ void ldsm4t(uint32_t (&r)[4], uint32_t addr) {
    asm volatile("ldmatrix.sync.aligned.m8n8.x4.trans.shared.b16 {%0,%1,%2,%3}, [%4];"
                 : "=r"(r[0]), "=r"(r[1]), "=r"(r[2]), "=r"(r[3]) : "r"(addr));
}
__device__ __forceinline__ void mma16816h(float (&d)[4], const uint32_t (&a)[4],
                                          const uint32_t (&b)[2]) {
    asm volatile(
        "mma.sync.aligned.m16n8k16.row.col.f32.f16.f16.f32 "
        "{%0,%1,%2,%3}, {%4,%5,%6,%7}, {%8,%9}, {%0,%1,%2,%3};"
        : "+f"(d[0]), "+f"(d[1]), "+f"(d[2]), "+f"(d[3])
        : "r"(a[0]), "r"(a[1]), "r"(a[2]), "r"(a[3]), "r"(b[0]), "r"(b[1]));
}
__device__ __forceinline__ uint32_t swz128(uint32_t o) { return o ^ ((o >> 3) & 0x70); }

__device__ __forceinline__ void h_split(float v, half& hi, half& lo) {
    hi = __float2half_rn(v);
    lo = __float2half_rn(v - __half2float(hi));
}
__device__ __forceinline__ void packh2(float a, float b, uint32_t& r) {
    half2 p; p.x = __float2half_rn(a); p.y = __float2half_rn(b);
    r = *(uint32_t*)&p;
}
__device__ __forceinline__ void packsplit16(float a, float b, uint32_t& hi, uint32_t& lo) {
    half ah, al, bh, bl;
    h_split(a, ah, al); h_split(b, bh, bl);
    half2 hp, lp;
    hp.x = ah; hp.y = bh; lp.x = al; lp.y = bl;
    hi = *(uint32_t*)&hp; lo = *(uint32_t*)&lp;
}

// ---------------- weight prep -------------------------------------------------
// All 6 QKV weights: [H,E,D] -> Bt[n=h*64+d][k=e], single fp16 (slots 0-5).
__global__ void __launch_bounds__(256) wqkv_cvt_all(
    const float* __restrict__ w0, const float* __restrict__ w1,
    const float* __restrict__ w2, const float* __restrict__ w3,
    const float* __restrict__ w4, const float* __restrict__ w5,
    half* __restrict__ o16) {
    __shared__ float tile[32][33];
    int dt = blockIdx.x;
    int et = blockIdx.y;
    int z  = blockIdx.z;            // s*16 + h
    int s = z >> 4, h = z & 15;
    const float* src;
    switch (s) {
        case 0: src = w0; break; case 1: src = w1; break; case 2: src = w2; break;
        case 3: src = w3; break; case 4: src = w4; break; default: src = w5; break;
    }
    int tx = threadIdx.x & 31, ty = threadIdx.x >> 5;
    int e0 = et * 32, d0 = dt * 32;
    #pragma unroll
    for (int i = 0; i < 4; i++)
        tile[ty + 8 * i][tx] = src[h * (E_DIM * D_DIM) + (e0 + ty + 8 * i) * D_DIM + d0 + tx];
    __syncthreads();
    #pragma unroll
    for (int i = 0; i < 4; i++) {
        size_t oidx = (size_t)s * MB1 + (size_t)(h * 64 + d0 + ty + 8 * i) * E_DIM + e0 + tx;
        o16[oidx] = __float2half_rn(tile[tx][ty + 8 * i]);
    }
}
// [K,N] row-major -> Bt[n][k], single fp16
__global__ void wt_cvt16(const float* __restrict__ src,
                         half* __restrict__ o16, int K, int N) {
    __shared__ float tile[32][33];
    int n0 = blockIdx.x * 32, k0 = blockIdx.y * 32;
    int tx = threadIdx.x, ty = threadIdx.y;
    #pragma unroll
    for (int i = 0; i < 4; i++)
        tile[ty + 8 * i][tx] = src[(size_t)(k0 + ty + 8 * i) * N + n0 + tx];
    __syncthreads();
    #pragma unroll
    for (int i = 0; i < 4; i++)
        o16[(size_t)(n0 + ty + 8 * i) * K + k0 + tx] = __float2half_rn(tile[tx][ty + 8 * i]);
}
// f32 -> single fp16
__global__ void cvt16(const float* __restrict__ src, half* __restrict__ dst) {
    int i = blockIdx.x * 256 + threadIdx.x;
    float4 v = ((const float4*)src)[i];
    uint32_t p0, p1;
    packh2(v.x, v.y, p0);
    packh2(v.z, v.w, p1);
    *(uint32_t*)(dst + 4 * (size_t)i) = p0;
    *(uint32_t*)(dst + 4 * (size_t)i + 2) = p1;
}

// ---------------- LayerNorm: f32 -> single fp16 -------------------------------
__global__ void __launch_bounds__(256) ln_kernel(const float* __restrict__ x,
                                                 const float* __restrict__ g,
                                                 const float* __restrict__ b,
                                                 half* __restrict__ o16) {
    int row = blockIdx.x;
    int t = threadIdx.x;
    float4 v = ((const float4*)(x + (size_t)row * E_DIM))[t];
    float s = v.x + v.y + v.z + v.w;
    float ss = v.x * v.x + v.y * v.y + v.z * v.z + v.w * v.w;
    #pragma unroll
    for (int o = 16; o > 0; o >>= 1) {
        s  += __shfl_xor_sync(0xffffffffu, s, o);
        ss += __shfl_xor_sync(0xffffffffu, ss, o);
    }
    __shared__ float red[2][8];
    int w = t >> 5, lane = t & 31;
    if (lane == 0) { red[0][w] = s; red[1][w] = ss; }
    __syncthreads();
    s = 0.0f; ss = 0.0f;
    #pragma unroll
    for (int i = 0; i < 8; i++) { s += red[0][i]; ss += red[1][i]; }
    float mu  = s * (1.0f / E_DIM);
    float var = ss * (1.0f / E_DIM) - mu * mu;
    float inv = rsqrtf(var + 1e-5f);
    float4 gv = ((const float4*)g)[t];
    float4 bv = ((const float4*)b)[t];
    float o0 = (v.x - mu) * inv * gv.x + bv.x;
    float o1 = (v.y - mu) * inv * gv.y + bv.y;
    float o2 = (v.z - mu) * inv * gv.z + bv.z;
    float o3 = (v.w - mu) * inv * gv.w + bv.w;
    size_t base = (size_t)row * E_DIM + t * 4;
    uint32_t p0, p1;
    packh2(o0, o1, p0);
    packh2(o2, o3, p1);
    *(uint32_t*)(o16 + base) = p0;
    *(uint32_t*)(o16 + base + 2) = p1;
}

#define G16_STAGE 32768
#define G16_SMEM (2 * G16_STAGE + 256)

// ---------------- fp16 GEMM (single x single) ----------------------------------
// EPI: 0 bias -> fp16 single, 1 bias+GELU -> fp16, 2 bias+res -> f32
template <int EPI>
__global__ void __launch_bounds__(128, 2) gemm16(
    const half* __restrict__ A, const half* __restrict__ B,
    const float* __restrict__ bias, const float* __restrict__ res,
    float* __restrict__ outF, half* __restrict__ outH,
    int M, int N, int K) {
    extern __shared__ char dyn[];
    uint32_t sb = (smem_u32(dyn) + 127) & ~127u;
    int tid = threadIdx.x, lane = tid & 31, wid = tid >> 5;
    int rBase = blockIdx.y * 128, cBase = blockIdx.x * 128;
    int m0 = (wid >> 1) * 64, n0 = (wid & 1) * 64;

    float acc[4][8][4];
    #pragma unroll
    for (int i = 0; i < 4; i++)
        #pragma unroll
        for (int j = 0; j < 8; j++)
            #pragma unroll
            for (int u = 0; u < 4; u++) acc[i][j][u] = 0.0f;

    const int nc = K >> 6;
    auto loadStage = [&](int s, int c) {
        uint32_t base = sb + s * G16_STAGE;
        int k0 = c << 6;
        #pragma unroll
        for (int i = 0; i < 8; i++) {
            int idx = i * 128 + tid;
            int row = idx >> 3, c16 = idx & 7;
            uint32_t off = swz128(row * 128 + c16 * 16);
            cpasync16(base + off,         A + (size_t)(rBase + row) * K + k0 + c16 * 8);
            cpasync16(base + 16384 + off, B + (size_t)(cBase + row) * K + k0 + c16 * 8);
        }
    };

    int aRow = (lane & 7) + ((lane >> 3) & 1) * 8;
    int aC   = lane >> 4;
    int bRow16 = (lane & 7) + ((lane >> 4) & 1) * 8;
    int bH     = (lane >> 3) & 1;

    loadStage(0, 0); cpcommit();

    for (int c = 0; c < nc; c++) {
        if (c + 1 < nc) { loadStage((c + 1) & 1, c + 1); cpcommit(); cpwait<1>(); }
        else            { cpwait<0>(); }
        __syncthreads();
        uint32_t base = sb + (c & 1) * G16_STAGE;
        #pragma unroll
        for (int kc = 0; kc < 4; kc++) {
            uint32_t bh[8][2];
            #pragma unroll
            for (int jp = 0; jp < 4; jp++) {
                int row = n0 + jp * 16 + bRow16;
                uint32_t t4[4];
                ldsm4(t4, base + 16384 + swz128(row * 128 + kc * 32 + bH * 16));
                bh[2 * jp][0] = t4[0]; bh[2 * jp][1] = t4[1];
                bh[2 * jp + 1][0] = t4[2]; bh[2 * jp + 1][1] = t4[3];
            }
            #pragma unroll
            for (int i = 0; i < 4; i++) {
                uint32_t a4[4];
                int row = m0 + i * 16 + aRow;
                ldsm4(a4, base + swz128(row * 128 + kc * 32 + aC * 16));
                #pragma unroll
                for (int j = 0; j < 8; j++)
                    mma16816h(acc[i][j], a4, bh[j]);
            }
        }
        __syncthreads();
    }

    int lr = lane >> 2, lc = (lane & 3) << 1;
    #pragma unroll
    for (int i = 0; i < 4; i++) {
        #pragma unroll
        for (int half_ = 0; half_ < 2; half_++) {
            size_t row = (size_t)(rBase + m0 + i * 16 + lr + half_ * 8);
            #pragma unroll
            for (int j = 0; j < 8; j++) {
                int col = cBase + n0 + j * 8 + lc;
                float v0 = acc[i][j][half_ * 2 + 0] + bias[col];
                float v1 = acc[i][j][half_ * 2 + 1] + bias[col + 1];
                if (EPI == 0) {
                    uint32_t p;
                    packh2(v0, v1, p);
                    *(uint32_t*)(outH + row * N + col) = p;
                } else if (EPI == 1) {
                    v0 = 0.5f * v0 * (1.0f + erff(v0 * 0.70710678118654752f));
                    v1 = 0.5f * v1 * (1.0f + erff(v1 * 0.70710678118654752f));
                    uint32_t p;
                    packh2(v0, v1, p);
                    *(uint32_t*)(outH + row * N + col) = p;
                } else {
                    float2 rv = *(const float2*)(res + row * N + col);
                    float2 o; o.x = v0 + rv.x; o.y = v1 + rv.y;
                    *(float2*)(outF + row * N + col) = o;
                }
            }
        }
    }
}

// ---------------- fused QKV / KV projection GEMM -------------------------------
// MODE 0 (N=3072): region 0 -> single o0 (Q), region 1 -> hi/lo o1h/o1l (K),
//                  region 2 -> single o2 (V)
// MODE 1 (N=2048): region 0 -> hi/lo o1h/o1l (K), region 1 -> single o2 (V)
template <int MODE>
__global__ void __launch_bounds__(128, 2) gemm_qkv(
    const half* __restrict__ A, const half* __restrict__ B,
    const float* __restrict__ b0, const float* __restrict__ b1,
    const float* __restrict__ b2,
    half* __restrict__ o0, half* __restrict__ o1h, half* __restrict__ o1l,
    half* __restrict__ o2, int M, int K) {
    extern __shared__ char dyn[];
    uint32_t sb = (smem_u32(dyn) + 127) & ~127u;
    int tid = threadIdx.x, lane = tid & 31, wid = tid >> 5;
    int rBase = blockIdx.y * 128, cBase = blockIdx.x * 128;
    int m0 = (wid >> 1) * 64, n0 = (wid & 1) * 64;

    float acc[4][8][4];
    #pragma unroll
    for (int i = 0; i < 4; i++)
        #pragma unroll
        for (int j = 0; j < 8; j++)
            #pragma unroll
            for (int u = 0; u < 4; u++) acc[i][j][u] = 0.0f;

    const int nc = K >> 6;
    auto loadStage = [&](int s, int c) {
        uint32_t base = sb + s * G16_STAGE;
        int k0 = c << 6;
        #pragma unroll
        for (int i = 0; i < 8; i++) {
            int idx = i * 128 + tid;
            int row = idx >> 3, c16 = idx & 7;
            uint32_t off = swz128(row * 128 + c16 * 16);
            cpasync16(base + off,         A + (size_t)(rBase + row) * K + k0 + c16 * 8);
            cpasync16(base + 16384 + off, B + (size_t)(cBase + row) * K + k0 + c16 * 8);
        }
    };

    int aRow = (lane & 7) + ((lane >> 3) & 1) * 8;
    int aC   = lane >> 4;
    int bRow16 = (lane & 7) + ((lane >> 4) & 1) * 8;
    int bH     = (lane >> 3) & 1;

    loadStage(0, 0); cpcommit();

    for (int c = 0; c < nc; c++) {
        if (c + 1 < nc) { loadStage((c + 1) & 1, c + 1); cpcommit(); cpwait<1>(); }
        else            { cpwait<0>(); }
        __syncthreads();
        uint32_t base = sb + (c & 1) * G16_STAGE;
        #pragma unroll
        for (int kc = 0; kc < 4; kc++) {
            uint32_t bh[8][2];
            #pragma unroll
            for (int jp = 0; jp < 4; jp++) {
                int row = n0 + jp * 16 + bRow16;
                uint32_t t4[4];
                ldsm4(t4, base + 16384 + swz128(row * 128 + kc * 32 + bH * 16));
                bh[2 * jp][0] = t4[0]; bh[2 * jp][1] = t4[1];
                bh[2 * jp + 1][0] = t4[2]; bh[2 * jp + 1][1] = t4[3];
            }
            #pragma unroll
            for (int i = 0; i < 4; i++) {
                uint32_t a4[4];
                int row = m0 + i * 16 + aRow;
                ldsm4(a4, base + swz128(row * 128 + kc * 32 + aC * 16));
                #pragma unroll
                for (int j = 0; j < 8; j++)
                    mma16816h(acc[i][j], a4, bh[j]);
            }
        }
        __syncthreads();
    }

    int region = cBase >> 10;
    int cLoc = (cBase & 1023) + n0;
    const float* bias = (MODE == 0)
        ? (region == 0 ? b0 : (region == 1 ? b1 : b2))
        : (region == 0 ? b1 : b2);
    bool hilo = (MODE == 0) ? (region == 1) : (region == 0);
    half* outS = (MODE == 0) ? (region == 0 ? o0 : o2) : o2;

    int lr = lane >> 2, lc = (lane & 3) << 1;
    #pragma unroll
    for (int i = 0; i < 4; i++) {
        #pragma unroll
        for (int half_ = 0; half_ < 2; half_++) {
            size_t row = (size_t)(rBase + m0 + i * 16 + lr + half_ * 8);
            #pragma unroll
            for (int j = 0; j < 8; j++) {
                int col = cLoc + j * 8 + lc;
                float v0 = acc[i][j][half_ * 2 + 0] + bias[col];
                float v1 = acc[i][j][half_ * 2 + 1] + bias[col + 1];
                if (hilo) {
                    uint32_t hp, lp;
                    packsplit16(v0, v1, hp, lp);
                    *(uint32_t*)(o1h + row * E_DIM + col) = hp;
                    *(uint32_t*)(o1l + row * E_DIM + col) = lp;
                } else {
                    uint32_t p;
                    packh2(v0, v1, p);
                    *(uint32_t*)(outS + row * E_DIM + col) = p;
                }
            }
        }
    }
}

// ---------------- flash attention (D=64): Q,P,V single; K hi/lo ---------------
#define ATTN_SMEM (8192 + 2 * 24576 + 1024)
template <bool CAUSAL>
__global__ void __launch_bounds__(128, 2) attn16(
    const half* __restrict__ Q,
    const half* __restrict__ Kh, const half* __restrict__ Kl,
    const half* __restrict__ V,
    half* __restrict__ O) {
    extern __shared__ char dyn[];
    uint32_t sb = (smem_u32(dyn) + 1023) & ~1023u;
    int tid = threadIdx.x, lane = tid & 31, w = tid >> 5;
    int b = blockIdx.z, hh = blockIdx.y, qt = blockIdx.x;
    size_t headOff = (size_t)hh * D_DIM;
    size_t tokBase = (size_t)b * S_LEN;

    int aRow = (lane & 7) + ((lane >> 3) & 1) * 8;
    int aC = lane >> 4;

    {
        #pragma unroll
        for (int i = 0; i < 4; i++) {
            int idx = i * 128 + tid;
            int r = idx >> 3, c = idx & 7;
            uint32_t off = swz128(r * 128 + c * 16);
            cpasync16(sb + off, Q + (tokBase + qt * 64 + r) * E_DIM + headOff + c * 8);
        }
    }
    auto loadKV = [&](int s, int kt) {
        uint32_t base = sb + 8192 + s * 24576;
        #pragma unroll
        for (int i = 0; i < 4; i++) {
            int idx = i * 128 + tid;
            int r = idx >> 3, c = idx & 7;
            uint32_t off = swz128(r * 128 + c * 16);
            size_t src = (tokBase + kt * 64 + r) * E_DIM + headOff + c * 8;
            cpasync16(base + off,         Kh + src);
            cpasync16(base + 8192 + off,  Kl + src);
            cpasync16(base + 16384 + off, V + src);
        }
    };
    loadKV(0, 0);
    cpcommit();

    uint32_t qf[4][4];
    float oacc[8][4];
    float mrow[2] = {-1e30f, -1e30f}, lrow[2] = {0.0f, 0.0f};
    #pragma unroll
    for (int j = 0; j < 8; j++)
        #pragma unroll
        for (int u = 0; u < 4; u++) oacc[j][u] = 0.0f;

    const int ntiles = CAUSAL ? (qt + 1) : (S_LEN / 64);
    for (int kt = 0; kt < ntiles; kt++) {
        if (kt + 1 < ntiles) { loadKV((kt + 1) & 1, kt + 1); cpcommit(); cpwait<1>(); }
        else                 { cpwait<0>(); }
        __syncthreads();
        if (kt == 0) {
            #pragma unroll
            for (int s = 0; s < 4; s++)
                ldsm4(qf[s], sb + swz128((w * 16 + aRow) * 128 + s * 32 + aC * 16));
        }
        uint32_t kb = sb + 8192 + (kt & 1) * 24576;
        uint32_t vb = kb + 16384;

        float sacc[8][4];
        #pragma unroll
        for (int j = 0; j < 8; j++)
            #pragma unroll
            for (int u = 0; u < 4; u++) sacc[j][u] = 0.0f;
        #pragma unroll
        for (int s = 0; s < 4; s++) {
            #pragma unroll
            for (int jp = 0; jp < 4; jp++) {
                uint32_t addr = kb + swz128((jp * 16 + aRow) * 128 + s * 32 + aC * 16);
                uint32_t kh4[4], kl4[4];
                ldsm4(kh4, addr);
                ldsm4(kl4, addr + 8192);
                uint32_t b0h[2] = {kh4[0], kh4[2]}, b1h[2] = {kh4[1], kh4[3]};
                uint32_t b0l[2] = {kl4[0], kl4[2]}, b1l[2] = {kl4[1], kl4[3]};
                mma16816h(sacc[2 * jp],     qf[s], b0h);
                mma16816h(sacc[2 * jp],     qf[s], b0l);
                mma16816h(sacc[2 * jp + 1], qf[s], b1h);
                mma16816h(sacc[2 * jp + 1], qf[s], b1l);
            }
        }

        if (CAUSAL && kt == qt) {
            int ql0 = w * 16 + (lane >> 2);
            #pragma unroll
            for (int j = 0; j < 8; j++)
                #pragma unroll
                for (int u = 0; u < 4; u++) {
                    int kcol = j * 8 + ((lane & 3) << 1) + (u & 1);
                    int qrow = ql0 + (u >> 1) * 8;
                    if (kcol > qrow) sacc[j][u] = -1e30f;
                }
        }

        #pragma unroll
        for (int h2 = 0; h2 < 2; h2++) {
            float mt = -1e30f;
            #pragma unroll
            for (int j = 0; j < 8; j++)
                mt = fmaxf(mt, fmaxf(sacc[j][2 * h2], sacc[j][2 * h2 + 1]));
            mt = fmaxf(mt, __shfl_xor_sync(0xffffffffu, mt, 1));
            mt = fmaxf(mt, __shfl_xor_sync(0xffffffffu, mt, 2));
            float mn = fmaxf(mrow[h2], mt);
            float sc = __expf(mrow[h2] - mn);
            mrow[h2] = mn;
            float ts = 0.0f;
            #pragma unroll
            for (int j = 0; j < 8; j++) {
                sacc[j][2 * h2]     = __expf(sacc[j][2 * h2] - mn);
                sacc[j][2 * h2 + 1] = __expf(sacc[j][2 * h2 + 1] - mn);
                ts += sacc[j][2 * h2] + sacc[j][2 * h2 + 1];
            }
            ts += __shfl_xor_sync(0xffffffffu, ts, 1);
            ts += __shfl_xor_sync(0xffffffffu, ts, 2);
            lrow[h2] = lrow[h2] * sc + ts;
            #pragma unroll
            for (int j = 0; j < 8; j++) {
                oacc[j][2 * h2]     *= sc;
                oacc[j][2 * h2 + 1] *= sc;
            }
        }

        #pragma unroll
        for (int s = 0; s < 4; s++) {
            uint32_t pf[4];
            packh2(sacc[2 * s][0],     sacc[2 * s][1],     pf[0]);
            packh2(sacc[2 * s][2],     sacc[2 * s][3],     pf[1]);
            packh2(sacc[2 * s + 1][0], sacc[2 * s + 1][1], pf[2]);
            packh2(sacc[2 * s + 1][2], sacc[2 * s + 1][3], pf[3]);
            #pragma unroll
            for (int jp = 0; jp < 4; jp++) {
                uint32_t vh4[4];
                ldsm4t(vh4, vb + swz128((s * 16 + aRow) * 128 + jp * 32 + aC * 16));
                uint32_t b0h[2] = {vh4[0], vh4[1]}, b1h[2] = {vh4[2], vh4[3]};
                mma16816h(oacc[2 * jp],     pf, b0h);
                mma16816h(oacc[2 * jp + 1], pf, b1h);
            }
        }
        __syncthreads();
    }

    #pragma unroll
    for (int h2 = 0; h2 < 2; h2++) {
        float inv = 1.0f / lrow[h2];
        int trow = qt * 64 + w * 16 + (lane >> 2) + h2 * 8;
        size_t rp = (tokBase + trow) * E_DIM + headOff;
        #pragma unroll
        for (int j = 0; j < 8; j++) {
            uint32_t p;
            packh2(oacc[j][2 * h2] * inv, oacc[j][2 * h2 + 1] * inv, p);
            int col = j * 8 + ((lane & 3) << 1);
            *(uint32_t*)(O + rp + col) = p;
        }
    }
}

// ---------------- launch ------------------------------------------------------
extern "C" void kernel_launch(void* const* d_in, const int* in_sizes, int n_in,
                              void* d_out, int out_size) {
    const float* x    = (const float*)d_in[0];
    const float* enc  = (const float*)d_in[1];
    const float* ln1g = (const float*)d_in[2];
    const float* ln1b = (const float*)d_in[3];
    const float* ln2g = (const float*)d_in[4];
    const float* ln2b = (const float*)d_in[5];
    const float* ln3g = (const float*)d_in[6];
    const float* ln3b = (const float*)d_in[7];
    const float* Wq1  = (const float*)d_in[8];
    const float* bq1  = (const float*)d_in[9];
    const float* Wk1  = (const float*)d_in[10];
    const float* bk1  = (const float*)d_in[11];
    const float* Wv1  = (const float*)d_in[12];
    const float* bv1  = (const float*)d_in[13];
    const float* Wo1  = (const float*)d_in[14];
    const float* bo1  = (const float*)d_in[15];
    const float* Wq2  = (const float*)d_in[16];
    const float* bq2  = (const float*)d_in[17];
    const float* Wk2  = (const float*)d_in[18];
    const float* bk2  = (const float*)d_in[19];
    const float* Wv2  = (const float*)d_in[20];
    const float* bv2  = (const float*)d_in[21];
    const float* Wo2  = (const float*)d_in[22];
    const float* bo2  = (const float*)d_in[23];
    const float* Wup  = (const float*)d_in[24];
    const float* bup  = (const float*)d_in[25];
    const float* Wdn  = (const float*)d_in[26];
    const float* bdn  = (const float*)d_in[27];
    float* out = (float*)d_out;

    half *W16, *h16, *e16, *q16, *kh16, *kl16, *v16, *a16;
    float *x1, *x2;
    cudaGetSymbolAddress((void**)&W16,  g_W16);
    cudaGetSymbolAddress((void**)&h16,  g_h16);
    cudaGetSymbolAddress((void**)&e16,  g_e16);
    cudaGetSymbolAddress((void**)&q16,  g_q16);
    cudaGetSymbolAddress((void**)&kh16, g_kh16);
    cudaGetSymbolAddress((void**)&kl16, g_kl16);
    cudaGetSymbolAddress((void**)&v16,  g_v16);
    cudaGetSymbolAddress((void**)&a16,  g_a16);
    cudaGetSymbolAddress((void**)&x1,   g_x1);
    cudaGetSymbolAddress((void**)&x2,   g_x2);

    cudaFuncSetAttribute(gemm16<0>, cudaFuncAttributeMaxDynamicSharedMemorySize, G16_SMEM);
    cudaFuncSetAttribute(gemm16<1>, cudaFuncAttributeMaxDynamicSharedMemorySize, G16_SMEM);
    cudaFuncSetAttribute(gemm16<2>, cudaFuncAttributeMaxDynamicSharedMemorySize, G16_SMEM);
    cudaFuncSetAttribute(gemm_qkv<0>, cudaFuncAttributeMaxDynamicSharedMemorySize, G16_SMEM);
    cudaFuncSetAttribute(gemm_qkv<1>, cudaFuncAttributeMaxDynamicSharedMemorySize, G16_SMEM);
    cudaFuncSetAttribute(attn16<true>,  cudaFuncAttributeMaxDynamicSharedMemorySize, ATTN_SMEM);
    cudaFuncSetAttribute(attn16<false>, cudaFuncAttributeMaxDynamicSharedMemorySize, ATTN_SMEM);

    // Side stream + events for weight-prep overlap (created once; reused across
    // calls — pure host-side handles, no device work or allocation semantics).
    static cudaStream_t sPrep = nullptr;
    static cudaEvent_t eFork, eQKVW, eEnc, eWo1, eWo2, eWup, eWdn;
    if (sPrep == nullptr) {
        cudaStreamCreateWithFlags(&sPrep, cudaStreamNonBlocking);
        cudaEventCreateWithFlags(&eFork, cudaEventDisableTiming);
        cudaEventCreateWithFlags(&eQKVW, cudaEventDisableTiming);
        cudaEventCreateWithFlags(&eEnc,  cudaEventDisableTiming);
        cudaEventCreateWithFlags(&eWo1,  cudaEventDisableTiming);
        cudaEventCreateWithFlags(&eWo2,  cudaEventDisableTiming);
        cudaEventCreateWithFlags(&eWup,  cudaEventDisableTiming);
        cudaEventCreateWithFlags(&eWdn,  cudaEventDisableTiming);
    }

    const int WS = E_DIM * E_DIM;
    dim3 gSq(8, 32);
    dim3 gUp(32, 32);
    dim3 gQKV(24, 32);
    dim3 gKV(16, 32);
    dim3 gAttn(S_LEN / 64, H_NUM, B_NUM);
    dim3 trB(32, 8);

    // ---- fork prep stream ----
    cudaEventRecord(eFork, 0);
    cudaStreamWaitEvent(sPrep, eFork, 0);
    wqkv_cvt_all<<<dim3(2, 32, 96), 256, 0, sPrep>>>(Wq1, Wk1, Wv1, Wq2, Wk2, Wv2, W16);
    cudaEventRecord(eQKVW, sPrep);
    wt_cvt16<<<dim3(32, 32), trB, 0, sPrep>>>(Wo1, W16 + 6 * WS, 1024, 1024);
    cudaEventRecord(eWo1, sPrep);
    cvt16<<<4096, 256, 0, sPrep>>>(enc, e16);
    cudaEventRecord(eEnc, sPrep);
    wt_cvt16<<<dim3(32, 32), trB, 0, sPrep>>>(Wo2, W16 + 7 * WS, 1024, 1024);
    cudaEventRecord(eWo2, sPrep);
    wt_cvt16<<<dim3(128, 32), trB, 0, sPrep>>>(Wup, W16 + 8 * WS, 1024, 4096);
    cudaEventRecord(eWup, sPrep);
    wt_cvt16<<<dim3(32, 128), trB, 0, sPrep>>>(Wdn, W16 + 12 * WS, 4096, 1024);
    cudaEventRecord(eWdn, sPrep);

    // ---- main chain ----
    ln_kernel<<<M_ROWS, 256>>>(x, ln1g, ln1b, h16);
    cudaStreamWaitEvent(0, eQKVW, 0);
    gemm_qkv<0><<<gQKV, 128, G16_SMEM>>>(h16, W16, bq1, bk1, bv1,
                                         q16, kh16, kl16, v16, M_ROWS, E_DIM);
    attn16<true><<<gAttn, 128, ATTN_SMEM>>>(q16, kh16, kl16, v16, a16);
    cudaStreamWaitEvent(0, eWo1, 0);
    gemm16<2><<<gSq, 128, G16_SMEM>>>(a16, W16 + 6 * WS, bo1, x,
                                      x1, nullptr, M_ROWS, E_DIM, E_DIM);

    ln_kernel<<<M_ROWS, 256>>>(x1, ln2g, ln2b, h16);
    gemm16<0><<<gSq, 128, G16_SMEM>>>(h16, W16 + 3 * WS, bq2, nullptr,
                                      nullptr, q16, M_ROWS, E_DIM, E_DIM);
    cudaStreamWaitEvent(0, eEnc, 0);
    gemm_qkv<1><<<gKV, 128, G16_SMEM>>>(e16, W16 + 4 * WS, nullptr, bk2, bv2,
                                        nullptr, kh16, kl16, v16, M_ROWS, E_DIM);
    attn16<false><<<gAttn, 128, ATTN_SMEM>>>(q16, kh16, kl16, v16, a16);
    cudaStreamWaitEvent(0, eWo2, 0);
    gemm16<2><<<gSq, 128, G16_SMEM>>>(a16, W16 + 7 * WS, bo2, x1,
                                      x2, nullptr, M_ROWS, E_DIM, E_DIM);

    ln_kernel<<<M_ROWS, 256>>>(x2, ln3g, ln3b, h16);
    cudaStreamWaitEvent(0, eWup, 0);
    gemm16<1><<<gUp, 128, G16_SMEM>>>(h16, W16 + 8 * WS, bup, nullptr,
                                      nullptr, a16, M_ROWS, F_DIM, E_DIM);
    cudaStreamWaitEvent(0, eWdn, 0);
    gemm16<2><<<gSq, 128, G16_SMEM>>>(a16, W16 + 12 * WS, bdn, x2,
                                      out, nullptr, M_ROWS, E_DIM, F_DIM);
}

// round 11
// speedup vs baseline: 6.6350x; 1.0398x over previous
#include <cuda_runtime.h>
#include <cuda_fp16.h>
#include <math.h>
#include <cstdint>

#define E_DIM 1024
#define H_NUM 16
#define D_DIM 64
#define B_NUM 4
#define S_LEN 1024
#define F_DIM 4096
#define M_ROWS (B_NUM * S_LEN)  // 4096
#define MB1 (1024 * 1024)

// ---------------- scratch (static device globals) ---------------------------
// Weight slots (single fp16, [N][K] transposed): QKV1 0-2, QKV2 3-5, Wo1 6, Wo2 7,
// Wup 8-11, Wdn 12-15.
__device__ __align__(16) half g_W16[16 * MB1];
__device__ __align__(16) half g_h16[4 * MB1];          // LN out
__device__ __align__(16) half g_e16[4 * MB1];          // enc
__device__ __align__(16) half g_q16[4 * MB1];          // Q (single)
__device__ __align__(16) half g_kh16[4 * MB1], g_kl16[4 * MB1];  // K1 hi/lo
__device__ __align__(16) half g_v16[4 * MB1];          // V1 (single)
__device__ __align__(16) half g_kh2[4 * MB1], g_kl2[4 * MB1];    // K2 hi/lo
__device__ __align__(16) half g_v2[4 * MB1];           // V2 (single)
__device__ __align__(16) half g_a16[16 * MB1];         // attn out / GELU out
__device__ __align__(16) float g_x1[4 * MB1], g_x2[4 * MB1];

// ---------------- PTX helpers -----------------------------------------------
__device__ __forceinline__ uint32_t smem_u32(const void* p) {
    uint32_t a;
    asm("{ .reg .u64 t; cvta.to.shared.u64 t, %1; cvt.u32.u64 %0, t; }" : "=r"(a) : "l"(p));
    return a;
}
__device__ __forceinline__ void cpasync16(uint32_t dst, const void* src) {
    asm volatile("cp.async.cg.shared.global [%0], [%1], 16;" :: "r"(dst), "l"(src));
}
__device__ __forceinline__ void cpcommit() { asm volatile("cp.async.commit_group;" ::: "memory"); }
template <int N>
__device__ __forceinline__ void cpwait() { asm volatile("cp.async.wait_group %0;" :: "n"(N) : "memory"); }

__device__ __forceinline__ void ldsm4(uint32_t (&r)[4], uint32_t addr) {
    asm volatile("ldmatrix.sync.aligned.m8n8.x4.shared.b16 {%0,%1,%2,%3}, [%4];"
                 : "=r"(r[0]), "=r"(r[1]), "=r"(r[2]), "=r"(r[3]) : "r"(addr));
}
__device__ __forceinline__ void ldsm4t(uint32_t (&r)[4], uint32_t addr) {
    asm volatile("ldmatrix.sync.aligned.m8n8.x4.trans.shared.b16 {%0,%1,%2,%3}, [%4];"
                 : "=r"(r[0]), "=r"(r[1]), "=r"(r[2]), "=r"(r[3]) : "r"(addr));
}
__device__ __forceinline__ void mma16816h(float (&d)[4], const uint32_t (&a)[4],
                                          const uint32_t (&b)[2]) {
    asm volatile(
        "mma.sync.aligned.m16n8k16.row.col.f32.f16.f16.f32 "
        "{%0,%1,%2,%3}, {%4,%5,%6,%7}, {%8,%9}, {%0,%1,%2,%3};"
        : "+f"(d[0]), "+f"(d[1]), "+f"(d[2]), "+f"(d[3])
        : "r"(a[0]), "r"(a[1]), "r"(a[2]), "r"(a[3]), "r"(b[0]), "r"(b[1]));
}
__device__ __forceinline__ uint32_t swz128(uint32_t o) { return o ^ ((o >> 3) & 0x70); }

__device__ __forceinline__ void h_split(float v, half& hi, half& lo) {
    hi = __float2half_rn(v);
    lo = __float2half_rn(v - __half2float(hi));
}
__device__ __forceinline__ void packh2(float a, float b, uint32_t& r) {
    half2 p; p.x = __float2half_rn(a); p.y = __float2half_rn(b);
    r = *(uint32_t*)&p;
}
__device__ __forceinline__ void packsplit16(float a, float b, uint32_t& hi, uint32_t& lo) {
    half ah, al, bh, bl;
    h_split(a, ah, al); h_split(b, bh, bl);
    half2 hp, lp;
    hp.x = ah; hp.y = bh; lp.x = al; lp.y = bl;
    hi = *(uint32_t*)&hp; lo = *(uint32_t*)&lp;
}

// ---------------- weight prep -------------------------------------------------
// 3 QKV weights: [H,E,D] -> Bt[n=h*64+d][k=e], single fp16 (3 consecutive slots).
__global__ void __launch_bounds__(256) wqkv_cvt3(
    const float* __restrict__ w0, const float* __restrict__ w1,
    const float* __restrict__ w2, half* __restrict__ o16) {
    __shared__ float tile[32][33];
    int dt = blockIdx.x;
    int et = blockIdx.y;
    int z  = blockIdx.z;            // s*16 + h, s in 0..2
    int s = z >> 4, h = z & 15;
    const float* src = (s == 0) ? w0 : (s == 1 ? w1 : w2);
    int tx = threadIdx.x & 31, ty = threadIdx.x >> 5;
    int e0 = et * 32, d0 = dt * 32;
    #pragma unroll
    for (int i = 0; i < 4; i++)
        tile[ty + 8 * i][tx] = src[h * (E_DIM * D_DIM) + (e0 + ty + 8 * i) * D_DIM + d0 + tx];
    __syncthreads();
    #pragma unroll
    for (int i = 0; i < 4; i++) {
        size_t oidx = (size_t)s * MB1 + (size_t)(h * 64 + d0 + ty + 8 * i) * E_DIM + e0 + tx;
        o16[oidx] = __float2half_rn(tile[tx][ty + 8 * i]);
    }
}
// [K,N] row-major -> Bt[n][k], single fp16
__global__ void wt_cvt16(const float* __restrict__ src,
                         half* __restrict__ o16, int K, int N) {
    __shared__ float tile[32][33];
    int n0 = blockIdx.x * 32, k0 = blockIdx.y * 32;
    int tx = threadIdx.x, ty = threadIdx.y;
    #pragma unroll
    for (int i = 0; i < 4; i++)
        tile[ty + 8 * i][tx] = src[(size_t)(k0 + ty + 8 * i) * N + n0 + tx];
    __syncthreads();
    #pragma unroll
    for (int i = 0; i < 4; i++)
        o16[(size_t)(n0 + ty + 8 * i) * K + k0 + tx] = __float2half_rn(tile[tx][ty + 8 * i]);
}
// f32 -> single fp16
__global__ void cvt16(const float* __restrict__ src, half* __restrict__ dst) {
    int i = blockIdx.x * 256 + threadIdx.x;
    float4 v = ((const float4*)src)[i];
    uint32_t p0, p1;
    packh2(v.x, v.y, p0);
    packh2(v.z, v.w, p1);
    *(uint32_t*)(dst + 4 * (size_t)i) = p0;
    *(uint32_t*)(dst + 4 * (size_t)i + 2) = p1;
}

// ---------------- LayerNorm: f32 -> single fp16 -------------------------------
__global__ void __launch_bounds__(256) ln_kernel(const float* __restrict__ x,
                                                 const float* __restrict__ g,
                                                 const float* __restrict__ b,
                                                 half* __restrict__ o16) {
    int row = blockIdx.x;
    int t = threadIdx.x;
    float4 v = ((const float4*)(x + (size_t)row * E_DIM))[t];
    float s = v.x + v.y + v.z + v.w;
    float ss = v.x * v.x + v.y * v.y + v.z * v.z + v.w * v.w;
    #pragma unroll
    for (int o = 16; o > 0; o >>= 1) {
        s  += __shfl_xor_sync(0xffffffffu, s, o);
        ss += __shfl_xor_sync(0xffffffffu, ss, o);
    }
    __shared__ float red[2][8];
    int w = t >> 5, lane = t & 31;
    if (lane == 0) { red[0][w] = s; red[1][w] = ss; }
    __syncthreads();
    s = 0.0f; ss = 0.0f;
    #pragma unroll
    for (int i = 0; i < 8; i++) { s += red[0][i]; ss += red[1][i]; }
    float mu  = s * (1.0f / E_DIM);
    float var = ss * (1.0f / E_DIM) - mu * mu;
    float inv = rsqrtf(var + 1e-5f);
    float4 gv = ((const float4*)g)[t];
    float4 bv = ((const float4*)b)[t];
    float o0 = (v.x - mu) * inv * gv.x + bv.x;
    float o1 = (v.y - mu) * inv * gv.y + bv.y;
    float o2 = (v.z - mu) * inv * gv.z + bv.z;
    float o3 = (v.w - mu) * inv * gv.w + bv.w;
    size_t base = (size_t)row * E_DIM + t * 4;
    uint32_t p0, p1;
    packh2(o0, o1, p0);
    packh2(o2, o3, p1);
    *(uint32_t*)(o16 + base) = p0;
    *(uint32_t*)(o16 + base + 2) = p1;
}

#define G16_STAGE 32768
#define G16_SMEM (2 * G16_STAGE + 256)

// ---------------- fp16 GEMM (single x single) ----------------------------------
// EPI: 0 bias -> fp16 single, 1 bias+GELU -> fp16, 2 bias+res -> f32
template <int EPI>
__global__ void __launch_bounds__(128, 2) gemm16(
    const half* __restrict__ A, const half* __restrict__ B,
    const float* __restrict__ bias, const float* __restrict__ res,
    float* __restrict__ outF, half* __restrict__ outH,
    int M, int N, int K) {
    extern __shared__ char dyn[];
    uint32_t sb = (smem_u32(dyn) + 127) & ~127u;
    int tid = threadIdx.x, lane = tid & 31, wid = tid >> 5;
    int rBase = blockIdx.y * 128, cBase = blockIdx.x * 128;
    int m0 = (wid >> 1) * 64, n0 = (wid & 1) * 64;

    float acc[4][8][4];
    #pragma unroll
    for (int i = 0; i < 4; i++)
        #pragma unroll
        for (int j = 0; j < 8; j++)
            #pragma unroll
            for (int u = 0; u < 4; u++) acc[i][j][u] = 0.0f;

    const int nc = K >> 6;
    auto loadStage = [&](int s, int c) {
        uint32_t base = sb + s * G16_STAGE;
        int k0 = c << 6;
        #pragma unroll
        for (int i = 0; i < 8; i++) {
            int idx = i * 128 + tid;
            int row = idx >> 3, c16 = idx & 7;
            uint32_t off = swz128(row * 128 + c16 * 16);
            cpasync16(base + off,         A + (size_t)(rBase + row) * K + k0 + c16 * 8);
            cpasync16(base + 16384 + off, B + (size_t)(cBase + row) * K + k0 + c16 * 8);
        }
    };

    int aRow = (lane & 7) + ((lane >> 3) & 1) * 8;
    int aC   = lane >> 4;
    int bRow16 = (lane & 7) + ((lane >> 4) & 1) * 8;
    int bH     = (lane >> 3) & 1;

    loadStage(0, 0); cpcommit();

    for (int c = 0; c < nc; c++) {
        if (c + 1 < nc) { loadStage((c + 1) & 1, c + 1); cpcommit(); cpwait<1>(); }
        else            { cpwait<0>(); }
        __syncthreads();
        uint32_t base = sb + (c & 1) * G16_STAGE;
        #pragma unroll
        for (int kc = 0; kc < 4; kc++) {
            uint32_t bh[8][2];
            #pragma unroll
            for (int jp = 0; jp < 4; jp++) {
                int row = n0 + jp * 16 + bRow16;
                uint32_t t4[4];
                ldsm4(t4, base + 16384 + swz128(row * 128 + kc * 32 + bH * 16));
                bh[2 * jp][0] = t4[0]; bh[2 * jp][1] = t4[1];
                bh[2 * jp + 1][0] = t4[2]; bh[2 * jp + 1][1] = t4[3];
            }
            #pragma unroll
            for (int i = 0; i < 4; i++) {
                uint32_t a4[4];
                int row = m0 + i * 16 + aRow;
                ldsm4(a4, base + swz128(row * 128 + kc * 32 + aC * 16));
                #pragma unroll
                for (int j = 0; j < 8; j++)
                    mma16816h(acc[i][j], a4, bh[j]);
            }
        }
        __syncthreads();
    }

    int lr = lane >> 2, lc = (lane & 3) << 1;
    #pragma unroll
    for (int i = 0; i < 4; i++) {
        #pragma unroll
        for (int half_ = 0; half_ < 2; half_++) {
            size_t row = (size_t)(rBase + m0 + i * 16 + lr + half_ * 8);
            #pragma unroll
            for (int j = 0; j < 8; j++) {
                int col = cBase + n0 + j * 8 + lc;
                float v0 = acc[i][j][half_ * 2 + 0] + bias[col];
                float v1 = acc[i][j][half_ * 2 + 1] + bias[col + 1];
                if (EPI == 0) {
                    uint32_t p;
                    packh2(v0, v1, p);
                    *(uint32_t*)(outH + row * N + col) = p;
                } else if (EPI == 1) {
                    v0 = 0.5f * v0 * (1.0f + erff(v0 * 0.70710678118654752f));
                    v1 = 0.5f * v1 * (1.0f + erff(v1 * 0.70710678118654752f));
                    uint32_t p;
                    packh2(v0, v1, p);
                    *(uint32_t*)(outH + row * N + col) = p;
                } else {
                    float2 rv = *(const float2*)(res + row * N + col);
                    float2 o; o.x = v0 + rv.x; o.y = v1 + rv.y;
                    *(float2*)(outF + row * N + col) = o;
                }
            }
        }
    }
}

// ---------------- fused QKV / KV projection GEMM -------------------------------
// MODE 0 (N=3072): region 0 -> single o0 (Q), region 1 -> hi/lo o1h/o1l (K),
//                  region 2 -> single o2 (V)
// MODE 1 (N=2048): region 0 -> hi/lo o1h/o1l (K), region 1 -> single o2 (V)
template <int MODE>
__global__ void __launch_bounds__(128, 2) gemm_qkv(
    const half* __restrict__ A, const half* __restrict__ B,
    const float* __restrict__ b0, const float* __restrict__ b1,
    const float* __restrict__ b2,
    half* __restrict__ o0, half* __restrict__ o1h, half* __restrict__ o1l,
    half* __restrict__ o2, int M, int K) {
    extern __shared__ char dyn[];
    uint32_t sb = (smem_u32(dyn) + 127) & ~127u;
    int tid = threadIdx.x, lane = tid & 31, wid = tid >> 5;
    int rBase = blockIdx.y * 128, cBase = blockIdx.x * 128;
    int m0 = (wid >> 1) * 64, n0 = (wid & 1) * 64;

    float acc[4][8][4];
    #pragma unroll
    for (int i = 0; i < 4; i++)
        #pragma unroll
        for (int j = 0; j < 8; j++)
            #pragma unroll
            for (int u = 0; u < 4; u++) acc[i][j][u] = 0.0f;

    const int nc = K >> 6;
    auto loadStage = [&](int s, int c) {
        uint32_t base = sb + s * G16_STAGE;
        int k0 = c << 6;
        #pragma unroll
        for (int i = 0; i < 8; i++) {
            int idx = i * 128 + tid;
            int row = idx >> 3, c16 = idx & 7;
            uint32_t off = swz128(row * 128 + c16 * 16);
            cpasync16(base + off,         A + (size_t)(rBase + row) * K + k0 + c16 * 8);
            cpasync16(base + 16384 + off, B + (size_t)(cBase + row) * K + k0 + c16 * 8);
        }
    };

    int aRow = (lane & 7) + ((lane >> 3) & 1) * 8;
    int aC   = lane >> 4;
    int bRow16 = (lane & 7) + ((lane >> 4) & 1) * 8;
    int bH     = (lane >> 3) & 1;

    loadStage(0, 0); cpcommit();

    for (int c = 0; c < nc; c++) {
        if (c + 1 < nc) { loadStage((c + 1) & 1, c + 1); cpcommit(); cpwait<1>(); }
        else            { cpwait<0>(); }
        __syncthreads();
        uint32_t base = sb + (c & 1) * G16_STAGE;
        #pragma unroll
        for (int kc = 0; kc < 4; kc++) {
            uint32_t bh[8][2];
            #pragma unroll
            for (int jp = 0; jp < 4; jp++) {
                int row = n0 + jp * 16 + bRow16;
                uint32_t t4[4];
                ldsm4(t4, base + 16384 + swz128(row * 128 + kc * 32 + bH * 16));
                bh[2 * jp][0] = t4[0]; bh[2 * jp][1] = t4[1];
                bh[2 * jp + 1][0] = t4[2]; bh[2 * jp + 1][1] = t4[3];
            }
            #pragma unroll
            for (int i = 0; i < 4; i++) {
                uint32_t a4[4];
                int row = m0 + i * 16 + aRow;
                ldsm4(a4, base + swz128(row * 128 + kc * 32 + aC * 16));
                #pragma unroll
                for (int j = 0; j < 8; j++)
                    mma16816h(acc[i][j], a4, bh[j]);
            }
        }
        __syncthreads();
    }

    int region = cBase >> 10;
    int cLoc = (cBase & 1023) + n0;
    const float* bias = (MODE == 0)
        ? (region == 0 ? b0 : (region == 1 ? b1 : b2))
        : (region == 0 ? b1 : b2);
    bool hilo = (MODE == 0) ? (region == 1) : (region == 0);
    half* outS = (MODE == 0) ? (region == 0 ? o0 : o2) : o2;

    int lr = lane >> 2, lc = (lane & 3) << 1;
    #pragma unroll
    for (int i = 0; i < 4; i++) {
        #pragma unroll
        for (int half_ = 0; half_ < 2; half_++) {
            size_t row = (size_t)(rBase + m0 + i * 16 + lr + half_ * 8);
            #pragma unroll
            for (int j = 0; j < 8; j++) {
                int col = cLoc + j * 8 + lc;
                float v0 = acc[i][j][half_ * 2 + 0] + bias[col];
                float v1 = acc[i][j][half_ * 2 + 1] + bias[col + 1];
                if (hilo) {
                    uint32_t hp, lp;
                    packsplit16(v0, v1, hp, lp);
                    *(uint32_t*)(o1h + row * E_DIM + col) = hp;
                    *(uint32_t*)(o1l + row * E_DIM + col) = lp;
                } else {
                    uint32_t p;
                    packh2(v0, v1, p);
                    *(uint32_t*)(outS + row * E_DIM + col) = p;
                }
            }
        }
    }
}

// ---------------- flash attention (D=64): Q,P,V single; K hi/lo ---------------
#define ATTN_SMEM (8192 + 2 * 24576 + 1024)
template <bool CAUSAL>
__global__ void __launch_bounds__(128, 2) attn16(
    const half* __restrict__ Q,
    const half* __restrict__ Kh, const half* __restrict__ Kl,
    const half* __restrict__ V,
    half* __restrict__ O) {
    extern __shared__ char dyn[];
    uint32_t sb = (smem_u32(dyn) + 1023) & ~1023u;
    int tid = threadIdx.x, lane = tid & 31, w = tid >> 5;
    int b = blockIdx.z, hh = blockIdx.y, qt = blockIdx.x;
    size_t headOff = (size_t)hh * D_DIM;
    size_t tokBase = (size_t)b * S_LEN;

    int aRow = (lane & 7) + ((lane >> 3) & 1) * 8;
    int aC = lane >> 4;

    {
        #pragma unroll
        for (int i = 0; i < 4; i++) {
            int idx = i * 128 + tid;
            int r = idx >> 3, c = idx & 7;
            uint32_t off = swz128(r * 128 + c * 16);
            cpasync16(sb + off, Q + (tokBase + qt * 64 + r) * E_DIM + headOff + c * 8);
        }
    }
    auto loadKV = [&](int s, int kt) {
        uint32_t base = sb + 8192 + s * 24576;
        #pragma unroll
        for (int i = 0; i < 4; i++) {
            int idx = i * 128 + tid;
            int r = idx >> 3, c = idx & 7;
            uint32_t off = swz128(r * 128 + c * 16);
            size_t src = (tokBase + kt * 64 + r) * E_DIM + headOff + c * 8;
            cpasync16(base + off,         Kh + src);
            cpasync16(base + 8192 + off,  Kl + src);
            cpasync16(base + 16384 + off, V + src);
        }
    };
    loadKV(0, 0);
    cpcommit();

    uint32_t qf[4][4];
    float oacc[8][4];
    float mrow[2] = {-1e30f, -1e30f}, lrow[2] = {0.0f, 0.0f};
    #pragma unroll
    for (int j = 0; j < 8; j++)
        #pragma unroll
        for (int u = 0; u < 4; u++) oacc[j][u] = 0.0f;

    const int ntiles = CAUSAL ? (qt + 1) : (S_LEN / 64);
    for (int kt = 0; kt < ntiles; kt++) {
        if (kt + 1 < ntiles) { loadKV((kt + 1) & 1, kt + 1); cpcommit(); cpwait<1>(); }
        else                 { cpwait<0>(); }
        __syncthreads();
        if (kt == 0) {
            #pragma unroll
            for (int s = 0; s < 4; s++)
                ldsm4(qf[s], sb + swz128((w * 16 + aRow) * 128 + s * 32 + aC * 16));
        }
        uint32_t kb = sb + 8192 + (kt & 1) * 24576;
        uint32_t vb = kb + 16384;

        float sacc[8][4];
        #pragma unroll
        for (int j = 0; j < 8; j++)
            #pragma unroll
            for (int u = 0; u < 4; u++) sacc[j][u] = 0.0f;
        #pragma unroll
        for (int s = 0; s < 4; s++) {
            #pragma unroll
            for (int jp = 0; jp < 4; jp++) {
                uint32_t addr = kb + swz128((jp * 16 + aRow) * 128 + s * 32 + aC * 16);
                uint32_t kh4[4], kl4[4];
                ldsm4(kh4, addr);
                ldsm4(kl4, addr + 8192);
                uint32_t b0h[2] = {kh4[0], kh4[2]}, b1h[2] = {kh4[1], kh4[3]};
                uint32_t b0l[2] = {kl4[0], kl4[2]}, b1l[2] = {kl4[1], kl4[3]};
                mma16816h(sacc[2 * jp],     qf[s], b0h);
                mma16816h(sacc[2 * jp],     qf[s], b0l);
                mma16816h(sacc[2 * jp + 1], qf[s], b1h);
                mma16816h(sacc[2 * jp + 1], qf[s], b1l);
            }
        }

        if (CAUSAL && kt == qt) {
            int ql0 = w * 16 + (lane >> 2);
            #pragma unroll
            for (int j = 0; j < 8; j++)
                #pragma unroll
                for (int u = 0; u < 4; u++) {
                    int kcol = j * 8 + ((lane & 3) << 1) + (u & 1);
                    int qrow = ql0 + (u >> 1) * 8;
                    if (kcol > qrow) sacc[j][u] = -1e30f;
                }
        }

        #pragma unroll
        for (int h2 = 0; h2 < 2; h2++) {
            float mt = -1e30f;
            #pragma unroll
            for (int j = 0; j < 8; j++)
                mt = fmaxf(mt, fmaxf(sacc[j][2 * h2], sacc[j][2 * h2 + 1]));
            mt = fmaxf(mt, __shfl_xor_sync(0xffffffffu, mt, 1));
            mt = fmaxf(mt, __shfl_xor_sync(0xffffffffu, mt, 2));
            float mn = fmaxf(mrow[h2], mt);
            float sc = __expf(mrow[h2] - mn);
            mrow[h2] = mn;
            float ts = 0.0f;
            #pragma unroll
            for (int j = 0; j < 8; j++) {
                sacc[j][2 * h2]     = __expf(sacc[j][2 * h2] - mn);
                sacc[j][2 * h2 + 1] = __expf(sacc[j][2 * h2 + 1] - mn);
                ts += sacc[j][2 * h2] + sacc[j][2 * h2 + 1];
            }
            ts += __shfl_xor_sync(0xffffffffu, ts, 1);
            ts += __shfl_xor_sync(0xffffffffu, ts, 2);
            lrow[h2] = lrow[h2] * sc + ts;
            #pragma unroll
            for (int j = 0; j < 8; j++) {
                oacc[j][2 * h2]     *= sc;
                oacc[j][2 * h2 + 1] *= sc;
            }
        }

        #pragma unroll
        for (int s = 0; s < 4; s++) {
            uint32_t pf[4];
            packh2(sacc[2 * s][0],     sacc[2 * s][1],     pf[0]);
            packh2(sacc[2 * s][2],     sacc[2 * s][3],     pf[1]);
            packh2(sacc[2 * s + 1][0], sacc[2 * s + 1][1], pf[2]);
            packh2(sacc[2 * s + 1][2], sacc[2 * s + 1][3], pf[3]);
            #pragma unroll
            for (int jp = 0; jp < 4; jp++) {
                uint32_t vh4[4];
                ldsm4t(vh4, vb + swz128((s * 16 + aRow) * 128 + jp * 32 + aC * 16));
                uint32_t b0h[2] = {vh4[0], vh4[1]}, b1h[2] = {vh4[2], vh4[3]};
                mma16816h(oacc[2 * jp],     pf, b0h);
                mma16816h(oacc[2 * jp + 1], pf, b1h);
            }
        }
        __syncthreads();
    }

    #pragma unroll
    for (int h2 = 0; h2 < 2; h2++) {
        float inv = 1.0f / lrow[h2];
        int trow = qt * 64 + w * 16 + (lane >> 2) + h2 * 8;
        size_t rp = (tokBase + trow) * E_DIM + headOff;
        #pragma unroll
        for (int j = 0; j < 8; j++) {
            uint32_t p;
            packh2(oacc[j][2 * h2] * inv, oacc[j][2 * h2 + 1] * inv, p);
            int col = j * 8 + ((lane & 3) << 1);
            *(uint32_t*)(O + rp + col) = p;
        }
    }
}

// ---------------- launch ------------------------------------------------------
extern "C" void kernel_launch(void* const* d_in, const int* in_sizes, int n_in,
                              void* d_out, int out_size) {
    const float* x    = (const float*)d_in[0];
    const float* enc  = (const float*)d_in[1];
    const float* ln1g = (const float*)d_in[2];
    const float* ln1b = (const float*)d_in[3];
    const float* ln2g = (const float*)d_in[4];
    const float* ln2b = (const float*)d_in[5];
    const float* ln3g = (const float*)d_in[6];
    const float* ln3b = (const float*)d_in[7];
    const float* Wq1  = (const float*)d_in[8];
    const float* bq1  = (const float*)d_in[9];
    const float* Wk1  = (const float*)d_in[10];
    const float* bk1  = (const float*)d_in[11];
    const float* Wv1  = (const float*)d_in[12];
    const float* bv1  = (const float*)d_in[13];
    const float* Wo1  = (const float*)d_in[14];
    const float* bo1  = (const float*)d_in[15];
    const float* Wq2  = (const float*)d_in[16];
    const float* bq2  = (const float*)d_in[17];
    const float* Wk2  = (const float*)d_in[18];
    const float* bk2  = (const float*)d_in[19];
    const float* Wv2  = (const float*)d_in[20];
    const float* bv2  = (const float*)d_in[21];
    const float* Wo2  = (const float*)d_in[22];
    const float* bo2  = (const float*)d_in[23];
    const float* Wup  = (const float*)d_in[24];
    const float* bup  = (const float*)d_in[25];
    const float* Wdn  = (const float*)d_in[26];
    const float* bdn  = (const float*)d_in[27];
    float* out = (float*)d_out;

    half *W16, *h16, *e16, *q16, *kh16, *kl16, *v16, *kh2, *kl2, *v2, *a16;
    float *x1, *x2;
    cudaGetSymbolAddress((void**)&W16,  g_W16);
    cudaGetSymbolAddress((void**)&h16,  g_h16);
    cudaGetSymbolAddress((void**)&e16,  g_e16);
    cudaGetSymbolAddress((void**)&q16,  g_q16);
    cudaGetSymbolAddress((void**)&kh16, g_kh16);
    cudaGetSymbolAddress((void**)&kl16, g_kl16);
    cudaGetSymbolAddress((void**)&v16,  g_v16);
    cudaGetSymbolAddress((void**)&kh2,  g_kh2);
    cudaGetSymbolAddress((void**)&kl2,  g_kl2);
    cudaGetSymbolAddress((void**)&v2,   g_v2);
    cudaGetSymbolAddress((void**)&a16,  g_a16);
    cudaGetSymbolAddress((void**)&x1,   g_x1);
    cudaGetSymbolAddress((void**)&x2,   g_x2);

    cudaFuncSetAttribute(gemm16<0>, cudaFuncAttributeMaxDynamicSharedMemorySize, G16_SMEM);
    cudaFuncSetAttribute(gemm16<1>, cudaFuncAttributeMaxDynamicSharedMemorySize, G16_SMEM);
    cudaFuncSetAttribute(gemm16<2>, cudaFuncAttributeMaxDynamicSharedMemorySize, G16_SMEM);
    cudaFuncSetAttribute(gemm_qkv<0>, cudaFuncAttributeMaxDynamicSharedMemorySize, G16_SMEM);
    cudaFuncSetAttribute(gemm_qkv<1>, cudaFuncAttributeMaxDynamicSharedMemorySize, G16_SMEM);
    cudaFuncSetAttribute(attn16<true>,  cudaFuncAttributeMaxDynamicSharedMemorySize, ATTN_SMEM);
    cudaFuncSetAttribute(attn16<false>, cudaFuncAttributeMaxDynamicSharedMemorySize, ATTN_SMEM);

    static cudaStream_t sPrep = nullptr;
    static cudaEvent_t eFork, eQKV1W, eQKV2W, eKV2, eWo1, eWo2, eWup, eWdn;
    if (sPrep == nullptr) {
        cudaStreamCreateWithFlags(&sPrep, cudaStreamNonBlocking);
        cudaEventCreateWithFlags(&eFork,  cudaEventDisableTiming);
        cudaEventCreateWithFlags(&eQKV1W, cudaEventDisableTiming);
        cudaEventCreateWithFlags(&eQKV2W, cudaEventDisableTiming);
        cudaEventCreateWithFlags(&eKV2,   cudaEventDisableTiming);
        cudaEventCreateWithFlags(&eWo1,   cudaEventDisableTiming);
        cudaEventCreateWithFlags(&eWo2,   cudaEventDisableTiming);
        cudaEventCreateWithFlags(&eWup,   cudaEventDisableTiming);
        cudaEventCreateWithFlags(&eWdn,   cudaEventDisableTiming);
    }

    const int WS = E_DIM * E_DIM;
    dim3 gSq(8, 32);
    dim3 gUp(32, 32);
    dim3 gQKV(24, 32);
    dim3 gKV(16, 32);
    dim3 gAttn(S_LEN / 64, H_NUM, B_NUM);
    dim3 trB(32, 8);

    // ---- fork prep stream ----
    cudaEventRecord(eFork, 0);
    cudaStreamWaitEvent(sPrep, eFork, 0);
    wqkv_cvt3<<<dim3(2, 32, 48), 256, 0, sPrep>>>(Wq1, Wk1, Wv1, W16);            // slots 0-2
    cudaEventRecord(eQKV1W, sPrep);
    wqkv_cvt3<<<dim3(2, 32, 48), 256, 0, sPrep>>>(Wq2, Wk2, Wv2, W16 + 3 * WS);   // slots 3-5
    cudaEventRecord(eQKV2W, sPrep);
    cvt16<<<4096, 256, 0, sPrep>>>(enc, e16);
    wt_cvt16<<<dim3(32, 32), trB, 0, sPrep>>>(Wo1, W16 + 6 * WS, 1024, 1024);
    cudaEventRecord(eWo1, sPrep);
    // KV2 projection — depends only on enc + slots 4-5; co-runs with block 1.
    gemm_qkv<1><<<gKV, 128, G16_SMEM, sPrep>>>(e16, W16 + 4 * WS, nullptr, bk2, bv2,
                                               nullptr, kh2, kl2, v2, M_ROWS, E_DIM);
    cudaEventRecord(eKV2, sPrep);
    wt_cvt16<<<dim3(32, 32), trB, 0, sPrep>>>(Wo2, W16 + 7 * WS, 1024, 1024);
    cudaEventRecord(eWo2, sPrep);
    wt_cvt16<<<dim3(128, 32), trB, 0, sPrep>>>(Wup, W16 + 8 * WS, 1024, 4096);
    cudaEventRecord(eWup, sPrep);
    wt_cvt16<<<dim3(32, 128), trB, 0, sPrep>>>(Wdn, W16 + 12 * WS, 4096, 1024);
    cudaEventRecord(eWdn, sPrep);

    // ---- main chain ----
    ln_kernel<<<M_ROWS, 256>>>(x, ln1g, ln1b, h16);
    cudaStreamWaitEvent(0, eQKV1W, 0);
    gemm_qkv<0><<<gQKV, 128, G16_SMEM>>>(h16, W16, bq1, bk1, bv1,
                                         q16, kh16, kl16, v16, M_ROWS, E_DIM);
    attn16<true><<<gAttn, 128, ATTN_SMEM>>>(q16, kh16, kl16, v16, a16);
    cudaStreamWaitEvent(0, eWo1, 0);
    gemm16<2><<<gSq, 128, G16_SMEM>>>(a16, W16 + 6 * WS, bo1, x,
                                      x1, nullptr, M_ROWS, E_DIM, E_DIM);

    ln_kernel<<<M_ROWS, 256>>>(x1, ln2g, ln2b, h16);
    cudaStreamWaitEvent(0, eQKV2W, 0);
    gemm16<0><<<gSq, 128, G16_SMEM>>>(h16, W16 + 3 * WS, bq2, nullptr,
                                      nullptr, q16, M_ROWS, E_DIM, E_DIM);
    cudaStreamWaitEvent(0, eKV2, 0);
    attn16<false><<<gAttn, 128, ATTN_SMEM>>>(q16, kh2, kl2, v2, a16);
    cudaStreamWaitEvent(0, eWo2, 0);
    gemm16<2><<<gSq, 128, G16_SMEM>>>(a16, W16 + 7 * WS, bo2, x1,
                                      x2, nullptr, M_ROWS, E_DIM, E_DIM);

    ln_kernel<<<M_ROWS, 256>>>(x2, ln3g, ln3b, h16);
    cudaStreamWaitEvent(0, eWup, 0);
    gemm16<1><<<gUp, 128, G16_SMEM>>>(h16, W16 + 8 * WS, bup, nullptr,
                                      nullptr, a16, M_ROWS, F_DIM, E_DIM);
    cudaStreamWaitEvent(0, eWdn, 0);
    gemm16<2><<<gSq, 128, G16_SMEM>>>(a16, W16 + 12 * WS, bdn, x2,
                                      out, nullptr, M_ROWS, E_DIM, F_DIM);
}

// round 12
// speedup vs baseline: 7.0508x; 1.0627x over previous
#include <cuda_runtime.h>
#include <cuda_fp16.h>
#include <math.h>
#include <cstdint>

#define E_DIM 1024
#define H_NUM 16
#define D_DIM 64
#define B_NUM 4
#define S_LEN 1024
#define F_DIM 4096
#define M_ROWS (B_NUM * S_LEN)  // 4096
#define MB1 (1024 * 1024)

// ---------------- scratch (static device globals) ---------------------------
// Weight slots (single fp16, [N][K] transposed): QKV1 0-2, QKV2 3-5, Wo1 6, Wo2 7,
// Wup 8-11, Wdn 12-15.
__device__ __align__(16) half g_W16[16 * MB1];
__device__ __align__(16) half g_h16[4 * MB1];          // LN out
__device__ __align__(16) half g_e16[4 * MB1];          // enc
__device__ __align__(16) half g_q16[4 * MB1];          // Q
__device__ __align__(16) half g_k16[4 * MB1];          // K1
__device__ __align__(16) half g_v16[4 * MB1];          // V1
__device__ __align__(16) half g_k2[4 * MB1];           // K2
__device__ __align__(16) half g_v2[4 * MB1];           // V2
__device__ __align__(16) half g_a16[16 * MB1];         // attn out / GELU out
__device__ __align__(16) float g_x1[4 * MB1], g_x2[4 * MB1];

// ---------------- PTX helpers -----------------------------------------------
__device__ __forceinline__ uint32_t smem_u32(const void* p) {
    uint32_t a;
    asm("{ .reg .u64 t; cvta.to.shared.u64 t, %1; cvt.u32.u64 %0, t; }" : "=r"(a) : "l"(p));
    return a;
}
__device__ __forceinline__ void cpasync16(uint32_t dst, const void* src) {
    asm volatile("cp.async.cg.shared.global [%0], [%1], 16;" :: "r"(dst), "l"(src));
}
__device__ __forceinline__ void cpcommit() { asm volatile("cp.async.commit_group;" ::: "memory"); }
template <int N>
__device__ __forceinline__ void cpwait() { asm volatile("cp.async.wait_group %0;" :: "n"(N) : "memory"); }

__device__ __forceinline__ void ldsm4(uint32_t (&r)[4], uint32_t addr) {
    asm volatile("ldmatrix.sync.aligned.m8n8.x4.shared.b16 {%0,%1,%2,%3}, [%4];"
                 : "=r"(r[0]), "=r"(r[1]), "=r"(r[2]), "=r"(r[3]) : "r"(addr));
}
__device__ __forceinline__ void ldsm4t(uint32_t (&r)[4], uint32_t addr) {
    asm volatile("ldmatrix.sync.aligned.m8n8.x4.trans.shared.b16 {%0,%1,%2,%3}, [%4];"
                 : "=r"(r[0]), "=r"(r[1]), "=r"(r[2]), "=r"(r[3]) : "r"(addr));
}
__device__ __forceinline__ void mma16816h(float (&d)[4], const uint32_t (&a)[4],
                                          const uint32_t (&b)[2]) {
    asm volatile(
        "mma.sync.aligned.m16n8k16.row.col.f32.f16.f16.f32 "
        "{%0,%1,%2,%3}, {%4,%5,%6,%7}, {%8,%9}, {%0,%1,%2,%3};"
        : "+f"(d[0]), "+f"(d[1]), "+f"(d[2]), "+f"(d[3])
        : "r"(a[0]), "r"(a[1]), "r"(a[2]), "r"(a[3]), "r"(b[0]), "r"(b[1]));
}
__device__ __forceinline__ uint32_t swz128(uint32_t o) { return o ^ ((o >> 3) & 0x70); }

__device__ __forceinline__ void packh2(float a, float b, uint32_t& r) {
    half2 p; p.x = __float2half_rn(a); p.y = __float2half_rn(b);
    r = *(uint32_t*)&p;
}

// ---------------- weight prep -------------------------------------------------
// 3 QKV weights: [H,E,D] -> Bt[n=h*64+d][k=e], single fp16 (3 consecutive slots).
__global__ void __launch_bounds__(256) wqkv_cvt3(
    const float* __restrict__ w0, const float* __restrict__ w1,
    const float* __restrict__ w2, half* __restrict__ o16) {
    __shared__ float tile[32][33];
    int dt = blockIdx.x;
    int et = blockIdx.y;
    int z  = blockIdx.z;            // s*16 + h, s in 0..2
    int s = z >> 4, h = z & 15;
    const float* src = (s == 0) ? w0 : (s == 1 ? w1 : w2);
    int tx = threadIdx.x & 31, ty = threadIdx.x >> 5;
    int e0 = et * 32, d0 = dt * 32;
    #pragma unroll
    for (int i = 0; i < 4; i++)
        tile[ty + 8 * i][tx] = src[h * (E_DIM * D_DIM) + (e0 + ty + 8 * i) * D_DIM + d0 + tx];
    __syncthreads();
    #pragma unroll
    for (int i = 0; i < 4; i++) {
        size_t oidx = (size_t)s * MB1 + (size_t)(h * 64 + d0 + ty + 8 * i) * E_DIM + e0 + tx;
        o16[oidx] = __float2half_rn(tile[tx][ty + 8 * i]);
    }
}
// [K,N] row-major -> Bt[n][k], single fp16
__global__ void wt_cvt16(const float* __restrict__ src,
                         half* __restrict__ o16, int K, int N) {
    __shared__ float tile[32][33];
    int n0 = blockIdx.x * 32, k0 = blockIdx.y * 32;
    int tx = threadIdx.x, ty = threadIdx.y;
    #pragma unroll
    for (int i = 0; i < 4; i++)
        tile[ty + 8 * i][tx] = src[(size_t)(k0 + ty + 8 * i) * N + n0 + tx];
    __syncthreads();
    #pragma unroll
    for (int i = 0; i < 4; i++)
        o16[(size_t)(n0 + ty + 8 * i) * K + k0 + tx] = __float2half_rn(tile[tx][ty + 8 * i]);
}
// f32 -> single fp16
__global__ void cvt16(const float* __restrict__ src, half* __restrict__ dst) {
    int i = blockIdx.x * 256 + threadIdx.x;
    float4 v = ((const float4*)src)[i];
    uint32_t p0, p1;
    packh2(v.x, v.y, p0);
    packh2(v.z, v.w, p1);
    *(uint32_t*)(dst + 4 * (size_t)i) = p0;
    *(uint32_t*)(dst + 4 * (size_t)i + 2) = p1;
}

// ---------------- LayerNorm: f32 -> single fp16 -------------------------------
__global__ void __launch_bounds__(256) ln_kernel(const float* __restrict__ x,
                                                 const float* __restrict__ g,
                                                 const float* __restrict__ b,
                                                 half* __restrict__ o16) {
    int row = blockIdx.x;
    int t = threadIdx.x;
    float4 v = ((const float4*)(x + (size_t)row * E_DIM))[t];
    float s = v.x + v.y + v.z + v.w;
    float ss = v.x * v.x + v.y * v.y + v.z * v.z + v.w * v.w;
    #pragma unroll
    for (int o = 16; o > 0; o >>= 1) {
        s  += __shfl_xor_sync(0xffffffffu, s, o);
        ss += __shfl_xor_sync(0xffffffffu, ss, o);
    }
    __shared__ float red[2][8];
    int w = t >> 5, lane = t & 31;
    if (lane == 0) { red[0][w] = s; red[1][w] = ss; }
    __syncthreads();
    s = 0.0f; ss = 0.0f;
    #pragma unroll
    for (int i = 0; i < 8; i++) { s += red[0][i]; ss += red[1][i]; }
    float mu  = s * (1.0f / E_DIM);
    float var = ss * (1.0f / E_DIM) - mu * mu;
    float inv = rsqrtf(var + 1e-5f);
    float4 gv = ((const float4*)g)[t];
    float4 bv = ((const float4*)b)[t];
    float o0 = (v.x - mu) * inv * gv.x + bv.x;
    float o1 = (v.y - mu) * inv * gv.y + bv.y;
    float o2 = (v.z - mu) * inv * gv.z + bv.z;
    float o3 = (v.w - mu) * inv * gv.w + bv.w;
    size_t base = (size_t)row * E_DIM + t * 4;
    uint32_t p0, p1;
    packh2(o0, o1, p0);
    packh2(o2, o3, p1);
    *(uint32_t*)(o16 + base) = p0;
    *(uint32_t*)(o16 + base + 2) = p1;
}

#define G16_STAGE 32768
#define G16_SMEM (2 * G16_STAGE + 256)

// ---------------- fp16 GEMM (single x single) ----------------------------------
// EPI: 0 bias -> fp16 single, 1 bias+GELU -> fp16, 2 bias+res -> f32
template <int EPI>
__global__ void __launch_bounds__(128, 2) gemm16(
    const half* __restrict__ A, const half* __restrict__ B,
    const float* __restrict__ bias, const float* __restrict__ res,
    float* __restrict__ outF, half* __restrict__ outH,
    int M, int N, int K) {
    extern __shared__ char dyn[];
    uint32_t sb = (smem_u32(dyn) + 127) & ~127u;
    int tid = threadIdx.x, lane = tid & 31, wid = tid >> 5;
    int rBase = blockIdx.y * 128, cBase = blockIdx.x * 128;
    int m0 = (wid >> 1) * 64, n0 = (wid & 1) * 64;

    float acc[4][8][4];
    #pragma unroll
    for (int i = 0; i < 4; i++)
        #pragma unroll
        for (int j = 0; j < 8; j++)
            #pragma unroll
            for (int u = 0; u < 4; u++) acc[i][j][u] = 0.0f;

    const int nc = K >> 6;
    auto loadStage = [&](int s, int c) {
        uint32_t base = sb + s * G16_STAGE;
        int k0 = c << 6;
        #pragma unroll
        for (int i = 0; i < 8; i++) {
            int idx = i * 128 + tid;
            int row = idx >> 3, c16 = idx & 7;
            uint32_t off = swz128(row * 128 + c16 * 16);
            cpasync16(base + off,         A + (size_t)(rBase + row) * K + k0 + c16 * 8);
            cpasync16(base + 16384 + off, B + (size_t)(cBase + row) * K + k0 + c16 * 8);
        }
    };

    int aRow = (lane & 7) + ((lane >> 3) & 1) * 8;
    int aC   = lane >> 4;
    int bRow16 = (lane & 7) + ((lane >> 4) & 1) * 8;
    int bH     = (lane >> 3) & 1;

    loadStage(0, 0); cpcommit();

    for (int c = 0; c < nc; c++) {
        if (c + 1 < nc) { loadStage((c + 1) & 1, c + 1); cpcommit(); cpwait<1>(); }
        else            { cpwait<0>(); }
        __syncthreads();
        uint32_t base = sb + (c & 1) * G16_STAGE;
        #pragma unroll
        for (int kc = 0; kc < 4; kc++) {
            uint32_t bh[8][2];
            #pragma unroll
            for (int jp = 0; jp < 4; jp++) {
                int row = n0 + jp * 16 + bRow16;
                uint32_t t4[4];
                ldsm4(t4, base + 16384 + swz128(row * 128 + kc * 32 + bH * 16));
                bh[2 * jp][0] = t4[0]; bh[2 * jp][1] = t4[1];
                bh[2 * jp + 1][0] = t4[2]; bh[2 * jp + 1][1] = t4[3];
            }
            #pragma unroll
            for (int i = 0; i < 4; i++) {
                uint32_t a4[4];
                int row = m0 + i * 16 + aRow;
                ldsm4(a4, base + swz128(row * 128 + kc * 32 + aC * 16));
                #pragma unroll
                for (int j = 0; j < 8; j++)
                    mma16816h(acc[i][j], a4, bh[j]);
            }
        }
        __syncthreads();
    }

    int lr = lane >> 2, lc = (lane & 3) << 1;
    #pragma unroll
    for (int i = 0; i < 4; i++) {
        #pragma unroll
        for (int half_ = 0; half_ < 2; half_++) {
            size_t row = (size_t)(rBase + m0 + i * 16 + lr + half_ * 8);
            #pragma unroll
            for (int j = 0; j < 8; j++) {
                int col = cBase + n0 + j * 8 + lc;
                float v0 = acc[i][j][half_ * 2 + 0] + bias[col];
                float v1 = acc[i][j][half_ * 2 + 1] + bias[col + 1];
                if (EPI == 0) {
                    uint32_t p;
                    packh2(v0, v1, p);
                    *(uint32_t*)(outH + row * N + col) = p;
                } else if (EPI == 1) {
                    v0 = 0.5f * v0 * (1.0f + erff(v0 * 0.70710678118654752f));
                    v1 = 0.5f * v1 * (1.0f + erff(v1 * 0.70710678118654752f));
                    uint32_t p;
                    packh2(v0, v1, p);
                    *(uint32_t*)(outH + row * N + col) = p;
                } else {
                    float2 rv = *(const float2*)(res + row * N + col);
                    float2 o; o.x = v0 + rv.x; o.y = v1 + rv.y;
                    *(float2*)(outF + row * N + col) = o;
                }
            }
        }
    }
}

// ---------------- fused QKV / KV projection GEMM -------------------------------
// MODE 0 (N=3072): region r -> out[r] with bias[r]  (Q, K, V — all single fp16)
// MODE 1 (N=2048): region 0 -> o1/b1 (K), region 1 -> o2/b2 (V)
template <int MODE>
__global__ void __launch_bounds__(128, 2) gemm_qkv(
    const half* __restrict__ A, const half* __restrict__ B,
    const float* __restrict__ b0, const float* __restrict__ b1,
    const float* __restrict__ b2,
    half* __restrict__ o0, half* __restrict__ o1, half* __restrict__ o2,
    int M, int K) {
    extern __shared__ char dyn[];
    uint32_t sb = (smem_u32(dyn) + 127) & ~127u;
    int tid = threadIdx.x, lane = tid & 31, wid = tid >> 5;
    int rBase = blockIdx.y * 128, cBase = blockIdx.x * 128;
    int m0 = (wid >> 1) * 64, n0 = (wid & 1) * 64;

    float acc[4][8][4];
    #pragma unroll
    for (int i = 0; i < 4; i++)
        #pragma unroll
        for (int j = 0; j < 8; j++)
            #pragma unroll
            for (int u = 0; u < 4; u++) acc[i][j][u] = 0.0f;

    const int nc = K >> 6;
    auto loadStage = [&](int s, int c) {
        uint32_t base = sb + s * G16_STAGE;
        int k0 = c << 6;
        #pragma unroll
        for (int i = 0; i < 8; i++) {
            int idx = i * 128 + tid;
            int row = idx >> 3, c16 = idx & 7;
            uint32_t off = swz128(row * 128 + c16 * 16);
            cpasync16(base + off,         A + (size_t)(rBase + row) * K + k0 + c16 * 8);
            cpasync16(base + 16384 + off, B + (size_t)(cBase + row) * K + k0 + c16 * 8);
        }
    };

    int aRow = (lane & 7) + ((lane >> 3) & 1) * 8;
    int aC   = lane >> 4;
    int bRow16 = (lane & 7) + ((lane >> 4) & 1) * 8;
    int bH     = (lane >> 3) & 1;

    loadStage(0, 0); cpcommit();

    for (int c = 0; c < nc; c++) {
        if (c + 1 < nc) { loadStage((c + 1) & 1, c + 1); cpcommit(); cpwait<1>(); }
        else            { cpwait<0>(); }
        __syncthreads();
        uint32_t base = sb + (c & 1) * G16_STAGE;
        #pragma unroll
        for (int kc = 0; kc < 4; kc++) {
            uint32_t bh[8][2];
            #pragma unroll
            for (int jp = 0; jp < 4; jp++) {
                int row = n0 + jp * 16 + bRow16;
                uint32_t t4[4];
                ldsm4(t4, base + 16384 + swz128(row * 128 + kc * 32 + bH * 16));
                bh[2 * jp][0] = t4[0]; bh[2 * jp][1] = t4[1];
                bh[2 * jp + 1][0] = t4[2]; bh[2 * jp + 1][1] = t4[3];
            }
            #pragma unroll
            for (int i = 0; i < 4; i++) {
                uint32_t a4[4];
                int row = m0 + i * 16 + aRow;
                ldsm4(a4, base + swz128(row * 128 + kc * 32 + aC * 16));
                #pragma unroll
                for (int j = 0; j < 8; j++)
                    mma16816h(acc[i][j], a4, bh[j]);
            }
        }
        __syncthreads();
    }

    int region = cBase >> 10;
    int cLoc = (cBase & 1023) + n0;
    const float* bias;
    half* outS;
    if (MODE == 0) {
        bias = (region == 0) ? b0 : (region == 1 ? b1 : b2);
        outS = (region == 0) ? o0 : (region == 1 ? o1 : o2);
    } else {
        bias = (region == 0) ? b1 : b2;
        outS = (region == 0) ? o1 : o2;
    }

    int lr = lane >> 2, lc = (lane & 3) << 1;
    #pragma unroll
    for (int i = 0; i < 4; i++) {
        #pragma unroll
        for (int half_ = 0; half_ < 2; half_++) {
            size_t row = (size_t)(rBase + m0 + i * 16 + lr + half_ * 8);
            #pragma unroll
            for (int j = 0; j < 8; j++) {
                int col = cLoc + j * 8 + lc;
                float v0 = acc[i][j][half_ * 2 + 0] + bias[col];
                float v1 = acc[i][j][half_ * 2 + 1] + bias[col + 1];
                uint32_t p;
                packh2(v0, v1, p);
                *(uint32_t*)(outS + row * E_DIM + col) = p;
            }
        }
    }
}

// ---------------- flash attention (D=64): all-single fp16 ---------------------
// grid (S/64, H, B), 128 threads, 3 CTAs/SM.
// SMEM: Q 8K @0 | stage s at 8K + s*16K: K (8K), V (8K).
#define ATTN_SMEM (8192 + 2 * 16384 + 1024)
template <bool CAUSAL>
__global__ void __launch_bounds__(128, 3) attn16(
    const half* __restrict__ Q, const half* __restrict__ K,
    const half* __restrict__ V, half* __restrict__ O) {
    extern __shared__ char dyn[];
    uint32_t sb = (smem_u32(dyn) + 1023) & ~1023u;
    int tid = threadIdx.x, lane = tid & 31, w = tid >> 5;
    int b = blockIdx.z, hh = blockIdx.y;
    // causal: heavy q-tiles first (descending qt) for better wave packing
    int qt = CAUSAL ? ((int)gridDim.x - 1 - (int)blockIdx.x) : (int)blockIdx.x;
    size_t headOff = (size_t)hh * D_DIM;
    size_t tokBase = (size_t)b * S_LEN;

    int aRow = (lane & 7) + ((lane >> 3) & 1) * 8;
    int aC = lane >> 4;

    {
        #pragma unroll
        for (int i = 0; i < 4; i++) {
            int idx = i * 128 + tid;
            int r = idx >> 3, c = idx & 7;
            uint32_t off = swz128(r * 128 + c * 16);
            cpasync16(sb + off, Q + (tokBase + qt * 64 + r) * E_DIM + headOff + c * 8);
        }
    }
    auto loadKV = [&](int s, int kt) {
        uint32_t base = sb + 8192 + s * 16384;
        #pragma unroll
        for (int i = 0; i < 4; i++) {
            int idx = i * 128 + tid;
            int r = idx >> 3, c = idx & 7;
            uint32_t off = swz128(r * 128 + c * 16);
            size_t src = (tokBase + kt * 64 + r) * E_DIM + headOff + c * 8;
            cpasync16(base + off,        K + src);
            cpasync16(base + 8192 + off, V + src);
        }
    };
    loadKV(0, 0);
    cpcommit();

    uint32_t qf[4][4];
    float oacc[8][4];
    float mrow[2] = {-1e30f, -1e30f}, lrow[2] = {0.0f, 0.0f};
    #pragma unroll
    for (int j = 0; j < 8; j++)
        #pragma unroll
        for (int u = 0; u < 4; u++) oacc[j][u] = 0.0f;

    const int ntiles = CAUSAL ? (qt + 1) : (S_LEN / 64);
    for (int kt = 0; kt < ntiles; kt++) {
        if (kt + 1 < ntiles) { loadKV((kt + 1) & 1, kt + 1); cpcommit(); cpwait<1>(); }
        else                 { cpwait<0>(); }
        __syncthreads();
        if (kt == 0) {
            #pragma unroll
            for (int s = 0; s < 4; s++)
                ldsm4(qf[s], sb + swz128((w * 16 + aRow) * 128 + s * 32 + aC * 16));
        }
        uint32_t kb = sb + 8192 + (kt & 1) * 16384;
        uint32_t vb = kb + 8192;

        float sacc[8][4];
        #pragma unroll
        for (int j = 0; j < 8; j++)
            #pragma unroll
            for (int u = 0; u < 4; u++) sacc[j][u] = 0.0f;
        #pragma unroll
        for (int s = 0; s < 4; s++) {
            #pragma unroll
            for (int jp = 0; jp < 4; jp++) {
                uint32_t k4[4];
                ldsm4(k4, kb + swz128((jp * 16 + aRow) * 128 + s * 32 + aC * 16));
                uint32_t b0[2] = {k4[0], k4[2]}, b1[2] = {k4[1], k4[3]};
                mma16816h(sacc[2 * jp],     qf[s], b0);
                mma16816h(sacc[2 * jp + 1], qf[s], b1);
            }
        }

        if (CAUSAL && kt == qt) {
            int ql0 = w * 16 + (lane >> 2);
            #pragma unroll
            for (int j = 0; j < 8; j++)
                #pragma unroll
                for (int u = 0; u < 4; u++) {
                    int kcol = j * 8 + ((lane & 3) << 1) + (u & 1);
                    int qrow = ql0 + (u >> 1) * 8;
                    if (kcol > qrow) sacc[j][u] = -1e30f;
                }
        }

        #pragma unroll
        for (int h2 = 0; h2 < 2; h2++) {
            float mt = -1e30f;
            #pragma unroll
            for (int j = 0; j < 8; j++)
                mt = fmaxf(mt, fmaxf(sacc[j][2 * h2], sacc[j][2 * h2 + 1]));
            mt = fmaxf(mt, __shfl_xor_sync(0xffffffffu, mt, 1));
            mt = fmaxf(mt, __shfl_xor_sync(0xffffffffu, mt, 2));
            float mn = fmaxf(mrow[h2], mt);
            float sc = __expf(mrow[h2] - mn);
            mrow[h2] = mn;
            float ts = 0.0f;
            #pragma unroll
            for (int j = 0; j < 8; j++) {
                sacc[j][2 * h2]     = __expf(sacc[j][2 * h2] - mn);
                sacc[j][2 * h2 + 1] = __expf(sacc[j][2 * h2 + 1] - mn);
                ts += sacc[j][2 * h2] + sacc[j][2 * h2 + 1];
            }
            ts += __shfl_xor_sync(0xffffffffu, ts, 1);
            ts += __shfl_xor_sync(0xffffffffu, ts, 2);
            lrow[h2] = lrow[h2] * sc + ts;
            #pragma unroll
            for (int j = 0; j < 8; j++) {
                oacc[j][2 * h2]     *= sc;
                oacc[j][2 * h2 + 1] *= sc;
            }
        }

        #pragma unroll
        for (int s = 0; s < 4; s++) {
            uint32_t pf[4];
            packh2(sacc[2 * s][0],     sacc[2 * s][1],     pf[0]);
            packh2(sacc[2 * s][2],     sacc[2 * s][3],     pf[1]);
            packh2(sacc[2 * s + 1][0], sacc[2 * s + 1][1], pf[2]);
            packh2(sacc[2 * s + 1][2], sacc[2 * s + 1][3], pf[3]);
            #pragma unroll
            for (int jp = 0; jp < 4; jp++) {
                uint32_t v4[4];
                ldsm4t(v4, vb + swz128((s * 16 + aRow) * 128 + jp * 32 + aC * 16));
                uint32_t b0[2] = {v4[0], v4[1]}, b1[2] = {v4[2], v4[3]};
                mma16816h(oacc[2 * jp],     pf, b0);
                mma16816h(oacc[2 * jp + 1], pf, b1);
            }
        }
        __syncthreads();
    }

    #pragma unroll
    for (int h2 = 0; h2 < 2; h2++) {
        float inv = 1.0f / lrow[h2];
        int trow = qt * 64 + w * 16 + (lane >> 2) + h2 * 8;
        size_t rp = (tokBase + trow) * E_DIM + headOff;
        #pragma unroll
        for (int j = 0; j < 8; j++) {
            uint32_t p;
            packh2(oacc[j][2 * h2] * inv, oacc[j][2 * h2 + 1] * inv, p);
            int col = j * 8 + ((lane & 3) << 1);
            *(uint32_t*)(O + rp + col) = p;
        }
    }
}

// ---------------- launch ------------------------------------------------------
extern "C" void kernel_launch(void* const* d_in, const int* in_sizes, int n_in,
                              void* d_out, int out_size) {
    const float* x    = (const float*)d_in[0];
    const float* enc  = (const float*)d_in[1];
    const float* ln1g = (const float*)d_in[2];
    const float* ln1b = (const float*)d_in[3];
    const float* ln2g = (const float*)d_in[4];
    const float* ln2b = (const float*)d_in[5];
    const float* ln3g = (const float*)d_in[6];
    const float* ln3b = (const float*)d_in[7];
    const float* Wq1  = (const float*)d_in[8];
    const float* bq1  = (const float*)d_in[9];
    const float* Wk1  = (const float*)d_in[10];
    const float* bk1  = (const float*)d_in[11];
    const float* Wv1  = (const float*)d_in[12];
    const float* bv1  = (const float*)d_in[13];
    const float* Wo1  = (const float*)d_in[14];
    const float* bo1  = (const float*)d_in[15];
    const float* Wq2  = (const float*)d_in[16];
    const float* bq2  = (const float*)d_in[17];
    const float* Wk2  = (const float*)d_in[18];
    const float* bk2  = (const float*)d_in[19];
    const float* Wv2  = (const float*)d_in[20];
    const float* bv2  = (const float*)d_in[21];
    const float* Wo2  = (const float*)d_in[22];
    const float* bo2  = (const float*)d_in[23];
    const float* Wup  = (const float*)d_in[24];
    const float* bup  = (const float*)d_in[25];
    const float* Wdn  = (const float*)d_in[26];
    const float* bdn  = (const float*)d_in[27];
    float* out = (float*)d_out;

    half *W16, *h16, *e16, *q16, *k16, *v16, *k2, *v2, *a16;
    float *x1, *x2;
    cudaGetSymbolAddress((void**)&W16, g_W16);
    cudaGetSymbolAddress((void**)&h16, g_h16);
    cudaGetSymbolAddress((void**)&e16, g_e16);
    cudaGetSymbolAddress((void**)&q16, g_q16);
    cudaGetSymbolAddress((void**)&k16, g_k16);
    cudaGetSymbolAddress((void**)&v16, g_v16);
    cudaGetSymbolAddress((void**)&k2,  g_k2);
    cudaGetSymbolAddress((void**)&v2,  g_v2);
    cudaGetSymbolAddress((void**)&a16, g_a16);
    cudaGetSymbolAddress((void**)&x1,  g_x1);
    cudaGetSymbolAddress((void**)&x2,  g_x2);

    cudaFuncSetAttribute(gemm16<0>, cudaFuncAttributeMaxDynamicSharedMemorySize, G16_SMEM);
    cudaFuncSetAttribute(gemm16<1>, cudaFuncAttributeMaxDynamicSharedMemorySize, G16_SMEM);
    cudaFuncSetAttribute(gemm16<2>, cudaFuncAttributeMaxDynamicSharedMemorySize, G16_SMEM);
    cudaFuncSetAttribute(gemm_qkv<0>, cudaFuncAttributeMaxDynamicSharedMemorySize, G16_SMEM);
    cudaFuncSetAttribute(gemm_qkv<1>, cudaFuncAttributeMaxDynamicSharedMemorySize, G16_SMEM);
    cudaFuncSetAttribute(attn16<true>,  cudaFuncAttributeMaxDynamicSharedMemorySize, ATTN_SMEM);
    cudaFuncSetAttribute(attn16<false>, cudaFuncAttributeMaxDynamicSharedMemorySize, ATTN_SMEM);

    static cudaStream_t sPrep = nullptr;
    static cudaEvent_t eFork, eQKV1W, eQKV2W, eKV2, eWo1, eWo2, eWup, eWdn;
    if (sPrep == nullptr) {
        cudaStreamCreateWithFlags(&sPrep, cudaStreamNonBlocking);
        cudaEventCreateWithFlags(&eFork,  cudaEventDisableTiming);
        cudaEventCreateWithFlags(&eQKV1W, cudaEventDisableTiming);
        cudaEventCreateWithFlags(&eQKV2W, cudaEventDisableTiming);
        cudaEventCreateWithFlags(&eKV2,   cudaEventDisableTiming);
        cudaEventCreateWithFlags(&eWo1,   cudaEventDisableTiming);
        cudaEventCreateWithFlags(&eWo2,   cudaEventDisableTiming);
        cudaEventCreateWithFlags(&eWup,   cudaEventDisableTiming);
        cudaEventCreateWithFlags(&eWdn,   cudaEventDisableTiming);
    }

    const int WS = E_DIM * E_DIM;
    dim3 gSq(8, 32);
    dim3 gUp(32, 32);
    dim3 gQKV(24, 32);
    dim3 gKV(16, 32);
    dim3 gAttn(S_LEN / 64, H_NUM, B_NUM);
    dim3 trB(32, 8);

    // ---- fork prep stream ----
    cudaEventRecord(eFork, 0);
    cudaStreamWaitEvent(sPrep, eFork, 0);
    wqkv_cvt3<<<dim3(2, 32, 48), 256, 0, sPrep>>>(Wq1, Wk1, Wv1, W16);            // slots 0-2
    cudaEventRecord(eQKV1W, sPrep);
    wqkv_cvt3<<<dim3(2, 32, 48), 256, 0, sPrep>>>(Wq2, Wk2, Wv2, W16 + 3 * WS);   // slots 3-5
    cudaEventRecord(eQKV2W, sPrep);
    cvt16<<<4096, 256, 0, sPrep>>>(enc, e16);
    wt_cvt16<<<dim3(32, 32), trB, 0, sPrep>>>(Wo1, W16 + 6 * WS, 1024, 1024);
    cudaEventRecord(eWo1, sPrep);
    // KV2 projection — depends only on enc + slots 4-5; co-runs with block 1.
    gemm_qkv<1><<<gKV, 128, G16_SMEM, sPrep>>>(e16, W16 + 4 * WS, nullptr, bk2, bv2,
                                               nullptr, k2, v2, M_ROWS, E_DIM);
    cudaEventRecord(eKV2, sPrep);
    wt_cvt16<<<dim3(32, 32), trB, 0, sPrep>>>(Wo2, W16 + 7 * WS, 1024, 1024);
    cudaEventRecord(eWo2, sPrep);
    wt_cvt16<<<dim3(128, 32), trB, 0, sPrep>>>(Wup, W16 + 8 * WS, 1024, 4096);
    cudaEventRecord(eWup, sPrep);
    wt_cvt16<<<dim3(32, 128), trB, 0, sPrep>>>(Wdn, W16 + 12 * WS, 4096, 1024);
    cudaEventRecord(eWdn, sPrep);

    // ---- main chain ----
    ln_kernel<<<M_ROWS, 256>>>(x, ln1g, ln1b, h16);
    cudaStreamWaitEvent(0, eQKV1W, 0);
    gemm_qkv<0><<<gQKV, 128, G16_SMEM>>>(h16, W16, bq1, bk1, bv1,
                                         q16, k16, v16, M_ROWS, E_DIM);
    attn16<true><<<gAttn, 128, ATTN_SMEM>>>(q16, k16, v16, a16);
    cudaStreamWaitEvent(0, eWo1, 0);
    gemm16<2><<<gSq, 128, G16_SMEM>>>(a16, W16 + 6 * WS, bo1, x,
                                      x1, nullptr, M_ROWS, E_DIM, E_DIM);

    ln_kernel<<<M_ROWS, 256>>>(x1, ln2g, ln2b, h16);
    cudaStreamWaitEvent(0, eQKV2W, 0);
    gemm16<0><<<gSq, 128, G16_SMEM>>>(h16, W16 + 3 * WS, bq2, nullptr,
                                      nullptr, q16, M_ROWS, E_DIM, E_DIM);
    cudaStreamWaitEvent(0, eKV2, 0);
    attn16<false><<<gAttn, 128, ATTN_SMEM>>>(q16, k2, v2, a16);
    cudaStreamWaitEvent(0, eWo2, 0);
    gemm16<2><<<gSq, 128, G16_SMEM>>>(a16, W16 + 7 * WS, bo2, x1,
                                      x2, nullptr, M_ROWS, E_DIM, E_DIM);

    ln_kernel<<<M_ROWS, 256>>>(x2, ln3g, ln3b, h16);
    cudaStreamWaitEvent(0, eWup, 0);
    gemm16<1><<<gUp, 128, G16_SMEM>>>(h16, W16 + 8 * WS, bup, nullptr,
                                      nullptr, a16, M_ROWS, F_DIM, E_DIM);
    cudaStreamWaitEvent(0, eWdn, 0);
    gemm16<2><<<gSq, 128, G16_SMEM>>>(a16, W16 + 12 * WS, bdn, x2,
                                      out, nullptr, M_ROWS, E_DIM, F_DIM);
}